// round 11
// baseline (speedup 1.0000x reference)
#include <cuda_runtime.h>
#include <cuda_fp16.h>
#include <float.h>
#include <stdint.h>

// Problem constants
#define Bn   8
#define Hn   64
#define Wn   64
#define Cn   384
#define NHd  8
#define Dh   48
#define NCn  256
#define HWn  4096
#define C3n  1152
#define SCALE 0.14433756729740643f

// ---- tiled operand layout: [tile(128 rows)][kchunk(24)][rows][pitch 24] ----
#define TP     24
#define ACHH   (128 * TP)          // halves per A chunk (3072)
#define WCHH   (128 * TP)          // halves per W chunk (3072)
#define ATILEH (24 * ACHH)
#define WTILEH (24 * WCHH)
#define APL    ((size_t)256 * ATILEH)  // plane size (256 m-tiles of 128 rows)

// ---------------- scratch (device globals; no allocation) ----------------
__device__ float g_qkvc[Bn * NCn * C3n];
__device__ int   g_topk[Bn * NHd * NCn * 4];
__device__ float g_xo  [Bn * NCn * Cn];
__device__ float g_qkvf[(size_t)Bn * HWn * C3n];
__device__ float g_yo  [(size_t)Bn * HWn * Cn];
__device__ float g_z   [(size_t)Bn * HWn * Cn];
__device__ __half g_abf[2 * APL];        // A hi plane, lo plane (tiled)
__device__ __half g_wqh[9 * WTILEH];     // qkv W hi (tiled)
__device__ __half g_wql[9 * WTILEH];     // qkv W lo
__device__ __half g_wph[3 * WTILEH];     // pw W hi
__device__ __half g_wpl[3 * WTILEH];     // pw W lo

__device__ __forceinline__ size_t a_off(int m, int k) {
    return (size_t)(m >> 7) * ATILEH + (size_t)(k >> 4) * ACHH
         + (m & 127) * TP + (k & 15);
}
__device__ __forceinline__ size_t w_off(int n, int k) {
    return (size_t)(n >> 7) * WTILEH + (size_t)(k >> 4) * WCHH
         + (n & 127) * TP + (k & 15);
}

// ---------------- helpers ----------------
__device__ __forceinline__ uint32_t smem_u32(const void* p) {
    uint32_t a;
    asm("{ .reg .u64 t; cvta.to.shared.u64 t, %1; cvt.u32.u64 %0, t; }"
        : "=r"(a) : "l"(p));
    return a;
}
__device__ __forceinline__ void ldmx4(uint32_t* r, uint32_t addr) {
    asm volatile("ldmatrix.sync.aligned.m8n8.x4.shared.b16 {%0,%1,%2,%3}, [%4];"
        : "=r"(r[0]), "=r"(r[1]), "=r"(r[2]), "=r"(r[3]) : "r"(addr));
}
__device__ __forceinline__ void mma16816(float* d, const uint32_t* a, const uint32_t* b) {
    asm volatile(
        "mma.sync.aligned.m16n8k16.row.col.f32.f16.f16.f32 "
        "{%0,%1,%2,%3}, {%4,%5,%6,%7}, {%8,%9}, {%0,%1,%2,%3};"
        : "+f"(d[0]), "+f"(d[1]), "+f"(d[2]), "+f"(d[3])
        : "r"(a[0]), "r"(a[1]), "r"(a[2]), "r"(a[3]), "r"(b[0]), "r"(b[1]));
}
__device__ __forceinline__ uint32_t pack_hf2(float x, float y) {
    unsigned short hx = __half_as_ushort(__float2half(x));
    unsigned short hy = __half_as_ushort(__float2half(y));
    return (uint32_t)hx | ((uint32_t)hy << 16);
}
__device__ __forceinline__ void mbar_init(uint32_t a, uint32_t cnt) {
    asm volatile("mbarrier.init.shared.b64 [%0], %1;" :: "r"(a), "r"(cnt) : "memory");
}
__device__ __forceinline__ void mbar_expect(uint32_t a, uint32_t bytes) {
    asm volatile("mbarrier.arrive.expect_tx.shared.b64 _, [%0], %1;"
                 :: "r"(a), "r"(bytes) : "memory");
}
__device__ __forceinline__ void mbar_wait(uint32_t a, uint32_t parity) {
    asm volatile(
        "{\n\t.reg .pred P;\n\t"
        "WL%=:\n\t"
        "mbarrier.try_wait.parity.acquire.cta.shared::cta.b64 P, [%0], %1, 0x989680;\n\t"
        "@P bra.uni WD%=;\n\t"
        "bra.uni WL%=;\n\t"
        "WD%=:\n\t}"
        :: "r"(a), "r"(parity) : "memory");
}
__device__ __forceinline__ void bulkcp(uint32_t sdst, const void* gsrc,
                                       uint32_t bytes, uint32_t mbar) {
    asm volatile(
        "cp.async.bulk.shared::cta.global.mbarrier::complete_tx::bytes "
        "[%0], [%1], %2, [%3];"
        :: "r"(sdst), "l"(gsrc), "r"(bytes), "r"(mbar) : "memory");
}

// ---------------- K1: 4x4 average pool -> fp16 hi/lo planes (tiled) -------
__global__ __launch_bounds__(384) void pool_kernel(const float* __restrict__ x)
{
    int blk = blockIdx.x;
    int n = blk & 255, b = blk >> 8;
    int hc = n >> 4, wc = n & 15;
    int c = threadIdx.x;
    float s = 0.f;
#pragma unroll
    for (int i = 0; i < 4; i++)
#pragma unroll
        for (int j = 0; j < 4; j++)
            s += x[(((size_t)(b * Hn + hc * 4 + i)) * Wn + wc * 4 + j) * Cn + c];
    s *= 0.0625f;
    __half h = __float2half(s);
    __half l = __float2half(s - __half2float(h));
    size_t o = a_off(b * NCn + n, c);
    g_abf[o] = h;
    g_abf[APL + o] = l;
}

// ---------------- weight fp16 hi/lo conversion (tiled) ----------------
__global__ __launch_bounds__(256) void convw_kernel(
    const float* __restrict__ w, int total, int mode)
{
    int i = blockIdx.x * 256 + threadIdx.x;
    if (i >= total) return;
    float v = w[i];
    __half h = __float2half(v);
    __half l = __float2half(v - __half2float(h));
    int n = i / 384, k = i % 384;
    size_t o = w_off(n, k);
    if (mode == 0) { g_wqh[o] = h; g_wql[o] = l; }
    else           { g_wph[o] = h; g_wpl[o] = l; }
}

// ---------------- A conversion: x (f32) -> fp16 hi/lo planes (tiled) ------
__global__ __launch_bounds__(256) void convA_kernel(
    const float* __restrict__ src, int n8)
{
    int i = blockIdx.x * 256 + threadIdx.x;
    if (i >= n8) return;
    float4 v0 = ((const float4*)src)[i * 2];
    float4 v1 = ((const float4*)src)[i * 2 + 1];
    uint4 H, L;
    H.x = pack_hf2(v0.x, v0.y); H.y = pack_hf2(v0.z, v0.w);
    H.z = pack_hf2(v1.x, v1.y); H.w = pack_hf2(v1.z, v1.w);
    float h0 = __half2float(__float2half(v0.x));
    float h1 = __half2float(__float2half(v0.y));
    float h2 = __half2float(__float2half(v0.z));
    float h3 = __half2float(__float2half(v0.w));
    float h4 = __half2float(__float2half(v1.x));
    float h5 = __half2float(__float2half(v1.y));
    float h6 = __half2float(__float2half(v1.z));
    float h7 = __half2float(__float2half(v1.w));
    L.x = pack_hf2(v0.x - h0, v0.y - h1);
    L.y = pack_hf2(v0.z - h2, v0.w - h3);
    L.z = pack_hf2(v1.x - h4, v1.y - h5);
    L.w = pack_hf2(v1.z - h6, v1.w - h7);
    int m = i / 48, k0 = (i % 48) * 8;
    size_t o = a_off(m, k0);
    *(uint4*)(g_abf + o)       = H;
    *(uint4*)(g_abf + APL + o) = L;
}

// ---------------- tensor-core GEMM: O[M,N] = A[M,384] * W[N,384]^T --------
// fp16 3-pass: acc = Ah*Wh + Al*Wh + Ah*Wl.  Operands tiled; staged with
// cp.async.bulk into a 4-stage mbarrier pipeline.
// 128x128 tile, 256 threads (4x2 warps, 32x64 warp tile), BK=16, 2 CTA/SM.
#define AH_S 0
#define AL_S 6144
#define WH_S 12288
#define WL_S 18432
#define STG  24576
#define GSMEM (4 * STG + 64)

__global__ __launch_bounds__(256, 2) void gemm_mma(
    const float* __restrict__ bias, float* __restrict__ Oext, int N, int mode)
{
    extern __shared__ __half sm[];

    float* O = (mode == 0) ? g_qkvc : (mode == 1) ? g_qkvf : Oext;
    const __half* WHp = (mode == 2) ? g_wph : g_wqh;
    const __half* WLp = (mode == 2) ? g_wpl : g_wql;

    int tid = threadIdx.x;
    int m0 = blockIdx.y * 128, n0 = blockIdx.x * 128;

    const __half* aH = g_abf + (size_t)(m0 >> 7) * ATILEH;
    const __half* aL = aH + APL;
    const __half* wH = WHp + (size_t)(n0 >> 7) * WTILEH;
    const __half* wL = WLp + (size_t)(n0 >> 7) * WTILEH;

    uint32_t sbase = smem_u32(sm);
    uint32_t mb = sbase + 4 * STG;

    if (tid == 0) {
#pragma unroll
        for (int s = 0; s < 4; s++) mbar_init(mb + s * 8, 1);
    }
    __syncthreads();

    if (tid == 0) {
#pragma unroll
        for (int s = 0; s < 3; s++) {
            uint32_t sb = sbase + s * STG;
            uint32_t mbs = mb + s * 8;
            mbar_expect(mbs, STG);
            bulkcp(sb + AH_S, aH + s * ACHH, 6144, mbs);
            bulkcp(sb + AL_S, aL + s * ACHH, 6144, mbs);
            bulkcp(sb + WH_S, wH + s * WCHH, 6144, mbs);
            bulkcp(sb + WL_S, wL + s * WCHH, 6144, mbs);
        }
    }

    int lane = tid & 31;
    int wid = tid >> 5;
    int mbase = (wid & 3) * 32;
    int nbase = (wid >> 2) * 64;

    int ar = lane & 15, ak = (lane >> 4) * 8;
    uint32_t offA0 = ((mbase + ar) * TP + ak) * 2;
    int br = (lane & 7) + ((lane >> 4) << 3), bk = ((lane >> 3) & 1) * 8;
    uint32_t offB0 = ((nbase + br) * TP + bk) * 2;

    float acc[2][8][4];
#pragma unroll
    for (int i = 0; i < 2; i++)
#pragma unroll
        for (int j = 0; j < 8; j++)
#pragma unroll
            for (int k = 0; k < 4; k++) acc[i][j][k] = 0.f;

    for (int kc = 0; kc < 24; kc++) {
        mbar_wait(mb + (kc & 3) * 8, (kc >> 2) & 1);
        uint32_t bb = sbase + (kc & 3) * STG;

        uint32_t ah[2][4], al[2][4], bf[4][4];
#pragma unroll
        for (int g = 0; g < 2; g++)
            ldmx4(ah[g], bb + AH_S + offA0 + g * 768);
#pragma unroll
        for (int g = 0; g < 2; g++)
            ldmx4(al[g], bb + AL_S + offA0 + g * 768);
#pragma unroll
        for (int g = 0; g < 4; g++)
            ldmx4(bf[g], bb + WH_S + offB0 + g * 768);

        __syncthreads();  // all reads of the stage being refilled are done

        if (tid == 0 && kc < 21) {
            int s = (kc + 3) & 3;
            uint32_t sb = sbase + s * STG;
            uint32_t mbs = mb + s * 8;
            int ck = kc + 3;
            mbar_expect(mbs, STG);
            bulkcp(sb + AH_S, aH + ck * ACHH, 6144, mbs);
            bulkcp(sb + AL_S, aL + ck * ACHH, 6144, mbs);
            bulkcp(sb + WH_S, wH + ck * WCHH, 6144, mbs);
            bulkcp(sb + WL_S, wL + ck * WCHH, 6144, mbs);
        }

        // phase 1: Ah * Wh
#pragma unroll
        for (int mi = 0; mi < 2; mi++)
#pragma unroll
            for (int g = 0; g < 4; g++)
#pragma unroll
                for (int sub = 0; sub < 2; sub++)
                    mma16816(acc[mi][g * 2 + sub], ah[mi], &bf[g][sub * 2]);
        // phase 2: Al * Wh
#pragma unroll
        for (int mi = 0; mi < 2; mi++)
#pragma unroll
            for (int g = 0; g < 4; g++)
#pragma unroll
                for (int sub = 0; sub < 2; sub++)
                    mma16816(acc[mi][g * 2 + sub], al[mi], &bf[g][sub * 2]);
        // phase 3: Ah * Wl  (bf reloaded with lo plane; same stage, safe)
#pragma unroll
        for (int g = 0; g < 4; g++)
            ldmx4(bf[g], bb + WL_S + offB0 + g * 768);
#pragma unroll
        for (int mi = 0; mi < 2; mi++)
#pragma unroll
            for (int g = 0; g < 4; g++)
#pragma unroll
                for (int sub = 0; sub < 2; sub++)
                    mma16816(acc[mi][g * 2 + sub], ah[mi], &bf[g][sub * 2]);
    }

    // epilogue
    int rbase = m0 + mbase, cbase = n0 + nbase;
#pragma unroll
    for (int mi = 0; mi < 2; mi++)
#pragma unroll
        for (int ni = 0; ni < 8; ni++) {
            int rrow = rbase + mi * 16 + (lane >> 2);
            int col = cbase + ni * 8 + (lane & 3) * 2;
            float b0 = 0.f, b1 = 0.f;
            if (mode == 2) { b0 = bias[col]; b1 = bias[col + 1]; }
            float2 v0 = make_float2(acc[mi][ni][0] + b0, acc[mi][ni][1] + b1);
            float2 v1 = make_float2(acc[mi][ni][2] + b0, acc[mi][ni][3] + b1);
            *(float2*)&O[(size_t)rrow * N + col] = v0;
            *(float2*)&O[(size_t)(rrow + 8) * N + col] = v1;
        }
}

// ---------------- K3: coarse routing attention + top-k (flash-style) ------
#define CA_SMEM (2 * 256 * 48 * 4)
__global__ __launch_bounds__(128) void coarse_attn_kernel()
{
    extern __shared__ float cas[];
    float* Ks = cas;
    float* Vs = cas + 256 * 48;

    int bid = blockIdx.x;
    int half = bid & 1;
    int hd = (bid >> 1) & 7;
    int b = bid >> 4;
    int tid = threadIdx.x;

    const float* base = g_qkvc + (size_t)b * NCn * C3n;

    for (int idx = tid; idx < 3072; idx += 128) {
        int j = idx / 12, d4 = (idx % 12) * 4;
        const float* rp = base + (size_t)j * C3n + Cn + hd * Dh + d4;
        *(float4*)&Ks[j * 48 + d4] = *(const float4*)rp;
        *(float4*)&Vs[j * 48 + d4] = *(const float4*)(rp + Cn);
    }

    int q = half * 128 + tid;
    float qv[48];
    const float* qp = base + (size_t)q * C3n + hd * Dh;
#pragma unroll
    for (int i = 0; i < 12; i++) {
        float4 v = *(const float4*)(qp + i * 4);
        qv[i * 4 + 0] = v.x; qv[i * 4 + 1] = v.y;
        qv[i * 4 + 2] = v.z; qv[i * 4 + 3] = v.w;
    }
    __syncthreads();

    float v0 = -FLT_MAX, v1 = -FLT_MAX, v2 = -FLT_MAX, v3 = -FLT_MAX;
    int i0 = 0, i1 = 0, i2 = 0, i3 = 0;
    for (int j = 0; j < 256; j++) {
        float a0 = 0.f, a1 = 0.f, a2 = 0.f, a3 = 0.f;
        const float* kp = &Ks[j * 48];
#pragma unroll
        for (int d4 = 0; d4 < 12; d4++) {
            float4 kv = *(const float4*)(kp + d4 * 4);
            a0 += qv[d4 * 4 + 0] * kv.x;
            a1 += qv[d4 * 4 + 1] * kv.y;
            a2 += qv[d4 * 4 + 2] * kv.z;
            a3 += qv[d4 * 4 + 3] * kv.w;
        }
        float s = (a0 + a1) + (a2 + a3);
        if (s > v3) {
            if (s > v0)      { v3 = v2; i3 = i2; v2 = v1; i2 = i1; v1 = v0; i1 = i0; v0 = s; i0 = j; }
            else if (s > v1) { v3 = v2; i3 = i2; v2 = v1; i2 = i1; v1 = s; i1 = j; }
            else if (s > v2) { v3 = v2; i3 = i2; v2 = s; i2 = j; }
            else             { v3 = s; i3 = j; }
        }
    }
    int obase = ((b * 8 + hd) * 256 + q) * 4;
    g_topk[obase + 0] = i0; g_topk[obase + 1] = i1;
    g_topk[obase + 2] = i2; g_topk[obase + 3] = i3;

    float mx = v0 * SCALE;

    float oacc[48];
#pragma unroll
    for (int d = 0; d < 48; d++) oacc[d] = 0.f;
    float psum = 0.f;
    for (int j = 0; j < 256; j++) {
        float a0 = 0.f, a1 = 0.f, a2 = 0.f, a3 = 0.f;
        const float* kp = &Ks[j * 48];
#pragma unroll
        for (int d4 = 0; d4 < 12; d4++) {
            float4 kv = *(const float4*)(kp + d4 * 4);
            a0 += qv[d4 * 4 + 0] * kv.x;
            a1 += qv[d4 * 4 + 1] * kv.y;
            a2 += qv[d4 * 4 + 2] * kv.z;
            a3 += qv[d4 * 4 + 3] * kv.w;
        }
        float p = __expf(((a0 + a1) + (a2 + a3)) * SCALE - mx);
        psum += p;
        const float* vp = &Vs[j * 48];
#pragma unroll
        for (int d4 = 0; d4 < 12; d4++) {
            float4 vv = *(const float4*)(vp + d4 * 4);
            oacc[d4 * 4 + 0] += p * vv.x;
            oacc[d4 * 4 + 1] += p * vv.y;
            oacc[d4 * 4 + 2] += p * vv.z;
            oacc[d4 * 4 + 3] += p * vv.w;
        }
    }
    float inv = 1.f / psum;
    float* op = &g_xo[((size_t)(b * NCn + q)) * Cn + hd * Dh];
#pragma unroll
    for (int i = 0; i < 12; i++) {
        float4 v = make_float4(oacc[i * 4] * inv, oacc[i * 4 + 1] * inv,
                               oacc[i * 4 + 2] * inv, oacc[i * 4 + 3] * inv);
        *(float4*)(op + i * 4) = v;
    }
}

// ---------------- K5: fine windowed attention (register-tiled) ------------
#define QT_P 18
#define KT_P 68
#define VS_P 52
#define A2_P 68
__global__ __launch_bounds__(128) void fine_attn_kernel()
{
    int bid = blockIdx.x;
    int n  = bid & 255;
    int hd = (bid >> 8) & 7;
    int b  = bid >> 11;

    __shared__ float Qt[48 * QT_P];
    __shared__ float Kt[48 * KT_P];
    __shared__ float Vs[64 * VS_P];
    __shared__ float A2[16 * A2_P];
    __shared__ int   wins[4];

    int tid = threadIdx.x;
    int hc = n >> 4, wc = n & 15;
    const float* base = g_qkvf + (size_t)b * HWn * C3n;

    if (tid < 4) wins[tid] = g_topk[(size_t)bid * 4 + tid];

    for (int idx = tid; idx < 16 * 12; idx += 128) {
        int p = idx / 12, d4 = (idx % 12) * 4;
        int s = (hc * 4 + (p >> 2)) * Wn + wc * 4 + (p & 3);
        float4 v = *(const float4*)&base[(size_t)s * C3n + hd * Dh + d4];
        Qt[(d4 + 0) * QT_P + p] = v.x;
        Qt[(d4 + 1) * QT_P + p] = v.y;
        Qt[(d4 + 2) * QT_P + p] = v.z;
        Qt[(d4 + 3) * QT_P + p] = v.w;
    }
    __syncthreads();

    for (int idx = tid; idx < 64 * 12; idx += 128) {
        int p = idx / 12, d4 = (idx % 12) * 4;
        int t = p >> 4, pl = p & 15;
        int m = wins[t];
        int s = ((m >> 4) * 4 + (pl >> 2)) * Wn + (m & 15) * 4 + (pl & 3);
        const float* rw = &base[(size_t)s * C3n + hd * Dh + d4];
        float4 kv = *(const float4*)(rw + Cn);
        float4 vv = *(const float4*)(rw + 2 * Cn);
        Kt[(d4 + 0) * KT_P + p] = kv.x;
        Kt[(d4 + 1) * KT_P + p] = kv.y;
        Kt[(d4 + 2) * KT_P + p] = kv.z;
        Kt[(d4 + 3) * KT_P + p] = kv.w;
        *(float4*)&Vs[p * VS_P + d4] = vv;
    }
    __syncthreads();

    {
        int tr = tid >> 4, tc = tid & 15;
        int r0 = tr * 2, c0 = tc * 4;
        float a0[4] = {0.f, 0.f, 0.f, 0.f};
        float a1[4] = {0.f, 0.f, 0.f, 0.f};
#pragma unroll 8
        for (int dd = 0; dd < Dh; dd++) {
            float2 qv = *(const float2*)&Qt[dd * QT_P + r0];
            float4 kv = *(const float4*)&Kt[dd * KT_P + c0];
            a0[0] += qv.x * kv.x; a0[1] += qv.x * kv.y;
            a0[2] += qv.x * kv.z; a0[3] += qv.x * kv.w;
            a1[0] += qv.y * kv.x; a1[1] += qv.y * kv.y;
            a1[2] += qv.y * kv.z; a1[3] += qv.y * kv.w;
        }
        float4 w0 = make_float4(a0[0] * SCALE, a0[1] * SCALE, a0[2] * SCALE, a0[3] * SCALE);
        float4 w1 = make_float4(a1[0] * SCALE, a1[1] * SCALE, a1[2] * SCALE, a1[3] * SCALE);
        *(float4*)&A2[r0 * A2_P + c0] = w0;
        *(float4*)&A2[(r0 + 1) * A2_P + c0] = w1;
    }
    __syncthreads();

    {
        int row = tid >> 3, j = tid & 7;
        float* ap = &A2[row * A2_P + j * 8];
        float v[8];
        float mx = -FLT_MAX;
#pragma unroll
        for (int i = 0; i < 8; i++) { v[i] = ap[i]; mx = fmaxf(mx, v[i]); }
#pragma unroll
        for (int m = 1; m < 8; m <<= 1)
            mx = fmaxf(mx, __shfl_xor_sync(0xffffffffu, mx, m));
        float sum = 0.f;
#pragma unroll
        for (int i = 0; i < 8; i++) { v[i] = __expf(v[i] - mx); sum += v[i]; }
#pragma unroll
        for (int m = 1; m < 8; m <<= 1)
            sum += __shfl_xor_sync(0xffffffffu, sum, m);
        float inv = 1.f / sum;
#pragma unroll
        for (int i = 0; i < 8; i++) ap[i] = v[i] * inv;
    }
    __syncthreads();

    {
        int tr2 = tid >> 4, tc2 = tid & 15;
        int p0 = tr2 * 2, dd0 = tc2 * 3;
        float o0[3] = {0.f, 0.f, 0.f};
        float o1[3] = {0.f, 0.f, 0.f};
#pragma unroll 8
        for (int kk = 0; kk < 64; kk++) {
            float av0 = A2[p0 * A2_P + kk];
            float av1 = A2[(p0 + 1) * A2_P + kk];
            const float* vp = &Vs[kk * VS_P + dd0];
            float v0 = vp[0], v1 = vp[1], v2 = vp[2];
            o0[0] += av0 * v0; o0[1] += av0 * v1; o0[2] += av0 * v2;
            o1[0] += av1 * v0; o1[1] += av1 * v1; o1[2] += av1 * v2;
        }
#pragma unroll
        for (int pi = 0; pi < 2; pi++) {
            int p = p0 + pi;
            int yy = hc * 4 + (p >> 2), xx = wc * 4 + (p & 3);
            float* op = &g_yo[(((size_t)(b * Hn + yy)) * Wn + xx) * Cn + hd * Dh + dd0];
            if (pi == 0) { op[0] = o0[0]; op[1] = o0[1]; op[2] = o0[2]; }
            else         { op[0] = o1[0]; op[1] = o1[1]; op[2] = o1[2]; }
        }
    }
}

// ---------------- K6: upsample(xo) -> dwconv3x3(dwx) -> mix with yo -------
__global__ __launch_bounds__(384) void dwmix_kernel(
    const float* __restrict__ dwxw, const float* __restrict__ dwxb)
{
    __shared__ float wsh[Cn * 9];
    int tid = threadIdx.x;
    for (int i = tid; i < Cn * 9; i += 384) wsh[i] = dwxw[i];
    __syncthreads();

    int b  = blockIdx.x >> 6;
    int yy = blockIdx.x & 63;
    int c  = tid;
    float w[9];
#pragma unroll
    for (int i = 0; i < 9; i++) w[i] = wsh[c * 9 + i];
    float bias = dwxb[c];

    const float* xob = g_xo + (size_t)b * NCn * Cn + c;
    bool up = yy > 0, dn = yy < 63;
    int ru = (yy - 1) >> 2, rm = yy >> 2, rd = (yy + 1) >> 2;

    float3 cm = make_float3(0.f, 0.f, 0.f), cc, cp;
    cc.x = up ? xob[(size_t)(ru * 16) * Cn] : 0.f;
    cc.y = xob[(size_t)(rm * 16) * Cn];
    cc.z = dn ? xob[(size_t)(rd * 16) * Cn] : 0.f;

    size_t pix0 = ((size_t)(b * Hn + yy)) * Wn;
    for (int xx = 0; xx < 64; xx++) {
        if (xx < 63) {
            int xc4 = (xx + 1) >> 2;
            cp.x = up ? xob[(size_t)(ru * 16 + xc4) * Cn] : 0.f;
            cp.y = xob[(size_t)(rm * 16 + xc4) * Cn];
            cp.z = dn ? xob[(size_t)(rd * 16 + xc4) * Cn] : 0.f;
        } else {
            cp = make_float3(0.f, 0.f, 0.f);
        }
        float acc = bias
            + w[0] * cm.x + w[1] * cc.x + w[2] * cp.x
            + w[3] * cm.y + w[4] * cc.y + w[5] * cp.y
            + w[6] * cm.z + w[7] * cc.z + w[8] * cp.z;
        size_t pix = pix0 + xx;
        g_z[pix * Cn + c] = 0.5f * acc + 0.5f * g_yo[pix * Cn + c];
        cm = cc; cc = cp;
    }
}

// ---------------- K7: dwconv3x3(dw) on z -> fp16 hi/lo planes (tiled) -----
__global__ __launch_bounds__(384) void dwconv2_kernel(
    const float* __restrict__ dww, const float* __restrict__ dwb)
{
    __shared__ float wsh[Cn * 9];
    int tid = threadIdx.x;
    for (int i = tid; i < Cn * 9; i += 384) wsh[i] = dww[i];
    __syncthreads();

    int b  = blockIdx.x >> 6;
    int yy = blockIdx.x & 63;
    int c  = tid;
    float w[9];
#pragma unroll
    for (int i = 0; i < 9; i++) w[i] = wsh[c * 9 + i];
    float bias = dwb[c];

    const float* zb = g_z + (size_t)b * HWn * Cn + c;
    bool up = yy > 0, dn = yy < 63;
    size_t rowm = (size_t)yy * Wn;

    float3 cm = make_float3(0.f, 0.f, 0.f), cc, cp;
    cc.x = up ? zb[(rowm - Wn) * Cn] : 0.f;
    cc.y = zb[rowm * Cn];
    cc.z = dn ? zb[(rowm + Wn) * Cn] : 0.f;

    int mrow0 = b * HWn + yy * Wn;
    for (int xx = 0; xx < 64; xx++) {
        if (xx < 63) {
            size_t bcol = rowm + xx + 1;
            cp.x = up ? zb[(bcol - Wn) * Cn] : 0.f;
            cp.y = zb[bcol * Cn];
            cp.z = dn ? zb[(bcol + Wn) * Cn] : 0.f;
        } else {
            cp = make_float3(0.f, 0.f, 0.f);
        }
        float acc = bias
            + w[0] * cm.x + w[1] * cc.x + w[2] * cp.x
            + w[3] * cm.y + w[4] * cc.y + w[5] * cp.y
            + w[6] * cm.z + w[7] * cc.z + w[8] * cp.z;
        __half h = __float2half(acc);
        __half l = __float2half(acc - __half2float(h));
        size_t o = a_off(mrow0 + xx, c);
        g_abf[o] = h;
        g_abf[APL + o] = l;
        cm = cc; cc = cp;
    }
}

// ---------------- launch ----------------
extern "C" void kernel_launch(void* const* d_in, const int* in_sizes, int n_in,
                              void* d_out, int out_size)
{
    const float* x     = (const float*)d_in[0];
    const float* qkv_w = (const float*)d_in[1];
    const float* dwx_w = (const float*)d_in[2];
    const float* dwx_b = (const float*)d_in[3];
    const float* dw_w  = (const float*)d_in[4];
    const float* dw_b  = (const float*)d_in[5];
    const float* pw_w  = (const float*)d_in[6];
    const float* pw_b  = (const float*)d_in[7];
    float* out = (float*)d_out;

    cudaFuncSetAttribute(gemm_mma, cudaFuncAttributeMaxDynamicSharedMemorySize,
                         GSMEM);
    cudaFuncSetAttribute(coarse_attn_kernel,
                         cudaFuncAttributeMaxDynamicSharedMemorySize, CA_SMEM);

    // weight conversions (tiny)
    convw_kernel<<<(C3n * Cn + 255) / 256, 256>>>(qkv_w, C3n * Cn, 0);
    convw_kernel<<<(Cn * Cn + 255) / 256, 256>>>(pw_w, Cn * Cn, 1);

    // 1) coarse pooling (writes fp16 tiled planes directly)
    pool_kernel<<<Bn * NCn, Cn>>>(x);

    // 2) coarse QKV: (2048 x 1152 x 384)
    gemm_mma<<<dim3(C3n / 128, (Bn * NCn) / 128), 256, GSMEM>>>(
        nullptr, nullptr, C3n, 0);

    // 3) coarse routing attention + top-k
    coarse_attn_kernel<<<Bn * NHd * 2, 128, CA_SMEM>>>();

    // 4) fine QKV: (32768 x 1152 x 384)
    convA_kernel<<<(Bn * HWn * 48 + 255) / 256, 256>>>(x, Bn * HWn * 48);
    gemm_mma<<<dim3(C3n / 128, (Bn * HWn) / 128), 256, GSMEM>>>(
        nullptr, nullptr, C3n, 1);

    // 5) fine windowed attention
    fine_attn_kernel<<<Bn * NHd * NCn, 128>>>();

    // 6) upsample+dwconv(dwx)+mix
    dwmix_kernel<<<Bn * Hn, Cn>>>(dwx_w, dwx_b);

    // 7) dwconv(dw) -> fp16 tiled planes directly
    dwconv2_kernel<<<Bn * Hn, Cn>>>(dw_w, dw_b);

    // 8) pointwise projection (+bias): (32768 x 384 x 384)
    gemm_mma<<<dim3(Cn / 128, (Bn * HWn) / 128), 256, GSMEM>>>(
        pw_b, out, Cn, 2);
}

// round 12
// speedup vs baseline: 1.4260x; 1.4260x over previous
#include <cuda_runtime.h>
#include <cuda_fp16.h>
#include <float.h>
#include <stdint.h>

// Problem constants
#define Bn   8
#define Hn   64
#define Wn   64
#define Cn   384
#define NHd  8
#define Dh   48
#define NCn  256
#define HWn  4096
#define C3n  1152
#define SCALE 0.14433756729740643f

// ---- tiled operand layout: [tile][kchunk(24)][rows][pitch 24 halves] ----
#define TP     24
#define ACHH   (256 * TP)          // halves per A chunk (6144)
#define WCHH   (128 * TP)          // halves per W chunk (3072)
#define ATILEH (24 * ACHH)         // per 256-row m-tile
#define WTILEH (24 * WCHH)         // per 128-row n-tile
#define APL    ((size_t)128 * ATILEH)  // plane size (128 m-tiles)

// ---------------- scratch (device globals; no allocation) ----------------
__device__ float g_qkvc[Bn * NCn * C3n];
__device__ int   g_topk[Bn * NHd * NCn * 4];
__device__ float g_xo  [Bn * NCn * Cn];
__device__ float g_qkvf[(size_t)Bn * HWn * C3n];
__device__ float g_yo  [(size_t)Bn * HWn * Cn];
__device__ float g_z   [(size_t)Bn * HWn * Cn];
__device__ __half g_abf[2 * APL];        // A hi plane, lo plane (tiled)
__device__ __half g_wqh[9 * WTILEH];     // qkv W hi (tiled)
__device__ __half g_wql[9 * WTILEH];     // qkv W lo
__device__ __half g_wph[3 * WTILEH];     // pw W hi
__device__ __half g_wpl[3 * WTILEH];     // pw W lo

__device__ __forceinline__ size_t a_off(int m, int k) {
    return (size_t)(m >> 8) * ATILEH + (size_t)(k >> 4) * ACHH
         + (m & 255) * TP + (k & 15);
}
__device__ __forceinline__ size_t w_off(int n, int k) {
    return (size_t)(n >> 7) * WTILEH + (size_t)(k >> 4) * WCHH
         + (n & 127) * TP + (k & 15);
}

// ---------------- helpers ----------------
__device__ __forceinline__ uint32_t smem_u32(const void* p) {
    uint32_t a;
    asm("{ .reg .u64 t; cvta.to.shared.u64 t, %1; cvt.u32.u64 %0, t; }"
        : "=r"(a) : "l"(p));
    return a;
}
__device__ __forceinline__ void ldmx4(uint32_t* r, uint32_t addr) {
    asm volatile("ldmatrix.sync.aligned.m8n8.x4.shared.b16 {%0,%1,%2,%3}, [%4];"
        : "=r"(r[0]), "=r"(r[1]), "=r"(r[2]), "=r"(r[3]) : "r"(addr));
}
__device__ __forceinline__ void mma16816(float* d, const uint32_t* a, const uint32_t* b) {
    asm volatile(
        "mma.sync.aligned.m16n8k16.row.col.f32.f16.f16.f32 "
        "{%0,%1,%2,%3}, {%4,%5,%6,%7}, {%8,%9}, {%0,%1,%2,%3};"
        : "+f"(d[0]), "+f"(d[1]), "+f"(d[2]), "+f"(d[3])
        : "r"(a[0]), "r"(a[1]), "r"(a[2]), "r"(a[3]), "r"(b[0]), "r"(b[1]));
}
__device__ __forceinline__ uint32_t pack_hf2(float x, float y) {
    unsigned short hx = __half_as_ushort(__float2half(x));
    unsigned short hy = __half_as_ushort(__float2half(y));
    return (uint32_t)hx | ((uint32_t)hy << 16);
}
__device__ __forceinline__ void mbar_init(uint32_t a, uint32_t cnt) {
    asm volatile("mbarrier.init.shared.b64 [%0], %1;" :: "r"(a), "r"(cnt) : "memory");
}
__device__ __forceinline__ void mbar_expect(uint32_t a, uint32_t bytes) {
    asm volatile("mbarrier.arrive.expect_tx.shared.b64 _, [%0], %1;"
                 :: "r"(a), "r"(bytes) : "memory");
}
__device__ __forceinline__ void mbar_wait(uint32_t a, uint32_t parity) {
    asm volatile(
        "{\n\t.reg .pred P;\n\t"
        "WL%=:\n\t"
        "mbarrier.try_wait.parity.acquire.cta.shared::cta.b64 P, [%0], %1, 0x989680;\n\t"
        "@P bra.uni WD%=;\n\t"
        "bra.uni WL%=;\n\t"
        "WD%=:\n\t}"
        :: "r"(a), "r"(parity) : "memory");
}
__device__ __forceinline__ void bulkcp(uint32_t sdst, const void* gsrc,
                                       uint32_t bytes, uint32_t mbar) {
    asm volatile(
        "cp.async.bulk.shared::cta.global.mbarrier::complete_tx::bytes "
        "[%0], [%1], %2, [%3];"
        :: "r"(sdst), "l"(gsrc), "r"(bytes), "r"(mbar) : "memory");
}

// ---------------- K1: 4x4 average pool -> fp16 hi/lo planes (tiled) -------
__global__ __launch_bounds__(384) void pool_kernel(const float* __restrict__ x)
{
    int blk = blockIdx.x;
    int n = blk & 255, b = blk >> 8;
    int hc = n >> 4, wc = n & 15;
    int c = threadIdx.x;
    float s = 0.f;
#pragma unroll
    for (int i = 0; i < 4; i++)
#pragma unroll
        for (int j = 0; j < 4; j++)
            s += x[(((size_t)(b * Hn + hc * 4 + i)) * Wn + wc * 4 + j) * Cn + c];
    s *= 0.0625f;
    __half h = __float2half(s);
    __half l = __float2half(s - __half2float(h));
    size_t o = a_off(b * NCn + n, c);
    g_abf[o] = h;
    g_abf[APL + o] = l;
}

// ---------------- weight fp16 hi/lo conversion (tiled) ----------------
__global__ __launch_bounds__(256) void convw_kernel(
    const float* __restrict__ w, int total, int mode)
{
    int i = blockIdx.x * 256 + threadIdx.x;
    if (i >= total) return;
    float v = w[i];
    __half h = __float2half(v);
    __half l = __float2half(v - __half2float(h));
    int n = i / 384, k = i % 384;
    size_t o = w_off(n, k);
    if (mode == 0) { g_wqh[o] = h; g_wql[o] = l; }
    else           { g_wph[o] = h; g_wpl[o] = l; }
}

// ---------------- A conversion: x (f32) -> fp16 hi/lo planes (tiled) ------
__global__ __launch_bounds__(256) void convA_kernel(
    const float* __restrict__ src, int n8)
{
    int i = blockIdx.x * 256 + threadIdx.x;
    if (i >= n8) return;
    float4 v0 = ((const float4*)src)[i * 2];
    float4 v1 = ((const float4*)src)[i * 2 + 1];
    uint4 H, L;
    H.x = pack_hf2(v0.x, v0.y); H.y = pack_hf2(v0.z, v0.w);
    H.z = pack_hf2(v1.x, v1.y); H.w = pack_hf2(v1.z, v1.w);
    float h0 = __half2float(__float2half(v0.x));
    float h1 = __half2float(__float2half(v0.y));
    float h2 = __half2float(__float2half(v0.z));
    float h3 = __half2float(__float2half(v0.w));
    float h4 = __half2float(__float2half(v1.x));
    float h5 = __half2float(__float2half(v1.y));
    float h6 = __half2float(__float2half(v1.z));
    float h7 = __half2float(__float2half(v1.w));
    L.x = pack_hf2(v0.x - h0, v0.y - h1);
    L.y = pack_hf2(v0.z - h2, v0.w - h3);
    L.z = pack_hf2(v1.x - h4, v1.y - h5);
    L.w = pack_hf2(v1.z - h6, v1.w - h7);
    int m = i / 48, k0 = (i % 48) * 8;
    size_t o = a_off(m, k0);
    *(uint4*)(g_abf + o)       = H;
    *(uint4*)(g_abf + APL + o) = L;
}

// ---------------- tensor-core GEMM: O[M,N] = A[M,384] * W[N,384]^T --------
// fp16 3-pass: acc = Ah*Wh + Al*Wh + Ah*Wl.  Operands tiled; staged with
// cp.async.bulk in a 3-stage mbarrier pipeline; each stage holds a PAIR of
// 16-k chunks (BK=32) -> only 12 wait/sync latency chains.
// 256x128 tile, 512 threads (4x4 warps, 64x32 warp tile).
#define AH_S 0
#define AL_S 24576
#define WH_S 49152
#define WL_S 61440
#define STG  73728
#define GSMEM (3 * STG + 64)

__global__ __launch_bounds__(512, 1) void gemm_mma(
    const float* __restrict__ bias, float* __restrict__ Oext, int N, int mode)
{
    extern __shared__ __half sm[];

    float* O = (mode == 0) ? g_qkvc : (mode == 1) ? g_qkvf : Oext;
    const __half* WHp = (mode == 2) ? g_wph : g_wqh;
    const __half* WLp = (mode == 2) ? g_wpl : g_wql;

    int tid = threadIdx.x;
    int m0 = blockIdx.y * 256, n0 = blockIdx.x * 128;

    const __half* aH = g_abf + (size_t)(m0 >> 8) * ATILEH;
    const __half* aL = aH + APL;
    const __half* wH = WHp + (size_t)(n0 >> 7) * WTILEH;
    const __half* wL = WLp + (size_t)(n0 >> 7) * WTILEH;

    uint32_t sbase = smem_u32(sm);
    uint32_t mb = sbase + 3 * STG;

    if (tid == 0) {
#pragma unroll
        for (int s = 0; s < 3; s++) mbar_init(mb + s * 8, 1);
    }
    __syncthreads();

    // prologue: stages 0,1 <- chunk pairs 0,1
    if (tid == 0) {
#pragma unroll
        for (int s = 0; s < 2; s++) {
            uint32_t sb = sbase + s * STG;
            uint32_t mbs = mb + s * 8;
            mbar_expect(mbs, STG);
            bulkcp(sb + AH_S, aH + s * 2 * ACHH, 24576, mbs);
            bulkcp(sb + AL_S, aL + s * 2 * ACHH, 24576, mbs);
            bulkcp(sb + WH_S, wH + s * 2 * WCHH, 12288, mbs);
            bulkcp(sb + WL_S, wL + s * 2 * WCHH, 12288, mbs);
        }
    }

    int lane = tid & 31;
    int wid = tid >> 5;
    int mbase = (wid & 3) * 64;
    int nbase = (wid >> 2) * 32;

    int ar = lane & 15, ak = (lane >> 4) * 8;
    uint32_t offA0 = ((mbase + ar) * TP + ak) * 2;
    int br = (lane & 7) + ((lane >> 4) << 3), bk = ((lane >> 3) & 1) * 8;
    uint32_t offB0 = ((nbase + br) * TP + bk) * 2;

    float acc[4][4][4];
#pragma unroll
    for (int i = 0; i < 4; i++)
#pragma unroll
        for (int j = 0; j < 4; j++)
#pragma unroll
            for (int k = 0; k < 4; k++) acc[i][j][k] = 0.f;

    int stg = 0, par = 0;
    for (int pc = 0; pc < 12; pc++) {
        mbar_wait(mb + stg * 8, par);
        uint32_t bb = sbase + stg * STG;

        uint32_t ah[4][4], al[4][4], bf[2][4];
        // ---- sub 0 loads (A sub-block at +0, W sub-block at +0) ----
#pragma unroll
        for (int g = 0; g < 4; g++)
            ldmx4(ah[g], bb + AH_S + offA0 + g * 768);
#pragma unroll
        for (int g = 0; g < 4; g++)
            ldmx4(al[g], bb + AL_S + offA0 + g * 768);
#pragma unroll
        for (int g = 0; g < 2; g++)
            ldmx4(bf[g], bb + WH_S + offB0 + g * 768);

        __syncthreads();  // every warp has finished reading stage (pc-1)%3

        if (tid == 0 && pc < 10) {
            int s = (pc + 2) % 3;
            uint32_t sb = sbase + s * STG;
            uint32_t mbs = mb + s * 8;
            int ck = pc + 2;
            mbar_expect(mbs, STG);
            bulkcp(sb + AH_S, aH + ck * 2 * ACHH, 24576, mbs);
            bulkcp(sb + AL_S, aL + ck * 2 * ACHH, 24576, mbs);
            bulkcp(sb + WH_S, wH + ck * 2 * WCHH, 12288, mbs);
            bulkcp(sb + WL_S, wL + ck * 2 * WCHH, 12288, mbs);
        }

        // ---- sub 0 math: Ah*Wh, Al*Wh, Ah*Wl ----
#pragma unroll
        for (int mi = 0; mi < 4; mi++)
#pragma unroll
            for (int g = 0; g < 2; g++)
#pragma unroll
                for (int sub = 0; sub < 2; sub++)
                    mma16816(acc[mi][g * 2 + sub], ah[mi], &bf[g][sub * 2]);
#pragma unroll
        for (int mi = 0; mi < 4; mi++)
#pragma unroll
            for (int g = 0; g < 2; g++)
#pragma unroll
                for (int sub = 0; sub < 2; sub++)
                    mma16816(acc[mi][g * 2 + sub], al[mi], &bf[g][sub * 2]);
#pragma unroll
        for (int g = 0; g < 2; g++)
            ldmx4(bf[g], bb + WL_S + offB0 + g * 768);
#pragma unroll
        for (int mi = 0; mi < 4; mi++)
#pragma unroll
            for (int g = 0; g < 2; g++)
#pragma unroll
                for (int sub = 0; sub < 2; sub++)
                    mma16816(acc[mi][g * 2 + sub], ah[mi], &bf[g][sub * 2]);

        // ---- sub 1 (A at +12288 B, W at +6144 B) ----
#pragma unroll
        for (int g = 0; g < 4; g++)
            ldmx4(ah[g], bb + AH_S + 12288 + offA0 + g * 768);
#pragma unroll
        for (int g = 0; g < 4; g++)
            ldmx4(al[g], bb + AL_S + 12288 + offA0 + g * 768);
#pragma unroll
        for (int g = 0; g < 2; g++)
            ldmx4(bf[g], bb + WH_S + 6144 + offB0 + g * 768);
#pragma unroll
        for (int mi = 0; mi < 4; mi++)
#pragma unroll
            for (int g = 0; g < 2; g++)
#pragma unroll
                for (int sub = 0; sub < 2; sub++)
                    mma16816(acc[mi][g * 2 + sub], ah[mi], &bf[g][sub * 2]);
#pragma unroll
        for (int mi = 0; mi < 4; mi++)
#pragma unroll
            for (int g = 0; g < 2; g++)
#pragma unroll
                for (int sub = 0; sub < 2; sub++)
                    mma16816(acc[mi][g * 2 + sub], al[mi], &bf[g][sub * 2]);
#pragma unroll
        for (int g = 0; g < 2; g++)
            ldmx4(bf[g], bb + WL_S + 6144 + offB0 + g * 768);
#pragma unroll
        for (int mi = 0; mi < 4; mi++)
#pragma unroll
            for (int g = 0; g < 2; g++)
#pragma unroll
                for (int sub = 0; sub < 2; sub++)
                    mma16816(acc[mi][g * 2 + sub], ah[mi], &bf[g][sub * 2]);

        if (++stg == 3) { stg = 0; par ^= 1; }
    }

    // epilogue
    int rbase = m0 + mbase, cbase = n0 + nbase;
#pragma unroll
    for (int mi = 0; mi < 4; mi++)
#pragma unroll
        for (int ni = 0; ni < 4; ni++) {
            int rrow = rbase + mi * 16 + (lane >> 2);
            int col = cbase + ni * 8 + (lane & 3) * 2;
            float b0 = 0.f, b1 = 0.f;
            if (mode == 2) { b0 = bias[col]; b1 = bias[col + 1]; }
            float2 v0 = make_float2(acc[mi][ni][0] + b0, acc[mi][ni][1] + b1);
            float2 v1 = make_float2(acc[mi][ni][2] + b0, acc[mi][ni][3] + b1);
            *(float2*)&O[(size_t)rrow * N + col] = v0;
            *(float2*)&O[(size_t)(rrow + 8) * N + col] = v1;
        }
}

// ---------------- K3: coarse routing attention + top-k (flash-style) ------
#define CA_SMEM (2 * 256 * 48 * 4)
__global__ __launch_bounds__(128) void coarse_attn_kernel()
{
    extern __shared__ float cas[];
    float* Ks = cas;
    float* Vs = cas + 256 * 48;

    int bid = blockIdx.x;
    int half = bid & 1;
    int hd = (bid >> 1) & 7;
    int b = bid >> 4;
    int tid = threadIdx.x;

    const float* base = g_qkvc + (size_t)b * NCn * C3n;

    for (int idx = tid; idx < 3072; idx += 128) {
        int j = idx / 12, d4 = (idx % 12) * 4;
        const float* rp = base + (size_t)j * C3n + Cn + hd * Dh + d4;
        *(float4*)&Ks[j * 48 + d4] = *(const float4*)rp;
        *(float4*)&Vs[j * 48 + d4] = *(const float4*)(rp + Cn);
    }

    int q = half * 128 + tid;
    float qv[48];
    const float* qp = base + (size_t)q * C3n + hd * Dh;
#pragma unroll
    for (int i = 0; i < 12; i++) {
        float4 v = *(const float4*)(qp + i * 4);
        qv[i * 4 + 0] = v.x; qv[i * 4 + 1] = v.y;
        qv[i * 4 + 2] = v.z; qv[i * 4 + 3] = v.w;
    }
    __syncthreads();

    float v0 = -FLT_MAX, v1 = -FLT_MAX, v2 = -FLT_MAX, v3 = -FLT_MAX;
    int i0 = 0, i1 = 0, i2 = 0, i3 = 0;
    for (int j = 0; j < 256; j++) {
        float a0 = 0.f, a1 = 0.f, a2 = 0.f, a3 = 0.f;
        const float* kp = &Ks[j * 48];
#pragma unroll
        for (int d4 = 0; d4 < 12; d4++) {
            float4 kv = *(const float4*)(kp + d4 * 4);
            a0 += qv[d4 * 4 + 0] * kv.x;
            a1 += qv[d4 * 4 + 1] * kv.y;
            a2 += qv[d4 * 4 + 2] * kv.z;
            a3 += qv[d4 * 4 + 3] * kv.w;
        }
        float s = (a0 + a1) + (a2 + a3);
        if (s > v3) {
            if (s > v0)      { v3 = v2; i3 = i2; v2 = v1; i2 = i1; v1 = v0; i1 = i0; v0 = s; i0 = j; }
            else if (s > v1) { v3 = v2; i3 = i2; v2 = v1; i2 = i1; v1 = s; i1 = j; }
            else if (s > v2) { v3 = v2; i3 = i2; v2 = s; i2 = j; }
            else             { v3 = s; i3 = j; }
        }
    }
    int obase = ((b * 8 + hd) * 256 + q) * 4;
    g_topk[obase + 0] = i0; g_topk[obase + 1] = i1;
    g_topk[obase + 2] = i2; g_topk[obase + 3] = i3;

    float mx = v0 * SCALE;

    float oacc[48];
#pragma unroll
    for (int d = 0; d < 48; d++) oacc[d] = 0.f;
    float psum = 0.f;
    for (int j = 0; j < 256; j++) {
        float a0 = 0.f, a1 = 0.f, a2 = 0.f, a3 = 0.f;
        const float* kp = &Ks[j * 48];
#pragma unroll
        for (int d4 = 0; d4 < 12; d4++) {
            float4 kv = *(const float4*)(kp + d4 * 4);
            a0 += qv[d4 * 4 + 0] * kv.x;
            a1 += qv[d4 * 4 + 1] * kv.y;
            a2 += qv[d4 * 4 + 2] * kv.z;
            a3 += qv[d4 * 4 + 3] * kv.w;
        }
        float p = __expf(((a0 + a1) + (a2 + a3)) * SCALE - mx);
        psum += p;
        const float* vp = &Vs[j * 48];
#pragma unroll
        for (int d4 = 0; d4 < 12; d4++) {
            float4 vv = *(const float4*)(vp + d4 * 4);
            oacc[d4 * 4 + 0] += p * vv.x;
            oacc[d4 * 4 + 1] += p * vv.y;
            oacc[d4 * 4 + 2] += p * vv.z;
            oacc[d4 * 4 + 3] += p * vv.w;
        }
    }
    float inv = 1.f / psum;
    float* op = &g_xo[((size_t)(b * NCn + q)) * Cn + hd * Dh];
#pragma unroll
    for (int i = 0; i < 12; i++) {
        float4 v = make_float4(oacc[i * 4] * inv, oacc[i * 4 + 1] * inv,
                               oacc[i * 4 + 2] * inv, oacc[i * 4 + 3] * inv);
        *(float4*)(op + i * 4) = v;
    }
}

// ---------------- K5: fine windowed attention (register-tiled) ------------
#define QT_P 18
#define KT_P 68
#define VS_P 52
#define A2_P 68
__global__ __launch_bounds__(128) void fine_attn_kernel()
{
    int bid = blockIdx.x;
    int n  = bid & 255;
    int hd = (bid >> 8) & 7;
    int b  = bid >> 11;

    __shared__ float Qt[48 * QT_P];
    __shared__ float Kt[48 * KT_P];
    __shared__ float Vs[64 * VS_P];
    __shared__ float A2[16 * A2_P];
    __shared__ int   wins[4];

    int tid = threadIdx.x;
    int hc = n >> 4, wc = n & 15;
    const float* base = g_qkvf + (size_t)b * HWn * C3n;

    if (tid < 4) wins[tid] = g_topk[(size_t)bid * 4 + tid];

    for (int idx = tid; idx < 16 * 12; idx += 128) {
        int p = idx / 12, d4 = (idx % 12) * 4;
        int s = (hc * 4 + (p >> 2)) * Wn + wc * 4 + (p & 3);
        float4 v = *(const float4*)&base[(size_t)s * C3n + hd * Dh + d4];
        Qt[(d4 + 0) * QT_P + p] = v.x;
        Qt[(d4 + 1) * QT_P + p] = v.y;
        Qt[(d4 + 2) * QT_P + p] = v.z;
        Qt[(d4 + 3) * QT_P + p] = v.w;
    }
    __syncthreads();

    for (int idx = tid; idx < 64 * 12; idx += 128) {
        int p = idx / 12, d4 = (idx % 12) * 4;
        int t = p >> 4, pl = p & 15;
        int m = wins[t];
        int s = ((m >> 4) * 4 + (pl >> 2)) * Wn + (m & 15) * 4 + (pl & 3);
        const float* rw = &base[(size_t)s * C3n + hd * Dh + d4];
        float4 kv = *(const float4*)(rw + Cn);
        float4 vv = *(const float4*)(rw + 2 * Cn);
        Kt[(d4 + 0) * KT_P + p] = kv.x;
        Kt[(d4 + 1) * KT_P + p] = kv.y;
        Kt[(d4 + 2) * KT_P + p] = kv.z;
        Kt[(d4 + 3) * KT_P + p] = kv.w;
        *(float4*)&Vs[p * VS_P + d4] = vv;
    }
    __syncthreads();

    {
        int tr = tid >> 4, tc = tid & 15;
        int r0 = tr * 2, c0 = tc * 4;
        float a0[4] = {0.f, 0.f, 0.f, 0.f};
        float a1[4] = {0.f, 0.f, 0.f, 0.f};
#pragma unroll 8
        for (int dd = 0; dd < Dh; dd++) {
            float2 qv = *(const float2*)&Qt[dd * QT_P + r0];
            float4 kv = *(const float4*)&Kt[dd * KT_P + c0];
            a0[0] += qv.x * kv.x; a0[1] += qv.x * kv.y;
            a0[2] += qv.x * kv.z; a0[3] += qv.x * kv.w;
            a1[0] += qv.y * kv.x; a1[1] += qv.y * kv.y;
            a1[2] += qv.y * kv.z; a1[3] += qv.y * kv.w;
        }
        float4 w0 = make_float4(a0[0] * SCALE, a0[1] * SCALE, a0[2] * SCALE, a0[3] * SCALE);
        float4 w1 = make_float4(a1[0] * SCALE, a1[1] * SCALE, a1[2] * SCALE, a1[3] * SCALE);
        *(float4*)&A2[r0 * A2_P + c0] = w0;
        *(float4*)&A2[(r0 + 1) * A2_P + c0] = w1;
    }
    __syncthreads();

    {
        int row = tid >> 3, j = tid & 7;
        float* ap = &A2[row * A2_P + j * 8];
        float v[8];
        float mx = -FLT_MAX;
#pragma unroll
        for (int i = 0; i < 8; i++) { v[i] = ap[i]; mx = fmaxf(mx, v[i]); }
#pragma unroll
        for (int m = 1; m < 8; m <<= 1)
            mx = fmaxf(mx, __shfl_xor_sync(0xffffffffu, mx, m));
        float sum = 0.f;
#pragma unroll
        for (int i = 0; i < 8; i++) { v[i] = __expf(v[i] - mx); sum += v[i]; }
#pragma unroll
        for (int m = 1; m < 8; m <<= 1)
            sum += __shfl_xor_sync(0xffffffffu, sum, m);
        float inv = 1.f / sum;
#pragma unroll
        for (int i = 0; i < 8; i++) ap[i] = v[i] * inv;
    }
    __syncthreads();

    {
        int tr2 = tid >> 4, tc2 = tid & 15;
        int p0 = tr2 * 2, dd0 = tc2 * 3;
        float o0[3] = {0.f, 0.f, 0.f};
        float o1[3] = {0.f, 0.f, 0.f};
#pragma unroll 8
        for (int kk = 0; kk < 64; kk++) {
            float av0 = A2[p0 * A2_P + kk];
            float av1 = A2[(p0 + 1) * A2_P + kk];
            const float* vp = &Vs[kk * VS_P + dd0];
            float v0 = vp[0], v1 = vp[1], v2 = vp[2];
            o0[0] += av0 * v0; o0[1] += av0 * v1; o0[2] += av0 * v2;
            o1[0] += av1 * v0; o1[1] += av1 * v1; o1[2] += av1 * v2;
        }
#pragma unroll
        for (int pi = 0; pi < 2; pi++) {
            int p = p0 + pi;
            int yy = hc * 4 + (p >> 2), xx = wc * 4 + (p & 3);
            float* op = &g_yo[(((size_t)(b * Hn + yy)) * Wn + xx) * Cn + hd * Dh + dd0];
            if (pi == 0) { op[0] = o0[0]; op[1] = o0[1]; op[2] = o0[2]; }
            else         { op[0] = o1[0]; op[1] = o1[1]; op[2] = o1[2]; }
        }
    }
}

// ---------------- K6: upsample(xo) -> dwconv3x3(dwx) -> mix with yo -------
__global__ __launch_bounds__(384) void dwmix_kernel(
    const float* __restrict__ dwxw, const float* __restrict__ dwxb)
{
    __shared__ float wsh[Cn * 9];
    int tid = threadIdx.x;
    for (int i = tid; i < Cn * 9; i += 384) wsh[i] = dwxw[i];
    __syncthreads();

    int b  = blockIdx.x >> 6;
    int yy = blockIdx.x & 63;
    int c  = tid;
    float w[9];
#pragma unroll
    for (int i = 0; i < 9; i++) w[i] = wsh[c * 9 + i];
    float bias = dwxb[c];

    const float* xob = g_xo + (size_t)b * NCn * Cn + c;
    bool up = yy > 0, dn = yy < 63;
    int ru = (yy - 1) >> 2, rm = yy >> 2, rd = (yy + 1) >> 2;

    float3 cm = make_float3(0.f, 0.f, 0.f), cc, cp;
    cc.x = up ? xob[(size_t)(ru * 16) * Cn] : 0.f;
    cc.y = xob[(size_t)(rm * 16) * Cn];
    cc.z = dn ? xob[(size_t)(rd * 16) * Cn] : 0.f;

    size_t pix0 = ((size_t)(b * Hn + yy)) * Wn;
    for (int xx = 0; xx < 64; xx++) {
        if (xx < 63) {
            int xc4 = (xx + 1) >> 2;
            cp.x = up ? xob[(size_t)(ru * 16 + xc4) * Cn] : 0.f;
            cp.y = xob[(size_t)(rm * 16 + xc4) * Cn];
            cp.z = dn ? xob[(size_t)(rd * 16 + xc4) * Cn] : 0.f;
        } else {
            cp = make_float3(0.f, 0.f, 0.f);
        }
        float acc = bias
            + w[0] * cm.x + w[1] * cc.x + w[2] * cp.x
            + w[3] * cm.y + w[4] * cc.y + w[5] * cp.y
            + w[6] * cm.z + w[7] * cc.z + w[8] * cp.z;
        size_t pix = pix0 + xx;
        g_z[pix * Cn + c] = 0.5f * acc + 0.5f * g_yo[pix * Cn + c];
        cm = cc; cc = cp;
    }
}

// ---------------- K7: dwconv3x3(dw) on z -> fp16 hi/lo planes (tiled) -----
__global__ __launch_bounds__(384) void dwconv2_kernel(
    const float* __restrict__ dww, const float* __restrict__ dwb)
{
    __shared__ float wsh[Cn * 9];
    int tid = threadIdx.x;
    for (int i = tid; i < Cn * 9; i += 384) wsh[i] = dww[i];
    __syncthreads();

    int b  = blockIdx.x >> 6;
    int yy = blockIdx.x & 63;
    int c  = tid;
    float w[9];
#pragma unroll
    for (int i = 0; i < 9; i++) w[i] = wsh[c * 9 + i];
    float bias = dwb[c];

    const float* zb = g_z + (size_t)b * HWn * Cn + c;
    bool up = yy > 0, dn = yy < 63;
    size_t rowm = (size_t)yy * Wn;

    float3 cm = make_float3(0.f, 0.f, 0.f), cc, cp;
    cc.x = up ? zb[(rowm - Wn) * Cn] : 0.f;
    cc.y = zb[rowm * Cn];
    cc.z = dn ? zb[(rowm + Wn) * Cn] : 0.f;

    int mrow0 = b * HWn + yy * Wn;
    for (int xx = 0; xx < 64; xx++) {
        if (xx < 63) {
            size_t bcol = rowm + xx + 1;
            cp.x = up ? zb[(bcol - Wn) * Cn] : 0.f;
            cp.y = zb[bcol * Cn];
            cp.z = dn ? zb[(bcol + Wn) * Cn] : 0.f;
        } else {
            cp = make_float3(0.f, 0.f, 0.f);
        }
        float acc = bias
            + w[0] * cm.x + w[1] * cc.x + w[2] * cp.x
            + w[3] * cm.y + w[4] * cc.y + w[5] * cp.y
            + w[6] * cm.z + w[7] * cc.z + w[8] * cp.z;
        __half h = __float2half(acc);
        __half l = __float2half(acc - __half2float(h));
        size_t o = a_off(mrow0 + xx, c);
        g_abf[o] = h;
        g_abf[APL + o] = l;
        cm = cc; cc = cp;
    }
}

// ---------------- launch ----------------
extern "C" void kernel_launch(void* const* d_in, const int* in_sizes, int n_in,
                              void* d_out, int out_size)
{
    const float* x     = (const float*)d_in[0];
    const float* qkv_w = (const float*)d_in[1];
    const float* dwx_w = (const float*)d_in[2];
    const float* dwx_b = (const float*)d_in[3];
    const float* dw_w  = (const float*)d_in[4];
    const float* dw_b  = (const float*)d_in[5];
    const float* pw_w  = (const float*)d_in[6];
    const float* pw_b  = (const float*)d_in[7];
    float* out = (float*)d_out;

    cudaFuncSetAttribute(gemm_mma, cudaFuncAttributeMaxDynamicSharedMemorySize,
                         GSMEM);
    cudaFuncSetAttribute(coarse_attn_kernel,
                         cudaFuncAttributeMaxDynamicSharedMemorySize, CA_SMEM);

    // weight conversions (tiny)
    convw_kernel<<<(C3n * Cn + 255) / 256, 256>>>(qkv_w, C3n * Cn, 0);
    convw_kernel<<<(Cn * Cn + 255) / 256, 256>>>(pw_w, Cn * Cn, 1);

    // 1) coarse pooling (writes fp16 tiled planes directly)
    pool_kernel<<<Bn * NCn, Cn>>>(x);

    // 2) coarse QKV: (2048 x 1152 x 384)
    gemm_mma<<<dim3(C3n / 128, (Bn * NCn) / 256), 512, GSMEM>>>(
        nullptr, nullptr, C3n, 0);

    // 3) coarse routing attention + top-k
    coarse_attn_kernel<<<Bn * NHd * 2, 128, CA_SMEM>>>();

    // 4) fine QKV: (32768 x 1152 x 384)
    convA_kernel<<<(Bn * HWn * 48 + 255) / 256, 256>>>(x, Bn * HWn * 48);
    gemm_mma<<<dim3(C3n / 128, (Bn * HWn) / 256), 512, GSMEM>>>(
        nullptr, nullptr, C3n, 1);

    // 5) fine windowed attention
    fine_attn_kernel<<<Bn * NHd * NCn, 128>>>();

    // 6) upsample+dwconv(dwx)+mix
    dwmix_kernel<<<Bn * Hn, Cn>>>(dwx_w, dwx_b);

    // 7) dwconv(dw) -> fp16 tiled planes directly
    dwconv2_kernel<<<Bn * Hn, Cn>>>(dw_w, dw_b);

    // 8) pointwise projection (+bias): (32768 x 384 x 384)
    gemm_mma<<<dim3(Cn / 128, (Bn * HWn) / 256), 512, GSMEM>>>(
        pw_b, out, Cn, 2);
}

// round 13
// speedup vs baseline: 1.5352x; 1.0766x over previous
#include <cuda_runtime.h>
#include <cuda_fp16.h>
#include <float.h>
#include <stdint.h>

// Problem constants
#define Bn   8
#define Hn   64
#define Wn   64
#define Cn   384
#define NHd  8
#define Dh   48
#define NCn  256
#define HWn  4096
#define C3n  1152
#define SCALE 0.14433756729740643f

// ---- tiled operand layout: [tile][kchunk(24)][rows][pitch 24 halves] ----
#define TP     24
#define ACHH   (256 * TP)
#define WCHH   (128 * TP)
#define ATILEH (24 * ACHH)
#define WTILEH (24 * WCHH)
#define APL    ((size_t)128 * ATILEH)

// ---------------- scratch (device globals; no allocation) ----------------
__device__ float g_qkvc[Bn * NCn * C3n];
__device__ int   g_topk[Bn * NHd * NCn * 4];
__device__ float g_xo  [Bn * NCn * Cn];
__device__ float g_qkvf[(size_t)Bn * HWn * C3n];
__device__ float g_yo  [(size_t)Bn * HWn * Cn];
__device__ float g_z   [(size_t)Bn * HWn * Cn];
__device__ __half g_abf[2 * APL];
__device__ __half g_wqh[9 * WTILEH];
__device__ __half g_wql[9 * WTILEH];
__device__ __half g_wph[3 * WTILEH];
__device__ __half g_wpl[3 * WTILEH];

__device__ __forceinline__ size_t a_off(int m, int k) {
    return (size_t)(m >> 8) * ATILEH + (size_t)(k >> 4) * ACHH
         + (m & 255) * TP + (k & 15);
}
__device__ __forceinline__ size_t w_off(int n, int k) {
    return (size_t)(n >> 7) * WTILEH + (size_t)(k >> 4) * WCHH
         + (n & 127) * TP + (k & 15);
}

// ---------------- helpers ----------------
__device__ __forceinline__ uint32_t smem_u32(const void* p) {
    uint32_t a;
    asm("{ .reg .u64 t; cvta.to.shared.u64 t, %1; cvt.u32.u64 %0, t; }"
        : "=r"(a) : "l"(p));
    return a;
}
__device__ __forceinline__ void ldmx4(uint32_t* r, uint32_t addr) {
    asm volatile("ldmatrix.sync.aligned.m8n8.x4.shared.b16 {%0,%1,%2,%3}, [%4];"
        : "=r"(r[0]), "=r"(r[1]), "=r"(r[2]), "=r"(r[3]) : "r"(addr));
}
__device__ __forceinline__ void mma16816(float* d, const uint32_t* a, const uint32_t* b) {
    asm volatile(
        "mma.sync.aligned.m16n8k16.row.col.f32.f16.f16.f32 "
        "{%0,%1,%2,%3}, {%4,%5,%6,%7}, {%8,%9}, {%0,%1,%2,%3};"
        : "+f"(d[0]), "+f"(d[1]), "+f"(d[2]), "+f"(d[3])
        : "r"(a[0]), "r"(a[1]), "r"(a[2]), "r"(a[3]), "r"(b[0]), "r"(b[1]));
}
__device__ __forceinline__ uint32_t pack_hf2(float x, float y) {
    unsigned short hx = __half_as_ushort(__float2half(x));
    unsigned short hy = __half_as_ushort(__float2half(y));
    return (uint32_t)hx | ((uint32_t)hy << 16);
}
__device__ __forceinline__ void mbar_init(uint32_t a, uint32_t cnt) {
    asm volatile("mbarrier.init.shared.b64 [%0], %1;" :: "r"(a), "r"(cnt) : "memory");
}
__device__ __forceinline__ void mbar_expect(uint32_t a, uint32_t bytes) {
    asm volatile("mbarrier.arrive.expect_tx.shared.b64 _, [%0], %1;"
                 :: "r"(a), "r"(bytes) : "memory");
}
__device__ __forceinline__ void mbar_wait(uint32_t a, uint32_t parity) {
    asm volatile(
        "{\n\t.reg .pred P;\n\t"
        "WL%=:\n\t"
        "mbarrier.try_wait.parity.acquire.cta.shared::cta.b64 P, [%0], %1, 0x989680;\n\t"
        "@P bra.uni WD%=;\n\t"
        "bra.uni WL%=;\n\t"
        "WD%=:\n\t}"
        :: "r"(a), "r"(parity) : "memory");
}
__device__ __forceinline__ void bulkcp(uint32_t sdst, const void* gsrc,
                                       uint32_t bytes, uint32_t mbar) {
    asm volatile(
        "cp.async.bulk.shared::cta.global.mbarrier::complete_tx::bytes "
        "[%0], [%1], %2, [%3];"
        :: "r"(sdst), "l"(gsrc), "r"(bytes), "r"(mbar) : "memory");
}

// ---------------- K1: 4x4 average pool -> fp16 hi/lo planes (tiled) -------
__global__ __launch_bounds__(384) void pool_kernel(const float* __restrict__ x)
{
    int blk = blockIdx.x;
    int n = blk & 255, b = blk >> 8;
    int hc = n >> 4, wc = n & 15;
    int c = threadIdx.x;
    float s = 0.f;
#pragma unroll
    for (int i = 0; i < 4; i++)
#pragma unroll
        for (int j = 0; j < 4; j++)
            s += x[(((size_t)(b * Hn + hc * 4 + i)) * Wn + wc * 4 + j) * Cn + c];
    s *= 0.0625f;
    __half h = __float2half(s);
    __half l = __float2half(s - __half2float(h));
    size_t o = a_off(b * NCn + n, c);
    g_abf[o] = h;
    g_abf[APL + o] = l;
}

// ---------------- weight fp16 hi/lo conversion (tiled) ----------------
__global__ __launch_bounds__(256) void convw_kernel(
    const float* __restrict__ w, int total, int mode)
{
    int i = blockIdx.x * 256 + threadIdx.x;
    if (i >= total) return;
    float v = w[i];
    __half h = __float2half(v);
    __half l = __float2half(v - __half2float(h));
    int n = i / 384, k = i % 384;
    size_t o = w_off(n, k);
    if (mode == 0) { g_wqh[o] = h; g_wql[o] = l; }
    else           { g_wph[o] = h; g_wpl[o] = l; }
}

// ---------------- A conversion: x (f32) -> fp16 hi/lo planes (tiled) ------
__global__ __launch_bounds__(256) void convA_kernel(
    const float* __restrict__ src, int n8)
{
    int i = blockIdx.x * 256 + threadIdx.x;
    if (i >= n8) return;
    float4 v0 = ((const float4*)src)[i * 2];
    float4 v1 = ((const float4*)src)[i * 2 + 1];
    uint4 H, L;
    H.x = pack_hf2(v0.x, v0.y); H.y = pack_hf2(v0.z, v0.w);
    H.z = pack_hf2(v1.x, v1.y); H.w = pack_hf2(v1.z, v1.w);
    float h0 = __half2float(__float2half(v0.x));
    float h1 = __half2float(__float2half(v0.y));
    float h2 = __half2float(__float2half(v0.z));
    float h3 = __half2float(__float2half(v0.w));
    float h4 = __half2float(__float2half(v1.x));
    float h5 = __half2float(__float2half(v1.y));
    float h6 = __half2float(__float2half(v1.z));
    float h7 = __half2float(__float2half(v1.w));
    L.x = pack_hf2(v0.x - h0, v0.y - h1);
    L.y = pack_hf2(v0.z - h2, v0.w - h3);
    L.z = pack_hf2(v1.x - h4, v1.y - h5);
    L.w = pack_hf2(v1.z - h6, v1.w - h7);
    int m = i / 48, k0 = (i % 48) * 8;
    size_t o = a_off(m, k0);
    *(uint4*)(g_abf + o)       = H;
    *(uint4*)(g_abf + APL + o) = L;
}

// ---------------- tensor-core GEMM: O[M,N] = A[M,384] * W[N,384]^T --------
// passes==3: acc = Ah*Wh + Al*Wh + Ah*Wl (near-exact)
// passes==2: acc = Ah*Wh + Al*Wh        (W fp16 error ~2^-11)
// Operands tiled; cp.async.bulk, 3-stage mbarrier pipeline, BK=32 pairs.
// 256x128 tile, 512 threads (4x4 warps, 64x32 warp tile).
#define AH_S 0
#define AL_S 24576
#define WH_S 49152
#define WL_S 61440
#define STG  73728
#define GSMEM (3 * STG + 64)

__global__ __launch_bounds__(512, 1) void gemm_mma(
    const float* __restrict__ bias, float* __restrict__ Oext, int N, int mode,
    int passes)
{
    extern __shared__ __half sm[];

    float* O = (mode == 0) ? g_qkvc : (mode == 1) ? g_qkvf : Oext;
    const __half* WHp = (mode == 2) ? g_wph : g_wqh;
    const __half* WLp = (mode == 2) ? g_wpl : g_wql;

    int tid = threadIdx.x;
    int m0 = blockIdx.y * 256, n0 = blockIdx.x * 128;

    const __half* aH = g_abf + (size_t)(m0 >> 8) * ATILEH;
    const __half* aL = aH + APL;
    const __half* wH = WHp + (size_t)(n0 >> 7) * WTILEH;
    const __half* wL = WLp + (size_t)(n0 >> 7) * WTILEH;

    uint32_t sbase = smem_u32(sm);
    uint32_t mb = sbase + 3 * STG;

    uint32_t stgbytes = (passes == 3) ? STG : (STG - 12288);

    if (tid == 0) {
#pragma unroll
        for (int s = 0; s < 3; s++) mbar_init(mb + s * 8, 1);
    }
    __syncthreads();

    if (tid == 0) {
#pragma unroll
        for (int s = 0; s < 2; s++) {
            uint32_t sb = sbase + s * STG;
            uint32_t mbs = mb + s * 8;
            mbar_expect(mbs, stgbytes);
            bulkcp(sb + AH_S, aH + s * 2 * ACHH, 24576, mbs);
            bulkcp(sb + AL_S, aL + s * 2 * ACHH, 24576, mbs);
            bulkcp(sb + WH_S, wH + s * 2 * WCHH, 12288, mbs);
            if (passes == 3)
                bulkcp(sb + WL_S, wL + s * 2 * WCHH, 12288, mbs);
        }
    }

    int lane = tid & 31;
    int wid = tid >> 5;
    int mbase = (wid & 3) * 64;
    int nbase = (wid >> 2) * 32;

    int ar = lane & 15, ak = (lane >> 4) * 8;
    uint32_t offA0 = ((mbase + ar) * TP + ak) * 2;
    int br = (lane & 7) + ((lane >> 4) << 3), bk = ((lane >> 3) & 1) * 8;
    uint32_t offB0 = ((nbase + br) * TP + bk) * 2;

    float acc[4][4][4];
#pragma unroll
    for (int i = 0; i < 4; i++)
#pragma unroll
        for (int j = 0; j < 4; j++)
#pragma unroll
            for (int k = 0; k < 4; k++) acc[i][j][k] = 0.f;

    int stg = 0, par = 0;
    for (int pc = 0; pc < 12; pc++) {
        mbar_wait(mb + stg * 8, par);
        uint32_t bb = sbase + stg * STG;

        uint32_t ah[4][4], al[4][4], bf[2][4];
        // ---- sub 0 loads ----
#pragma unroll
        for (int g = 0; g < 4; g++)
            ldmx4(ah[g], bb + AH_S + offA0 + g * 768);
#pragma unroll
        for (int g = 0; g < 4; g++)
            ldmx4(al[g], bb + AL_S + offA0 + g * 768);
#pragma unroll
        for (int g = 0; g < 2; g++)
            ldmx4(bf[g], bb + WH_S + offB0 + g * 768);

        __syncthreads();

        if (tid == 0 && pc < 10) {
            int s = (pc + 2) % 3;
            uint32_t sb = sbase + s * STG;
            uint32_t mbs = mb + s * 8;
            int ck = pc + 2;
            mbar_expect(mbs, stgbytes);
            bulkcp(sb + AH_S, aH + ck * 2 * ACHH, 24576, mbs);
            bulkcp(sb + AL_S, aL + ck * 2 * ACHH, 24576, mbs);
            bulkcp(sb + WH_S, wH + ck * 2 * WCHH, 12288, mbs);
            if (passes == 3)
                bulkcp(sb + WL_S, wL + ck * 2 * WCHH, 12288, mbs);
        }

        // ---- sub 0 math ----
#pragma unroll
        for (int mi = 0; mi < 4; mi++)
#pragma unroll
            for (int g = 0; g < 2; g++)
#pragma unroll
                for (int sub = 0; sub < 2; sub++)
                    mma16816(acc[mi][g * 2 + sub], ah[mi], &bf[g][sub * 2]);
#pragma unroll
        for (int mi = 0; mi < 4; mi++)
#pragma unroll
            for (int g = 0; g < 2; g++)
#pragma unroll
                for (int sub = 0; sub < 2; sub++)
                    mma16816(acc[mi][g * 2 + sub], al[mi], &bf[g][sub * 2]);
        if (passes == 3) {
#pragma unroll
            for (int g = 0; g < 2; g++)
                ldmx4(bf[g], bb + WL_S + offB0 + g * 768);
#pragma unroll
            for (int mi = 0; mi < 4; mi++)
#pragma unroll
                for (int g = 0; g < 2; g++)
#pragma unroll
                    for (int sub = 0; sub < 2; sub++)
                        mma16816(acc[mi][g * 2 + sub], ah[mi], &bf[g][sub * 2]);
        }

        // ---- sub 1 ----
#pragma unroll
        for (int g = 0; g < 4; g++)
            ldmx4(ah[g], bb + AH_S + 12288 + offA0 + g * 768);
#pragma unroll
        for (int g = 0; g < 4; g++)
            ldmx4(al[g], bb + AL_S + 12288 + offA0 + g * 768);
#pragma unroll
        for (int g = 0; g < 2; g++)
            ldmx4(bf[g], bb + WH_S + 6144 + offB0 + g * 768);
#pragma unroll
        for (int mi = 0; mi < 4; mi++)
#pragma unroll
            for (int g = 0; g < 2; g++)
#pragma unroll
                for (int sub = 0; sub < 2; sub++)
                    mma16816(acc[mi][g * 2 + sub], ah[mi], &bf[g][sub * 2]);
#pragma unroll
        for (int mi = 0; mi < 4; mi++)
#pragma unroll
            for (int g = 0; g < 2; g++)
#pragma unroll
                for (int sub = 0; sub < 2; sub++)
                    mma16816(acc[mi][g * 2 + sub], al[mi], &bf[g][sub * 2]);
        if (passes == 3) {
#pragma unroll
            for (int g = 0; g < 2; g++)
                ldmx4(bf[g], bb + WL_S + 6144 + offB0 + g * 768);
#pragma unroll
            for (int mi = 0; mi < 4; mi++)
#pragma unroll
                for (int g = 0; g < 2; g++)
#pragma unroll
                    for (int sub = 0; sub < 2; sub++)
                        mma16816(acc[mi][g * 2 + sub], ah[mi], &bf[g][sub * 2]);
        }

        if (++stg == 3) { stg = 0; par ^= 1; }
    }

    // epilogue
    int rbase = m0 + mbase, cbase = n0 + nbase;
#pragma unroll
    for (int mi = 0; mi < 4; mi++)
#pragma unroll
        for (int ni = 0; ni < 4; ni++) {
            int rrow = rbase + mi * 16 + (lane >> 2);
            int col = cbase + ni * 8 + (lane & 3) * 2;
            float b0 = 0.f, b1 = 0.f;
            if (mode == 2) { b0 = bias[col]; b1 = bias[col + 1]; }
            float2 v0 = make_float2(acc[mi][ni][0] + b0, acc[mi][ni][1] + b1);
            float2 v1 = make_float2(acc[mi][ni][2] + b0, acc[mi][ni][3] + b1);
            *(float2*)&O[(size_t)rrow * N + col] = v0;
            *(float2*)&O[(size_t)(rrow + 8) * N + col] = v1;
        }
}

// ---------------- K3: coarse routing attention + top-k (flash-style) ------
#define CA_SMEM (2 * 256 * 48 * 4)
__global__ __launch_bounds__(128) void coarse_attn_kernel()
{
    extern __shared__ float cas[];
    float* Ks = cas;
    float* Vs = cas + 256 * 48;

    int bid = blockIdx.x;
    int half = bid & 1;
    int hd = (bid >> 1) & 7;
    int b = bid >> 4;
    int tid = threadIdx.x;

    const float* base = g_qkvc + (size_t)b * NCn * C3n;

    for (int idx = tid; idx < 3072; idx += 128) {
        int j = idx / 12, d4 = (idx % 12) * 4;
        const float* rp = base + (size_t)j * C3n + Cn + hd * Dh + d4;
        *(float4*)&Ks[j * 48 + d4] = *(const float4*)rp;
        *(float4*)&Vs[j * 48 + d4] = *(const float4*)(rp + Cn);
    }

    int q = half * 128 + tid;
    float qv[48];
    const float* qp = base + (size_t)q * C3n + hd * Dh;
#pragma unroll
    for (int i = 0; i < 12; i++) {
        float4 v = *(const float4*)(qp + i * 4);
        qv[i * 4 + 0] = v.x; qv[i * 4 + 1] = v.y;
        qv[i * 4 + 2] = v.z; qv[i * 4 + 3] = v.w;
    }
    __syncthreads();

    float v0 = -FLT_MAX, v1 = -FLT_MAX, v2 = -FLT_MAX, v3 = -FLT_MAX;
    int i0 = 0, i1 = 0, i2 = 0, i3 = 0;
    for (int j = 0; j < 256; j++) {
        float a0 = 0.f, a1 = 0.f, a2 = 0.f, a3 = 0.f;
        const float* kp = &Ks[j * 48];
#pragma unroll
        for (int d4 = 0; d4 < 12; d4++) {
            float4 kv = *(const float4*)(kp + d4 * 4);
            a0 += qv[d4 * 4 + 0] * kv.x;
            a1 += qv[d4 * 4 + 1] * kv.y;
            a2 += qv[d4 * 4 + 2] * kv.z;
            a3 += qv[d4 * 4 + 3] * kv.w;
        }
        float s = (a0 + a1) + (a2 + a3);
        if (s > v3) {
            if (s > v0)      { v3 = v2; i3 = i2; v2 = v1; i2 = i1; v1 = v0; i1 = i0; v0 = s; i0 = j; }
            else if (s > v1) { v3 = v2; i3 = i2; v2 = v1; i2 = i1; v1 = s; i1 = j; }
            else if (s > v2) { v3 = v2; i3 = i2; v2 = s; i2 = j; }
            else             { v3 = s; i3 = j; }
        }
    }
    int obase = ((b * 8 + hd) * 256 + q) * 4;
    g_topk[obase + 0] = i0; g_topk[obase + 1] = i1;
    g_topk[obase + 2] = i2; g_topk[obase + 3] = i3;

    float mx = v0 * SCALE;

    float oacc[48];
#pragma unroll
    for (int d = 0; d < 48; d++) oacc[d] = 0.f;
    float psum = 0.f;
    for (int j = 0; j < 256; j++) {
        float a0 = 0.f, a1 = 0.f, a2 = 0.f, a3 = 0.f;
        const float* kp = &Ks[j * 48];
#pragma unroll
        for (int d4 = 0; d4 < 12; d4++) {
            float4 kv = *(const float4*)(kp + d4 * 4);
            a0 += qv[d4 * 4 + 0] * kv.x;
            a1 += qv[d4 * 4 + 1] * kv.y;
            a2 += qv[d4 * 4 + 2] * kv.z;
            a3 += qv[d4 * 4 + 3] * kv.w;
        }
        float p = __expf(((a0 + a1) + (a2 + a3)) * SCALE - mx);
        psum += p;
        const float* vp = &Vs[j * 48];
#pragma unroll
        for (int d4 = 0; d4 < 12; d4++) {
            float4 vv = *(const float4*)(vp + d4 * 4);
            oacc[d4 * 4 + 0] += p * vv.x;
            oacc[d4 * 4 + 1] += p * vv.y;
            oacc[d4 * 4 + 2] += p * vv.z;
            oacc[d4 * 4 + 3] += p * vv.w;
        }
    }
    float inv = 1.f / psum;
    float* op = &g_xo[((size_t)(b * NCn + q)) * Cn + hd * Dh];
#pragma unroll
    for (int i = 0; i < 12; i++) {
        float4 v = make_float4(oacc[i * 4] * inv, oacc[i * 4 + 1] * inv,
                               oacc[i * 4 + 2] * inv, oacc[i * 4 + 3] * inv);
        *(float4*)(op + i * 4) = v;
    }
}

// ---------------- K5: fine windowed attention (register-tiled) ------------
#define QT_P 18
#define KT_P 68
#define VS_P 52
#define A2_P 68
__global__ __launch_bounds__(128) void fine_attn_kernel()
{
    int bid = blockIdx.x;
    int n  = bid & 255;
    int hd = (bid >> 8) & 7;
    int b  = bid >> 11;

    __shared__ float Qt[48 * QT_P];
    __shared__ float Kt[48 * KT_P];
    __shared__ float Vs[64 * VS_P];
    __shared__ float A2[16 * A2_P];
    __shared__ int   wins[4];

    int tid = threadIdx.x;
    int hc = n >> 4, wc = n & 15;
    const float* base = g_qkvf + (size_t)b * HWn * C3n;

    if (tid < 4) wins[tid] = g_topk[(size_t)bid * 4 + tid];

    for (int idx = tid; idx < 16 * 12; idx += 128) {
        int p = idx / 12, d4 = (idx % 12) * 4;
        int s = (hc * 4 + (p >> 2)) * Wn + wc * 4 + (p & 3);
        float4 v = *(const float4*)&base[(size_t)s * C3n + hd * Dh + d4];
        Qt[(d4 + 0) * QT_P + p] = v.x;
        Qt[(d4 + 1) * QT_P + p] = v.y;
        Qt[(d4 + 2) * QT_P + p] = v.z;
        Qt[(d4 + 3) * QT_P + p] = v.w;
    }
    __syncthreads();

    for (int idx = tid; idx < 64 * 12; idx += 128) {
        int p = idx / 12, d4 = (idx % 12) * 4;
        int t = p >> 4, pl = p & 15;
        int m = wins[t];
        int s = ((m >> 4) * 4 + (pl >> 2)) * Wn + (m & 15) * 4 + (pl & 3);
        const float* rw = &base[(size_t)s * C3n + hd * Dh + d4];
        float4 kv = *(const float4*)(rw + Cn);
        float4 vv = *(const float4*)(rw + 2 * Cn);
        Kt[(d4 + 0) * KT_P + p] = kv.x;
        Kt[(d4 + 1) * KT_P + p] = kv.y;
        Kt[(d4 + 2) * KT_P + p] = kv.z;
        Kt[(d4 + 3) * KT_P + p] = kv.w;
        *(float4*)&Vs[p * VS_P + d4] = vv;
    }
    __syncthreads();

    {
        int tr = tid >> 4, tc = tid & 15;
        int r0 = tr * 2, c0 = tc * 4;
        float a0[4] = {0.f, 0.f, 0.f, 0.f};
        float a1[4] = {0.f, 0.f, 0.f, 0.f};
#pragma unroll 8
        for (int dd = 0; dd < Dh; dd++) {
            float2 qv = *(const float2*)&Qt[dd * QT_P + r0];
            float4 kv = *(const float4*)&Kt[dd * KT_P + c0];
            a0[0] += qv.x * kv.x; a0[1] += qv.x * kv.y;
            a0[2] += qv.x * kv.z; a0[3] += qv.x * kv.w;
            a1[0] += qv.y * kv.x; a1[1] += qv.y * kv.y;
            a1[2] += qv.y * kv.z; a1[3] += qv.y * kv.w;
        }
        float4 w0 = make_float4(a0[0] * SCALE, a0[1] * SCALE, a0[2] * SCALE, a0[3] * SCALE);
        float4 w1 = make_float4(a1[0] * SCALE, a1[1] * SCALE, a1[2] * SCALE, a1[3] * SCALE);
        *(float4*)&A2[r0 * A2_P + c0] = w0;
        *(float4*)&A2[(r0 + 1) * A2_P + c0] = w1;
    }
    __syncthreads();

    {
        int row = tid >> 3, j = tid & 7;
        float* ap = &A2[row * A2_P + j * 8];
        float v[8];
        float mx = -FLT_MAX;
#pragma unroll
        for (int i = 0; i < 8; i++) { v[i] = ap[i]; mx = fmaxf(mx, v[i]); }
#pragma unroll
        for (int m = 1; m < 8; m <<= 1)
            mx = fmaxf(mx, __shfl_xor_sync(0xffffffffu, mx, m));
        float sum = 0.f;
#pragma unroll
        for (int i = 0; i < 8; i++) { v[i] = __expf(v[i] - mx); sum += v[i]; }
#pragma unroll
        for (int m = 1; m < 8; m <<= 1)
            sum += __shfl_xor_sync(0xffffffffu, sum, m);
        float inv = 1.f / sum;
#pragma unroll
        for (int i = 0; i < 8; i++) ap[i] = v[i] * inv;
    }
    __syncthreads();

    {
        int tr2 = tid >> 4, tc2 = tid & 15;
        int p0 = tr2 * 2, dd0 = tc2 * 3;
        float o0[3] = {0.f, 0.f, 0.f};
        float o1[3] = {0.f, 0.f, 0.f};
#pragma unroll 8
        for (int kk = 0; kk < 64; kk++) {
            float av0 = A2[p0 * A2_P + kk];
            float av1 = A2[(p0 + 1) * A2_P + kk];
            const float* vp = &Vs[kk * VS_P + dd0];
            float v0 = vp[0], v1 = vp[1], v2 = vp[2];
            o0[0] += av0 * v0; o0[1] += av0 * v1; o0[2] += av0 * v2;
            o1[0] += av1 * v0; o1[1] += av1 * v1; o1[2] += av1 * v2;
        }
#pragma unroll
        for (int pi = 0; pi < 2; pi++) {
            int p = p0 + pi;
            int yy = hc * 4 + (p >> 2), xx = wc * 4 + (p & 3);
            float* op = &g_yo[(((size_t)(b * Hn + yy)) * Wn + xx) * Cn + hd * Dh + dd0];
            if (pi == 0) { op[0] = o0[0]; op[1] = o0[1]; op[2] = o0[2]; }
            else         { op[0] = o1[0]; op[1] = o1[1]; op[2] = o1[2]; }
        }
    }
}

// ---------------- K6: upsample(xo) -> dwconv3x3(dwx) -> mix with yo -------
__global__ __launch_bounds__(384) void dwmix_kernel(
    const float* __restrict__ dwxw, const float* __restrict__ dwxb)
{
    __shared__ float wsh[Cn * 9];
    int tid = threadIdx.x;
    for (int i = tid; i < Cn * 9; i += 384) wsh[i] = dwxw[i];
    __syncthreads();

    int b  = blockIdx.x >> 6;
    int yy = blockIdx.x & 63;
    int c  = tid;
    float w[9];
#pragma unroll
    for (int i = 0; i < 9; i++) w[i] = wsh[c * 9 + i];
    float bias = dwxb[c];

    const float* xob = g_xo + (size_t)b * NCn * Cn + c;
    bool up = yy > 0, dn = yy < 63;
    int ru = (yy - 1) >> 2, rm = yy >> 2, rd = (yy + 1) >> 2;

    float3 cm = make_float3(0.f, 0.f, 0.f), cc, cp;
    cc.x = up ? xob[(size_t)(ru * 16) * Cn] : 0.f;
    cc.y = xob[(size_t)(rm * 16) * Cn];
    cc.z = dn ? xob[(size_t)(rd * 16) * Cn] : 0.f;

    size_t pix0 = ((size_t)(b * Hn + yy)) * Wn;
    for (int xx = 0; xx < 64; xx++) {
        if (xx < 63) {
            int xc4 = (xx + 1) >> 2;
            cp.x = up ? xob[(size_t)(ru * 16 + xc4) * Cn] : 0.f;
            cp.y = xob[(size_t)(rm * 16 + xc4) * Cn];
            cp.z = dn ? xob[(size_t)(rd * 16 + xc4) * Cn] : 0.f;
        } else {
            cp = make_float3(0.f, 0.f, 0.f);
        }
        float acc = bias
            + w[0] * cm.x + w[1] * cc.x + w[2] * cp.x
            + w[3] * cm.y + w[4] * cc.y + w[5] * cp.y
            + w[6] * cm.z + w[7] * cc.z + w[8] * cp.z;
        size_t pix = pix0 + xx;
        g_z[pix * Cn + c] = 0.5f * acc + 0.5f * g_yo[pix * Cn + c];
        cm = cc; cc = cp;
    }
}

// ---------------- K7: dwconv3x3(dw) on z -> fp16 hi/lo planes (tiled) -----
__global__ __launch_bounds__(384) void dwconv2_kernel(
    const float* __restrict__ dww, const float* __restrict__ dwb)
{
    __shared__ float wsh[Cn * 9];
    int tid = threadIdx.x;
    for (int i = tid; i < Cn * 9; i += 384) wsh[i] = dww[i];
    __syncthreads();

    int b  = blockIdx.x >> 6;
    int yy = blockIdx.x & 63;
    int c  = tid;
    float w[9];
#pragma unroll
    for (int i = 0; i < 9; i++) w[i] = wsh[c * 9 + i];
    float bias = dwb[c];

    const float* zb = g_z + (size_t)b * HWn * Cn + c;
    bool up = yy > 0, dn = yy < 63;
    size_t rowm = (size_t)yy * Wn;

    float3 cm = make_float3(0.f, 0.f, 0.f), cc, cp;
    cc.x = up ? zb[(rowm - Wn) * Cn] : 0.f;
    cc.y = zb[rowm * Cn];
    cc.z = dn ? zb[(rowm + Wn) * Cn] : 0.f;

    int mrow0 = b * HWn + yy * Wn;
    for (int xx = 0; xx < 64; xx++) {
        if (xx < 63) {
            size_t bcol = rowm + xx + 1;
            cp.x = up ? zb[(bcol - Wn) * Cn] : 0.f;
            cp.y = zb[bcol * Cn];
            cp.z = dn ? zb[(bcol + Wn) * Cn] : 0.f;
        } else {
            cp = make_float3(0.f, 0.f, 0.f);
        }
        float acc = bias
            + w[0] * cm.x + w[1] * cc.x + w[2] * cp.x
            + w[3] * cm.y + w[4] * cc.y + w[5] * cp.y
            + w[6] * cm.z + w[7] * cc.z + w[8] * cp.z;
        __half h = __float2half(acc);
        __half l = __float2half(acc - __half2float(h));
        size_t o = a_off(mrow0 + xx, c);
        g_abf[o] = h;
        g_abf[APL + o] = l;
        cm = cc; cc = cp;
    }
}

// ---------------- launch ----------------
extern "C" void kernel_launch(void* const* d_in, const int* in_sizes, int n_in,
                              void* d_out, int out_size)
{
    const float* x     = (const float*)d_in[0];
    const float* qkv_w = (const float*)d_in[1];
    const float* dwx_w = (const float*)d_in[2];
    const float* dwx_b = (const float*)d_in[3];
    const float* dw_w  = (const float*)d_in[4];
    const float* dw_b  = (const float*)d_in[5];
    const float* pw_w  = (const float*)d_in[6];
    const float* pw_b  = (const float*)d_in[7];
    float* out = (float*)d_out;

    cudaFuncSetAttribute(gemm_mma, cudaFuncAttributeMaxDynamicSharedMemorySize,
                         GSMEM);
    cudaFuncSetAttribute(coarse_attn_kernel,
                         cudaFuncAttributeMaxDynamicSharedMemorySize, CA_SMEM);

    // weight conversions (tiny)
    convw_kernel<<<(C3n * Cn + 255) / 256, 256>>>(qkv_w, C3n * Cn, 0);
    convw_kernel<<<(Cn * Cn + 255) / 256, 256>>>(pw_w, Cn * Cn, 1);

    // 1) coarse pooling (writes fp16 tiled planes directly)
    pool_kernel<<<Bn * NCn, Cn>>>(x);

    // 2) coarse QKV: (2048 x 1152 x 384), 3-pass (near-exact)
    gemm_mma<<<dim3(C3n / 128, (Bn * NCn) / 256), 512, GSMEM>>>(
        nullptr, nullptr, C3n, 0, 3);

    // 3) coarse routing attention + top-k
    coarse_attn_kernel<<<Bn * NHd * 2, 128, CA_SMEM>>>();

    // 4) fine QKV: (32768 x 1152 x 384), 2-pass (W fp16)
    convA_kernel<<<(Bn * HWn * 48 + 255) / 256, 256>>>(x, Bn * HWn * 48);
    gemm_mma<<<dim3(C3n / 128, (Bn * HWn) / 256), 512, GSMEM>>>(
        nullptr, nullptr, C3n, 1, 2);

    // 5) fine windowed attention
    fine_attn_kernel<<<Bn * NHd * NCn, 128>>>();

    // 6) upsample+dwconv(dwx)+mix
    dwmix_kernel<<<Bn * Hn, Cn>>>(dwx_w, dwx_b);

    // 7) dwconv(dw) -> fp16 tiled planes directly
    dwconv2_kernel<<<Bn * Hn, Cn>>>(dw_w, dw_b);

    // 8) pointwise projection (+bias): (32768 x 384 x 384), 3-pass
    gemm_mma<<<dim3(Cn / 128, (Bn * HWn) / 256), 512, GSMEM>>>(
        pw_b, out, Cn, 2, 3);
}

// round 14
// speedup vs baseline: 1.5936x; 1.0380x over previous
#include <cuda_runtime.h>
#include <cuda_fp16.h>
#include <float.h>
#include <stdint.h>

// Problem constants
#define Bn   8
#define Hn   64
#define Wn   64
#define Cn   384
#define NHd  8
#define Dh   48
#define NCn  256
#define HWn  4096
#define C3n  1152
#define SCALE 0.14433756729740643f

// ---- tiled operand layout: [tile][kchunk(24)][rows][pitch 24 halves] ----
#define TP     24
#define ACHH   (256 * TP)
#define WCHH   (128 * TP)
#define ATILEH (24 * ACHH)
#define WTILEH (24 * WCHH)
#define APL    ((size_t)128 * ATILEH)

// ---------------- scratch (device globals; no allocation) ----------------
__device__ float  g_qkvc[Bn * NCn * C3n];
__device__ int    g_topk[Bn * NHd * NCn * 4];
__device__ float  g_xo  [Bn * NCn * Cn];
__device__ __half g_qkvh[(size_t)Bn * HWn * C3n];   // fine QKV in fp16
__device__ float  g_yo  [(size_t)Bn * HWn * Cn];
__device__ float  g_z   [(size_t)Bn * HWn * Cn];
__device__ __half g_abf[2 * APL];
__device__ __half g_wqh[9 * WTILEH];
__device__ __half g_wql[9 * WTILEH];
__device__ __half g_wph[3 * WTILEH];
__device__ __half g_wpl[3 * WTILEH];

__device__ __forceinline__ size_t a_off(int m, int k) {
    return (size_t)(m >> 8) * ATILEH + (size_t)(k >> 4) * ACHH
         + (m & 255) * TP + (k & 15);
}
__device__ __forceinline__ size_t w_off(int n, int k) {
    return (size_t)(n >> 7) * WTILEH + (size_t)(k >> 4) * WCHH
         + (n & 127) * TP + (k & 15);
}

// ---------------- helpers ----------------
__device__ __forceinline__ uint32_t smem_u32(const void* p) {
    uint32_t a;
    asm("{ .reg .u64 t; cvta.to.shared.u64 t, %1; cvt.u32.u64 %0, t; }"
        : "=r"(a) : "l"(p));
    return a;
}
__device__ __forceinline__ void ldmx4(uint32_t* r, uint32_t addr) {
    asm volatile("ldmatrix.sync.aligned.m8n8.x4.shared.b16 {%0,%1,%2,%3}, [%4];"
        : "=r"(r[0]), "=r"(r[1]), "=r"(r[2]), "=r"(r[3]) : "r"(addr));
}
__device__ __forceinline__ void mma16816(float* d, const uint32_t* a, const uint32_t* b) {
    asm volatile(
        "mma.sync.aligned.m16n8k16.row.col.f32.f16.f16.f32 "
        "{%0,%1,%2,%3}, {%4,%5,%6,%7}, {%8,%9}, {%0,%1,%2,%3};"
        : "+f"(d[0]), "+f"(d[1]), "+f"(d[2]), "+f"(d[3])
        : "r"(a[0]), "r"(a[1]), "r"(a[2]), "r"(a[3]), "r"(b[0]), "r"(b[1]));
}
__device__ __forceinline__ uint32_t pack_hf2(float x, float y) {
    unsigned short hx = __half_as_ushort(__float2half(x));
    unsigned short hy = __half_as_ushort(__float2half(y));
    return (uint32_t)hx | ((uint32_t)hy << 16);
}
__device__ __forceinline__ void mbar_init(uint32_t a, uint32_t cnt) {
    asm volatile("mbarrier.init.shared.b64 [%0], %1;" :: "r"(a), "r"(cnt) : "memory");
}
__device__ __forceinline__ void mbar_expect(uint32_t a, uint32_t bytes) {
    asm volatile("mbarrier.arrive.expect_tx.shared.b64 _, [%0], %1;"
                 :: "r"(a), "r"(bytes) : "memory");
}
__device__ __forceinline__ void mbar_wait(uint32_t a, uint32_t parity) {
    asm volatile(
        "{\n\t.reg .pred P;\n\t"
        "WL%=:\n\t"
        "mbarrier.try_wait.parity.acquire.cta.shared::cta.b64 P, [%0], %1, 0x989680;\n\t"
        "@P bra.uni WD%=;\n\t"
        "bra.uni WL%=;\n\t"
        "WD%=:\n\t}"
        :: "r"(a), "r"(parity) : "memory");
}
__device__ __forceinline__ void bulkcp(uint32_t sdst, const void* gsrc,
                                       uint32_t bytes, uint32_t mbar) {
    asm volatile(
        "cp.async.bulk.shared::cta.global.mbarrier::complete_tx::bytes "
        "[%0], [%1], %2, [%3];"
        :: "r"(sdst), "l"(gsrc), "r"(bytes), "r"(mbar) : "memory");
}

// ---------------- K1: 4x4 average pool -> fp16 hi/lo planes (tiled) -------
__global__ __launch_bounds__(384) void pool_kernel(const float* __restrict__ x)
{
    int blk = blockIdx.x;
    int n = blk & 255, b = blk >> 8;
    int hc = n >> 4, wc = n & 15;
    int c = threadIdx.x;
    float s = 0.f;
#pragma unroll
    for (int i = 0; i < 4; i++)
#pragma unroll
        for (int j = 0; j < 4; j++)
            s += x[(((size_t)(b * Hn + hc * 4 + i)) * Wn + wc * 4 + j) * Cn + c];
    s *= 0.0625f;
    __half h = __float2half(s);
    __half l = __float2half(s - __half2float(h));
    size_t o = a_off(b * NCn + n, c);
    g_abf[o] = h;
    g_abf[APL + o] = l;
}

// ---------------- weight fp16 hi/lo conversion (tiled) ----------------
__global__ __launch_bounds__(256) void convw_kernel(
    const float* __restrict__ w, int total, int mode)
{
    int i = blockIdx.x * 256 + threadIdx.x;
    if (i >= total) return;
    float v = w[i];
    __half h = __float2half(v);
    __half l = __float2half(v - __half2float(h));
    int n = i / 384, k = i % 384;
    size_t o = w_off(n, k);
    if (mode == 0) { g_wqh[o] = h; g_wql[o] = l; }
    else           { g_wph[o] = h; g_wpl[o] = l; }
}

// ---------------- A conversion: x (f32) -> fp16 hi/lo planes (tiled) ------
__global__ __launch_bounds__(256) void convA_kernel(
    const float* __restrict__ src, int n8)
{
    int i = blockIdx.x * 256 + threadIdx.x;
    if (i >= n8) return;
    float4 v0 = ((const float4*)src)[i * 2];
    float4 v1 = ((const float4*)src)[i * 2 + 1];
    uint4 H, L;
    H.x = pack_hf2(v0.x, v0.y); H.y = pack_hf2(v0.z, v0.w);
    H.z = pack_hf2(v1.x, v1.y); H.w = pack_hf2(v1.z, v1.w);
    float h0 = __half2float(__float2half(v0.x));
    float h1 = __half2float(__float2half(v0.y));
    float h2 = __half2float(__float2half(v0.z));
    float h3 = __half2float(__float2half(v0.w));
    float h4 = __half2float(__float2half(v1.x));
    float h5 = __half2float(__float2half(v1.y));
    float h6 = __half2float(__float2half(v1.z));
    float h7 = __half2float(__float2half(v1.w));
    L.x = pack_hf2(v0.x - h0, v0.y - h1);
    L.y = pack_hf2(v0.z - h2, v0.w - h3);
    L.z = pack_hf2(v1.x - h4, v1.y - h5);
    L.w = pack_hf2(v1.z - h6, v1.w - h7);
    int m = i / 48, k0 = (i % 48) * 8;
    size_t o = a_off(m, k0);
    *(uint4*)(g_abf + o)       = H;
    *(uint4*)(g_abf + APL + o) = L;
}

// ---------------- tensor-core GEMM: O[M,N] = A[M,384] * W[N,384]^T --------
// passes==3: acc = Ah*Wh + Al*Wh + Ah*Wl   passes==2: acc = A*Wh
// mode 0: O=g_qkvc (f32)  mode 1: O=g_qkvh (f16)  mode 2: O=out (+bias)
// cp.async.bulk, 3-stage mbarrier pipeline, BK=32 pairs, 256x128 tile.
#define AH_S 0
#define AL_S 24576
#define WH_S 49152
#define WL_S 61440
#define STG  73728
#define GSMEM (3 * STG + 64)

__global__ __launch_bounds__(512, 1) void gemm_mma(
    const float* __restrict__ bias, float* __restrict__ Oext, int N, int mode,
    int passes)
{
    extern __shared__ __half sm[];

    const __half* WHp = (mode == 2) ? g_wph : g_wqh;
    const __half* WLp = (mode == 2) ? g_wpl : g_wql;

    int tid = threadIdx.x;
    int m0 = blockIdx.y * 256, n0 = blockIdx.x * 128;

    const __half* aH = g_abf + (size_t)(m0 >> 8) * ATILEH;
    const __half* aL = aH + APL;
    const __half* wH = WHp + (size_t)(n0 >> 7) * WTILEH;
    const __half* wL = WLp + (size_t)(n0 >> 7) * WTILEH;

    uint32_t sbase = smem_u32(sm);
    uint32_t mb = sbase + 3 * STG;

    uint32_t stgbytes = (passes == 3) ? STG : (STG - 12288);

    if (tid == 0) {
#pragma unroll
        for (int s = 0; s < 3; s++) mbar_init(mb + s * 8, 1);
    }
    __syncthreads();

    if (tid == 0) {
#pragma unroll
        for (int s = 0; s < 2; s++) {
            uint32_t sb = sbase + s * STG;
            uint32_t mbs = mb + s * 8;
            mbar_expect(mbs, stgbytes);
            bulkcp(sb + AH_S, aH + s * 2 * ACHH, 24576, mbs);
            bulkcp(sb + AL_S, aL + s * 2 * ACHH, 24576, mbs);
            bulkcp(sb + WH_S, wH + s * 2 * WCHH, 12288, mbs);
            if (passes == 3)
                bulkcp(sb + WL_S, wL + s * 2 * WCHH, 12288, mbs);
        }
    }

    int lane = tid & 31;
    int wid = tid >> 5;
    int mbase = (wid & 3) * 64;
    int nbase = (wid >> 2) * 32;

    int ar = lane & 15, ak = (lane >> 4) * 8;
    uint32_t offA0 = ((mbase + ar) * TP + ak) * 2;
    int br = (lane & 7) + ((lane >> 4) << 3), bk = ((lane >> 3) & 1) * 8;
    uint32_t offB0 = ((nbase + br) * TP + bk) * 2;

    float acc[4][4][4];
#pragma unroll
    for (int i = 0; i < 4; i++)
#pragma unroll
        for (int j = 0; j < 4; j++)
#pragma unroll
            for (int k = 0; k < 4; k++) acc[i][j][k] = 0.f;

    int stg = 0, par = 0;
    for (int pc = 0; pc < 12; pc++) {
        mbar_wait(mb + stg * 8, par);
        uint32_t bb = sbase + stg * STG;

        uint32_t ah[4][4], al[4][4], bf[2][4];
#pragma unroll
        for (int g = 0; g < 4; g++)
            ldmx4(ah[g], bb + AH_S + offA0 + g * 768);
#pragma unroll
        for (int g = 0; g < 4; g++)
            ldmx4(al[g], bb + AL_S + offA0 + g * 768);
#pragma unroll
        for (int g = 0; g < 2; g++)
            ldmx4(bf[g], bb + WH_S + offB0 + g * 768);

        __syncthreads();

        if (tid == 0 && pc < 10) {
            int s = (pc + 2) % 3;
            uint32_t sb = sbase + s * STG;
            uint32_t mbs = mb + s * 8;
            int ck = pc + 2;
            mbar_expect(mbs, stgbytes);
            bulkcp(sb + AH_S, aH + ck * 2 * ACHH, 24576, mbs);
            bulkcp(sb + AL_S, aL + ck * 2 * ACHH, 24576, mbs);
            bulkcp(sb + WH_S, wH + ck * 2 * WCHH, 12288, mbs);
            if (passes == 3)
                bulkcp(sb + WL_S, wL + ck * 2 * WCHH, 12288, mbs);
        }

        // ---- sub 0 math ----
#pragma unroll
        for (int mi = 0; mi < 4; mi++)
#pragma unroll
            for (int g = 0; g < 2; g++)
#pragma unroll
                for (int sub = 0; sub < 2; sub++)
                    mma16816(acc[mi][g * 2 + sub], ah[mi], &bf[g][sub * 2]);
#pragma unroll
        for (int mi = 0; mi < 4; mi++)
#pragma unroll
            for (int g = 0; g < 2; g++)
#pragma unroll
                for (int sub = 0; sub < 2; sub++)
                    mma16816(acc[mi][g * 2 + sub], al[mi], &bf[g][sub * 2]);
        if (passes == 3) {
#pragma unroll
            for (int g = 0; g < 2; g++)
                ldmx4(bf[g], bb + WL_S + offB0 + g * 768);
#pragma unroll
            for (int mi = 0; mi < 4; mi++)
#pragma unroll
                for (int g = 0; g < 2; g++)
#pragma unroll
                    for (int sub = 0; sub < 2; sub++)
                        mma16816(acc[mi][g * 2 + sub], ah[mi], &bf[g][sub * 2]);
        }

        // ---- sub 1 ----
#pragma unroll
        for (int g = 0; g < 4; g++)
            ldmx4(ah[g], bb + AH_S + 12288 + offA0 + g * 768);
#pragma unroll
        for (int g = 0; g < 4; g++)
            ldmx4(al[g], bb + AL_S + 12288 + offA0 + g * 768);
#pragma unroll
        for (int g = 0; g < 2; g++)
            ldmx4(bf[g], bb + WH_S + 6144 + offB0 + g * 768);
#pragma unroll
        for (int mi = 0; mi < 4; mi++)
#pragma unroll
            for (int g = 0; g < 2; g++)
#pragma unroll
                for (int sub = 0; sub < 2; sub++)
                    mma16816(acc[mi][g * 2 + sub], ah[mi], &bf[g][sub * 2]);
#pragma unroll
        for (int mi = 0; mi < 4; mi++)
#pragma unroll
            for (int g = 0; g < 2; g++)
#pragma unroll
                for (int sub = 0; sub < 2; sub++)
                    mma16816(acc[mi][g * 2 + sub], al[mi], &bf[g][sub * 2]);
        if (passes == 3) {
#pragma unroll
            for (int g = 0; g < 2; g++)
                ldmx4(bf[g], bb + WL_S + 6144 + offB0 + g * 768);
#pragma unroll
            for (int mi = 0; mi < 4; mi++)
#pragma unroll
                for (int g = 0; g < 2; g++)
#pragma unroll
                    for (int sub = 0; sub < 2; sub++)
                        mma16816(acc[mi][g * 2 + sub], ah[mi], &bf[g][sub * 2]);
        }

        if (++stg == 3) { stg = 0; par ^= 1; }
    }

    // epilogue
    int rbase = m0 + mbase, cbase = n0 + nbase;
#pragma unroll
    for (int mi = 0; mi < 4; mi++)
#pragma unroll
        for (int ni = 0; ni < 4; ni++) {
            int rrow = rbase + mi * 16 + (lane >> 2);
            int col = cbase + ni * 8 + (lane & 3) * 2;
            if (mode == 1) {
                __half2* o0 = (__half2*)(g_qkvh + (size_t)rrow * N + col);
                __half2* o1 = (__half2*)(g_qkvh + (size_t)(rrow + 8) * N + col);
                *o0 = __floats2half2_rn(acc[mi][ni][0], acc[mi][ni][1]);
                *o1 = __floats2half2_rn(acc[mi][ni][2], acc[mi][ni][3]);
            } else {
                float b0 = 0.f, b1 = 0.f;
                if (mode == 2) { b0 = bias[col]; b1 = bias[col + 1]; }
                float* O = (mode == 0) ? g_qkvc : Oext;
                float2 v0 = make_float2(acc[mi][ni][0] + b0, acc[mi][ni][1] + b1);
                float2 v1 = make_float2(acc[mi][ni][2] + b0, acc[mi][ni][3] + b1);
                *(float2*)&O[(size_t)rrow * N + col] = v0;
                *(float2*)&O[(size_t)(rrow + 8) * N + col] = v1;
            }
        }
}

// ---------------- K3: coarse routing attention + top-k (flash-style) ------
#define CA_SMEM (2 * 256 * 48 * 4)
__global__ __launch_bounds__(128) void coarse_attn_kernel()
{
    extern __shared__ float cas[];
    float* Ks = cas;
    float* Vs = cas + 256 * 48;

    int bid = blockIdx.x;
    int half = bid & 1;
    int hd = (bid >> 1) & 7;
    int b = bid >> 4;
    int tid = threadIdx.x;

    const float* base = g_qkvc + (size_t)b * NCn * C3n;

    for (int idx = tid; idx < 3072; idx += 128) {
        int j = idx / 12, d4 = (idx % 12) * 4;
        const float* rp = base + (size_t)j * C3n + Cn + hd * Dh + d4;
        *(float4*)&Ks[j * 48 + d4] = *(const float4*)rp;
        *(float4*)&Vs[j * 48 + d4] = *(const float4*)(rp + Cn);
    }

    int q = half * 128 + tid;
    float qv[48];
    const float* qp = base + (size_t)q * C3n + hd * Dh;
#pragma unroll
    for (int i = 0; i < 12; i++) {
        float4 v = *(const float4*)(qp + i * 4);
        qv[i * 4 + 0] = v.x; qv[i * 4 + 1] = v.y;
        qv[i * 4 + 2] = v.z; qv[i * 4 + 3] = v.w;
    }
    __syncthreads();

    float v0 = -FLT_MAX, v1 = -FLT_MAX, v2 = -FLT_MAX, v3 = -FLT_MAX;
    int i0 = 0, i1 = 0, i2 = 0, i3 = 0;
    for (int j = 0; j < 256; j++) {
        float a0 = 0.f, a1 = 0.f, a2 = 0.f, a3 = 0.f;
        const float* kp = &Ks[j * 48];
#pragma unroll
        for (int d4 = 0; d4 < 12; d4++) {
            float4 kv = *(const float4*)(kp + d4 * 4);
            a0 += qv[d4 * 4 + 0] * kv.x;
            a1 += qv[d4 * 4 + 1] * kv.y;
            a2 += qv[d4 * 4 + 2] * kv.z;
            a3 += qv[d4 * 4 + 3] * kv.w;
        }
        float s = (a0 + a1) + (a2 + a3);
        if (s > v3) {
            if (s > v0)      { v3 = v2; i3 = i2; v2 = v1; i2 = i1; v1 = v0; i1 = i0; v0 = s; i0 = j; }
            else if (s > v1) { v3 = v2; i3 = i2; v2 = v1; i2 = i1; v1 = s; i1 = j; }
            else if (s > v2) { v3 = v2; i3 = i2; v2 = s; i2 = j; }
            else             { v3 = s; i3 = j; }
        }
    }
    int obase = ((b * 8 + hd) * 256 + q) * 4;
    g_topk[obase + 0] = i0; g_topk[obase + 1] = i1;
    g_topk[obase + 2] = i2; g_topk[obase + 3] = i3;

    float mx = v0 * SCALE;

    float oacc[48];
#pragma unroll
    for (int d = 0; d < 48; d++) oacc[d] = 0.f;
    float psum = 0.f;
    for (int j = 0; j < 256; j++) {
        float a0 = 0.f, a1 = 0.f, a2 = 0.f, a3 = 0.f;
        const float* kp = &Ks[j * 48];
#pragma unroll
        for (int d4 = 0; d4 < 12; d4++) {
            float4 kv = *(const float4*)(kp + d4 * 4);
            a0 += qv[d4 * 4 + 0] * kv.x;
            a1 += qv[d4 * 4 + 1] * kv.y;
            a2 += qv[d4 * 4 + 2] * kv.z;
            a3 += qv[d4 * 4 + 3] * kv.w;
        }
        float p = __expf(((a0 + a1) + (a2 + a3)) * SCALE - mx);
        psum += p;
        const float* vp = &Vs[j * 48];
#pragma unroll
        for (int d4 = 0; d4 < 12; d4++) {
            float4 vv = *(const float4*)(vp + d4 * 4);
            oacc[d4 * 4 + 0] += p * vv.x;
            oacc[d4 * 4 + 1] += p * vv.y;
            oacc[d4 * 4 + 2] += p * vv.z;
            oacc[d4 * 4 + 3] += p * vv.w;
        }
    }
    float inv = 1.f / psum;
    float* op = &g_xo[((size_t)(b * NCn + q)) * Cn + hd * Dh];
#pragma unroll
    for (int i = 0; i < 12; i++) {
        float4 v = make_float4(oacc[i * 4] * inv, oacc[i * 4 + 1] * inv,
                               oacc[i * 4 + 2] * inv, oacc[i * 4 + 3] * inv);
        *(float4*)(op + i * 4) = v;
    }
}

// ---------------- K5: fine windowed attention (fp16 inputs) ---------------
#define QT_P 18
#define KT_P 68
#define VS_P 52
#define A2_P 68
__global__ __launch_bounds__(128) void fine_attn_kernel()
{
    int bid = blockIdx.x;
    int n  = bid & 255;
    int hd = (bid >> 8) & 7;
    int b  = bid >> 11;

    __shared__ float Qt[48 * QT_P];
    __shared__ float Kt[48 * KT_P];
    __shared__ float Vs[64 * VS_P];
    __shared__ float A2[16 * A2_P];
    __shared__ int   wins[4];

    int tid = threadIdx.x;
    int hc = n >> 4, wc = n & 15;
    const __half* base = g_qkvh + (size_t)b * HWn * C3n;

    if (tid < 4) wins[tid] = g_topk[(size_t)bid * 4 + tid];

    for (int idx = tid; idx < 16 * 12; idx += 128) {
        int p = idx / 12, d4 = (idx % 12) * 4;
        int s = (hc * 4 + (p >> 2)) * Wn + wc * 4 + (p & 3);
        uint2 r = *(const uint2*)&base[(size_t)s * C3n + hd * Dh + d4];
        float2 f0 = __half22float2(*(__half2*)&r.x);
        float2 f1 = __half22float2(*(__half2*)&r.y);
        Qt[(d4 + 0) * QT_P + p] = f0.x;
        Qt[(d4 + 1) * QT_P + p] = f0.y;
        Qt[(d4 + 2) * QT_P + p] = f1.x;
        Qt[(d4 + 3) * QT_P + p] = f1.y;
    }
    __syncthreads();

    for (int idx = tid; idx < 64 * 12; idx += 128) {
        int p = idx / 12, d4 = (idx % 12) * 4;
        int t = p >> 4, pl = p & 15;
        int m = wins[t];
        int s = ((m >> 4) * 4 + (pl >> 2)) * Wn + (m & 15) * 4 + (pl & 3);
        const __half* rw = &base[(size_t)s * C3n + hd * Dh + d4];
        uint2 rk = *(const uint2*)(rw + Cn);
        uint2 rv = *(const uint2*)(rw + 2 * Cn);
        float2 k0 = __half22float2(*(__half2*)&rk.x);
        float2 k1 = __half22float2(*(__half2*)&rk.y);
        float2 w0 = __half22float2(*(__half2*)&rv.x);
        float2 w1 = __half22float2(*(__half2*)&rv.y);
        Kt[(d4 + 0) * KT_P + p] = k0.x;
        Kt[(d4 + 1) * KT_P + p] = k0.y;
        Kt[(d4 + 2) * KT_P + p] = k1.x;
        Kt[(d4 + 3) * KT_P + p] = k1.y;
        float4 vv = make_float4(w0.x, w0.y, w1.x, w1.y);
        *(float4*)&Vs[p * VS_P + d4] = vv;
    }
    __syncthreads();

    {
        int tr = tid >> 4, tc = tid & 15;
        int r0 = tr * 2, c0 = tc * 4;
        float a0[4] = {0.f, 0.f, 0.f, 0.f};
        float a1[4] = {0.f, 0.f, 0.f, 0.f};
#pragma unroll 8
        for (int dd = 0; dd < Dh; dd++) {
            float2 qv = *(const float2*)&Qt[dd * QT_P + r0];
            float4 kv = *(const float4*)&Kt[dd * KT_P + c0];
            a0[0] += qv.x * kv.x; a0[1] += qv.x * kv.y;
            a0[2] += qv.x * kv.z; a0[3] += qv.x * kv.w;
            a1[0] += qv.y * kv.x; a1[1] += qv.y * kv.y;
            a1[2] += qv.y * kv.z; a1[3] += qv.y * kv.w;
        }
        float4 w0 = make_float4(a0[0] * SCALE, a0[1] * SCALE, a0[2] * SCALE, a0[3] * SCALE);
        float4 w1 = make_float4(a1[0] * SCALE, a1[1] * SCALE, a1[2] * SCALE, a1[3] * SCALE);
        *(float4*)&A2[r0 * A2_P + c0] = w0;
        *(float4*)&A2[(r0 + 1) * A2_P + c0] = w1;
    }
    __syncthreads();

    {
        int row = tid >> 3, j = tid & 7;
        float* ap = &A2[row * A2_P + j * 8];
        float v[8];
        float mx = -FLT_MAX;
#pragma unroll
        for (int i = 0; i < 8; i++) { v[i] = ap[i]; mx = fmaxf(mx, v[i]); }
#pragma unroll
        for (int m = 1; m < 8; m <<= 1)
            mx = fmaxf(mx, __shfl_xor_sync(0xffffffffu, mx, m));
        float sum = 0.f;
#pragma unroll
        for (int i = 0; i < 8; i++) { v[i] = __expf(v[i] - mx); sum += v[i]; }
#pragma unroll
        for (int m = 1; m < 8; m <<= 1)
            sum += __shfl_xor_sync(0xffffffffu, sum, m);
        float inv = 1.f / sum;
#pragma unroll
        for (int i = 0; i < 8; i++) ap[i] = v[i] * inv;
    }
    __syncthreads();

    {
        int tr2 = tid >> 4, tc2 = tid & 15;
        int p0 = tr2 * 2, dd0 = tc2 * 3;
        float o0[3] = {0.f, 0.f, 0.f};
        float o1[3] = {0.f, 0.f, 0.f};
#pragma unroll 8
        for (int kk = 0; kk < 64; kk++) {
            float av0 = A2[p0 * A2_P + kk];
            float av1 = A2[(p0 + 1) * A2_P + kk];
            const float* vp = &Vs[kk * VS_P + dd0];
            float v0 = vp[0], v1 = vp[1], v2 = vp[2];
            o0[0] += av0 * v0; o0[1] += av0 * v1; o0[2] += av0 * v2;
            o1[0] += av1 * v0; o1[1] += av1 * v1; o1[2] += av1 * v2;
        }
#pragma unroll
        for (int pi = 0; pi < 2; pi++) {
            int p = p0 + pi;
            int yy = hc * 4 + (p >> 2), xx = wc * 4 + (p & 3);
            float* op = &g_yo[(((size_t)(b * Hn + yy)) * Wn + xx) * Cn + hd * Dh + dd0];
            if (pi == 0) { op[0] = o0[0]; op[1] = o0[1]; op[2] = o0[2]; }
            else         { op[0] = o1[0]; op[1] = o1[1]; op[2] = o1[2]; }
        }
    }
}

// ---------------- K6: upsample(xo) -> dwconv3x3(dwx) -> mix with yo -------
__global__ __launch_bounds__(384) void dwmix_kernel(
    const float* __restrict__ dwxw, const float* __restrict__ dwxb)
{
    __shared__ float wsh[Cn * 9];
    int tid = threadIdx.x;
    for (int i = tid; i < Cn * 9; i += 384) wsh[i] = dwxw[i];
    __syncthreads();

    int b  = blockIdx.x >> 6;
    int yy = blockIdx.x & 63;
    int c  = tid;
    float w[9];
#pragma unroll
    for (int i = 0; i < 9; i++) w[i] = wsh[c * 9 + i];
    float bias = dwxb[c];

    const float* xob = g_xo + (size_t)b * NCn * Cn + c;
    bool up = yy > 0, dn = yy < 63;
    int ru = (yy - 1) >> 2, rm = yy >> 2, rd = (yy + 1) >> 2;

    float3 cm = make_float3(0.f, 0.f, 0.f), cc, cp;
    cc.x = up ? xob[(size_t)(ru * 16) * Cn] : 0.f;
    cc.y = xob[(size_t)(rm * 16) * Cn];
    cc.z = dn ? xob[(size_t)(rd * 16) * Cn] : 0.f;

    size_t pix0 = ((size_t)(b * Hn + yy)) * Wn;
    for (int xx = 0; xx < 64; xx++) {
        if (xx < 63) {
            int xc4 = (xx + 1) >> 2;
            cp.x = up ? xob[(size_t)(ru * 16 + xc4) * Cn] : 0.f;
            cp.y = xob[(size_t)(rm * 16 + xc4) * Cn];
            cp.z = dn ? xob[(size_t)(rd * 16 + xc4) * Cn] : 0.f;
        } else {
            cp = make_float3(0.f, 0.f, 0.f);
        }
        float acc = bias
            + w[0] * cm.x + w[1] * cc.x + w[2] * cp.x
            + w[3] * cm.y + w[4] * cc.y + w[5] * cp.y
            + w[6] * cm.z + w[7] * cc.z + w[8] * cp.z;
        size_t pix = pix0 + xx;
        g_z[pix * Cn + c] = 0.5f * acc + 0.5f * g_yo[pix * Cn + c];
        cm = cc; cc = cp;
    }
}

// ---------------- K7: dwconv3x3(dw) on z -> fp16 hi/lo planes (tiled) -----
__global__ __launch_bounds__(384) void dwconv2_kernel(
    const float* __restrict__ dww, const float* __restrict__ dwb)
{
    __shared__ float wsh[Cn * 9];
    int tid = threadIdx.x;
    for (int i = tid; i < Cn * 9; i += 384) wsh[i] = dww[i];
    __syncthreads();

    int b  = blockIdx.x >> 6;
    int yy = blockIdx.x & 63;
    int c  = tid;
    float w[9];
#pragma unroll
    for (int i = 0; i < 9; i++) w[i] = wsh[c * 9 + i];
    float bias = dwb[c];

    const float* zb = g_z + (size_t)b * HWn * Cn + c;
    bool up = yy > 0, dn = yy < 63;
    size_t rowm = (size_t)yy * Wn;

    float3 cm = make_float3(0.f, 0.f, 0.f), cc, cp;
    cc.x = up ? zb[(rowm - Wn) * Cn] : 0.f;
    cc.y = zb[rowm * Cn];
    cc.z = dn ? zb[(rowm + Wn) * Cn] : 0.f;

    int mrow0 = b * HWn + yy * Wn;
    for (int xx = 0; xx < 64; xx++) {
        if (xx < 63) {
            size_t bcol = rowm + xx + 1;
            cp.x = up ? zb[(bcol - Wn) * Cn] : 0.f;
            cp.y = zb[bcol * Cn];
            cp.z = dn ? zb[(bcol + Wn) * Cn] : 0.f;
        } else {
            cp = make_float3(0.f, 0.f, 0.f);
        }
        float acc = bias
            + w[0] * cm.x + w[1] * cc.x + w[2] * cp.x
            + w[3] * cm.y + w[4] * cc.y + w[5] * cp.y
            + w[6] * cm.z + w[7] * cc.z + w[8] * cp.z;
        __half h = __float2half(acc);
        __half l = __float2half(acc - __half2float(h));
        size_t o = a_off(mrow0 + xx, c);
        g_abf[o] = h;
        g_abf[APL + o] = l;
        cm = cc; cc = cp;
    }
}

// ---------------- launch ----------------
extern "C" void kernel_launch(void* const* d_in, const int* in_sizes, int n_in,
                              void* d_out, int out_size)
{
    const float* x     = (const float*)d_in[0];
    const float* qkv_w = (const float*)d_in[1];
    const float* dwx_w = (const float*)d_in[2];
    const float* dwx_b = (const float*)d_in[3];
    const float* dw_w  = (const float*)d_in[4];
    const float* dw_b  = (const float*)d_in[5];
    const float* pw_w  = (const float*)d_in[6];
    const float* pw_b  = (const float*)d_in[7];
    float* out = (float*)d_out;

    cudaFuncSetAttribute(gemm_mma, cudaFuncAttributeMaxDynamicSharedMemorySize,
                         GSMEM);
    cudaFuncSetAttribute(coarse_attn_kernel,
                         cudaFuncAttributeMaxDynamicSharedMemorySize, CA_SMEM);

    // weight conversions (tiny)
    convw_kernel<<<(C3n * Cn + 255) / 256, 256>>>(qkv_w, C3n * Cn, 0);
    convw_kernel<<<(Cn * Cn + 255) / 256, 256>>>(pw_w, Cn * Cn, 1);

    // 1) coarse pooling (writes fp16 tiled planes directly)
    pool_kernel<<<Bn * NCn, Cn>>>(x);

    // 2) coarse QKV: (2048 x 1152 x 384), 3-pass (exact top-k)
    gemm_mma<<<dim3(C3n / 128, (Bn * NCn) / 256), 512, GSMEM>>>(
        nullptr, nullptr, C3n, 0, 3);

    // 3) coarse routing attention + top-k
    coarse_attn_kernel<<<Bn * NHd * 2, 128, CA_SMEM>>>();

    // 4) fine QKV: (32768 x 1152 x 384), 2-pass, fp16 output
    convA_kernel<<<(Bn * HWn * 48 + 255) / 256, 256>>>(x, Bn * HWn * 48);
    gemm_mma<<<dim3(C3n / 128, (Bn * HWn) / 256), 512, GSMEM>>>(
        nullptr, nullptr, C3n, 1, 2);

    // 5) fine windowed attention (fp16 inputs)
    fine_attn_kernel<<<Bn * NHd * NCn, 128>>>();

    // 6) upsample+dwconv(dwx)+mix
    dwmix_kernel<<<Bn * Hn, Cn>>>(dwx_w, dwx_b);

    // 7) dwconv(dw) -> fp16 tiled planes directly
    dwconv2_kernel<<<Bn * Hn, Cn>>>(dw_w, dw_b);

    // 8) pointwise projection (+bias): (32768 x 384 x 384), 2-pass
    gemm_mma<<<dim3(Cn / 128, (Bn * HWn) / 256), 512, GSMEM>>>(
        pw_b, out, Cn, 2, 2);
}

// round 15
// speedup vs baseline: 1.6489x; 1.0347x over previous
#include <cuda_runtime.h>
#include <cuda_fp16.h>
#include <float.h>
#include <stdint.h>

// Problem constants
#define Bn   8
#define Hn   64
#define Wn   64
#define Cn   384
#define NHd  8
#define Dh   48
#define NCn  256
#define HWn  4096
#define C3n  1152
#define SCALE 0.14433756729740643f

// ---- tiled operand layout: [tile][kchunk(24)][rows][pitch 24 halves] ----
#define TP     24
#define ACHH   (256 * TP)
#define WCHH   (128 * TP)
#define ATILEH (24 * ACHH)
#define WTILEH (24 * WCHH)
#define APL    ((size_t)128 * ATILEH)

// ---------------- scratch (device globals; no allocation) ----------------
__device__ float  g_qkvc[Bn * NCn * C3n];
__device__ int    g_topk[Bn * NHd * NCn * 4];
__device__ float  g_xo  [Bn * NCn * Cn];
__device__ __half g_qkvh[(size_t)Bn * HWn * C3n];   // fine QKV (fp16)
__device__ __half g_yo  [(size_t)Bn * HWn * Cn];    // fine attn out (fp16)
__device__ __half g_z   [(size_t)Bn * HWn * Cn];    // mixed (fp16)
__device__ __half g_abf[2 * APL];
__device__ __half g_wqh[9 * WTILEH];
__device__ __half g_wql[9 * WTILEH];
__device__ __half g_wph[3 * WTILEH];
__device__ __half g_wpl[3 * WTILEH];

__device__ __forceinline__ size_t a_off(int m, int k) {
    return (size_t)(m >> 8) * ATILEH + (size_t)(k >> 4) * ACHH
         + (m & 255) * TP + (k & 15);
}
__device__ __forceinline__ size_t w_off(int n, int k) {
    return (size_t)(n >> 7) * WTILEH + (size_t)(k >> 4) * WCHH
         + (n & 127) * TP + (k & 15);
}

// ---------------- helpers ----------------
__device__ __forceinline__ uint32_t smem_u32(const void* p) {
    uint32_t a;
    asm("{ .reg .u64 t; cvta.to.shared.u64 t, %1; cvt.u32.u64 %0, t; }"
        : "=r"(a) : "l"(p));
    return a;
}
__device__ __forceinline__ void ldmx4(uint32_t* r, uint32_t addr) {
    asm volatile("ldmatrix.sync.aligned.m8n8.x4.shared.b16 {%0,%1,%2,%3}, [%4];"
        : "=r"(r[0]), "=r"(r[1]), "=r"(r[2]), "=r"(r[3]) : "r"(addr));
}
__device__ __forceinline__ void mma16816(float* d, const uint32_t* a, const uint32_t* b) {
    asm volatile(
        "mma.sync.aligned.m16n8k16.row.col.f32.f16.f16.f32 "
        "{%0,%1,%2,%3}, {%4,%5,%6,%7}, {%8,%9}, {%0,%1,%2,%3};"
        : "+f"(d[0]), "+f"(d[1]), "+f"(d[2]), "+f"(d[3])
        : "r"(a[0]), "r"(a[1]), "r"(a[2]), "r"(a[3]), "r"(b[0]), "r"(b[1]));
}
__device__ __forceinline__ uint32_t pack_hf2(float x, float y) {
    unsigned short hx = __half_as_ushort(__float2half(x));
    unsigned short hy = __half_as_ushort(__float2half(y));
    return (uint32_t)hx | ((uint32_t)hy << 16);
}
__device__ __forceinline__ void mbar_init(uint32_t a, uint32_t cnt) {
    asm volatile("mbarrier.init.shared.b64 [%0], %1;" :: "r"(a), "r"(cnt) : "memory");
}
__device__ __forceinline__ void mbar_expect(uint32_t a, uint32_t bytes) {
    asm volatile("mbarrier.arrive.expect_tx.shared.b64 _, [%0], %1;"
                 :: "r"(a), "r"(bytes) : "memory");
}
__device__ __forceinline__ void mbar_wait(uint32_t a, uint32_t parity) {
    asm volatile(
        "{\n\t.reg .pred P;\n\t"
        "WL%=:\n\t"
        "mbarrier.try_wait.parity.acquire.cta.shared::cta.b64 P, [%0], %1, 0x989680;\n\t"
        "@P bra.uni WD%=;\n\t"
        "bra.uni WL%=;\n\t"
        "WD%=:\n\t}"
        :: "r"(a), "r"(parity) : "memory");
}
__device__ __forceinline__ void bulkcp(uint32_t sdst, const void* gsrc,
                                       uint32_t bytes, uint32_t mbar) {
    asm volatile(
        "cp.async.bulk.shared::cta.global.mbarrier::complete_tx::bytes "
        "[%0], [%1], %2, [%3];"
        :: "r"(sdst), "l"(gsrc), "r"(bytes), "r"(mbar) : "memory");
}

// ---------------- K1: 4x4 average pool -> fp16 hi/lo planes (tiled) -------
__global__ __launch_bounds__(384) void pool_kernel(const float* __restrict__ x)
{
    int blk = blockIdx.x;
    int n = blk & 255, b = blk >> 8;
    int hc = n >> 4, wc = n & 15;
    int c = threadIdx.x;
    float s = 0.f;
#pragma unroll
    for (int i = 0; i < 4; i++)
#pragma unroll
        for (int j = 0; j < 4; j++)
            s += x[(((size_t)(b * Hn + hc * 4 + i)) * Wn + wc * 4 + j) * Cn + c];
    s *= 0.0625f;
    __half h = __float2half(s);
    __half l = __float2half(s - __half2float(h));
    size_t o = a_off(b * NCn + n, c);
    g_abf[o] = h;
    g_abf[APL + o] = l;
}

// ---------------- weight fp16 hi/lo conversion (tiled) ----------------
__global__ __launch_bounds__(256) void convw_kernel(
    const float* __restrict__ w, int total, int mode)
{
    int i = blockIdx.x * 256 + threadIdx.x;
    if (i >= total) return;
    float v = w[i];
    __half h = __float2half(v);
    __half l = __float2half(v - __half2float(h));
    int n = i / 384, k = i % 384;
    size_t o = w_off(n, k);
    if (mode == 0) { g_wqh[o] = h; g_wql[o] = l; }
    else           { g_wph[o] = h; g_wpl[o] = l; }
}

// ---------------- A conversion: x (f32) -> fp16 hi/lo planes (tiled) ------
__global__ __launch_bounds__(256) void convA_kernel(
    const float* __restrict__ src, int n8)
{
    int i = blockIdx.x * 256 + threadIdx.x;
    if (i >= n8) return;
    float4 v0 = ((const float4*)src)[i * 2];
    float4 v1 = ((const float4*)src)[i * 2 + 1];
    uint4 H, L;
    H.x = pack_hf2(v0.x, v0.y); H.y = pack_hf2(v0.z, v0.w);
    H.z = pack_hf2(v1.x, v1.y); H.w = pack_hf2(v1.z, v1.w);
    float h0 = __half2float(__float2half(v0.x));
    float h1 = __half2float(__float2half(v0.y));
    float h2 = __half2float(__float2half(v0.z));
    float h3 = __half2float(__float2half(v0.w));
    float h4 = __half2float(__float2half(v1.x));
    float h5 = __half2float(__float2half(v1.y));
    float h6 = __half2float(__float2half(v1.z));
    float h7 = __half2float(__float2half(v1.w));
    L.x = pack_hf2(v0.x - h0, v0.y - h1);
    L.y = pack_hf2(v0.z - h2, v0.w - h3);
    L.z = pack_hf2(v1.x - h4, v1.y - h5);
    L.w = pack_hf2(v1.z - h6, v1.w - h7);
    int m = i / 48, k0 = (i % 48) * 8;
    size_t o = a_off(m, k0);
    *(uint4*)(g_abf + o)       = H;
    *(uint4*)(g_abf + APL + o) = L;
}

// ---------------- tensor-core GEMM (unchanged from R14) -------------------
#define AH_S 0
#define AL_S 24576
#define WH_S 49152
#define WL_S 61440
#define STG  73728
#define GSMEM (3 * STG + 64)

__global__ __launch_bounds__(512, 1) void gemm_mma(
    const float* __restrict__ bias, float* __restrict__ Oext, int N, int mode,
    int passes)
{
    extern __shared__ __half sm[];

    const __half* WHp = (mode == 2) ? g_wph : g_wqh;
    const __half* WLp = (mode == 2) ? g_wpl : g_wql;

    int tid = threadIdx.x;
    int m0 = blockIdx.y * 256, n0 = blockIdx.x * 128;

    const __half* aH = g_abf + (size_t)(m0 >> 8) * ATILEH;
    const __half* aL = aH + APL;
    const __half* wH = WHp + (size_t)(n0 >> 7) * WTILEH;
    const __half* wL = WLp + (size_t)(n0 >> 7) * WTILEH;

    uint32_t sbase = smem_u32(sm);
    uint32_t mb = sbase + 3 * STG;

    uint32_t stgbytes = (passes == 3) ? STG : (STG - 12288);

    if (tid == 0) {
#pragma unroll
        for (int s = 0; s < 3; s++) mbar_init(mb + s * 8, 1);
    }
    __syncthreads();

    if (tid == 0) {
#pragma unroll
        for (int s = 0; s < 2; s++) {
            uint32_t sb = sbase + s * STG;
            uint32_t mbs = mb + s * 8;
            mbar_expect(mbs, stgbytes);
            bulkcp(sb + AH_S, aH + s * 2 * ACHH, 24576, mbs);
            bulkcp(sb + AL_S, aL + s * 2 * ACHH, 24576, mbs);
            bulkcp(sb + WH_S, wH + s * 2 * WCHH, 12288, mbs);
            if (passes == 3)
                bulkcp(sb + WL_S, wL + s * 2 * WCHH, 12288, mbs);
        }
    }

    int lane = tid & 31;
    int wid = tid >> 5;
    int mbase = (wid & 3) * 64;
    int nbase = (wid >> 2) * 32;

    int ar = lane & 15, ak = (lane >> 4) * 8;
    uint32_t offA0 = ((mbase + ar) * TP + ak) * 2;
    int br = (lane & 7) + ((lane >> 4) << 3), bk = ((lane >> 3) & 1) * 8;
    uint32_t offB0 = ((nbase + br) * TP + bk) * 2;

    float acc[4][4][4];
#pragma unroll
    for (int i = 0; i < 4; i++)
#pragma unroll
        for (int j = 0; j < 4; j++)
#pragma unroll
            for (int k = 0; k < 4; k++) acc[i][j][k] = 0.f;

    int stg = 0, par = 0;
    for (int pc = 0; pc < 12; pc++) {
        mbar_wait(mb + stg * 8, par);
        uint32_t bb = sbase + stg * STG;

        uint32_t ah[4][4], al[4][4], bf[2][4];
#pragma unroll
        for (int g = 0; g < 4; g++)
            ldmx4(ah[g], bb + AH_S + offA0 + g * 768);
#pragma unroll
        for (int g = 0; g < 4; g++)
            ldmx4(al[g], bb + AL_S + offA0 + g * 768);
#pragma unroll
        for (int g = 0; g < 2; g++)
            ldmx4(bf[g], bb + WH_S + offB0 + g * 768);

        __syncthreads();

        if (tid == 0 && pc < 10) {
            int s = (pc + 2) % 3;
            uint32_t sb = sbase + s * STG;
            uint32_t mbs = mb + s * 8;
            int ck = pc + 2;
            mbar_expect(mbs, stgbytes);
            bulkcp(sb + AH_S, aH + ck * 2 * ACHH, 24576, mbs);
            bulkcp(sb + AL_S, aL + ck * 2 * ACHH, 24576, mbs);
            bulkcp(sb + WH_S, wH + ck * 2 * WCHH, 12288, mbs);
            if (passes == 3)
                bulkcp(sb + WL_S, wL + ck * 2 * WCHH, 12288, mbs);
        }

        // ---- sub 0 math ----
#pragma unroll
        for (int mi = 0; mi < 4; mi++)
#pragma unroll
            for (int g = 0; g < 2; g++)
#pragma unroll
                for (int sub = 0; sub < 2; sub++)
                    mma16816(acc[mi][g * 2 + sub], ah[mi], &bf[g][sub * 2]);
#pragma unroll
        for (int mi = 0; mi < 4; mi++)
#pragma unroll
            for (int g = 0; g < 2; g++)
#pragma unroll
                for (int sub = 0; sub < 2; sub++)
                    mma16816(acc[mi][g * 2 + sub], al[mi], &bf[g][sub * 2]);
        if (passes == 3) {
#pragma unroll
            for (int g = 0; g < 2; g++)
                ldmx4(bf[g], bb + WL_S + offB0 + g * 768);
#pragma unroll
            for (int mi = 0; mi < 4; mi++)
#pragma unroll
                for (int g = 0; g < 2; g++)
#pragma unroll
                    for (int sub = 0; sub < 2; sub++)
                        mma16816(acc[mi][g * 2 + sub], ah[mi], &bf[g][sub * 2]);
        }

        // ---- sub 1 ----
#pragma unroll
        for (int g = 0; g < 4; g++)
            ldmx4(ah[g], bb + AH_S + 12288 + offA0 + g * 768);
#pragma unroll
        for (int g = 0; g < 4; g++)
            ldmx4(al[g], bb + AL_S + 12288 + offA0 + g * 768);
#pragma unroll
        for (int g = 0; g < 2; g++)
            ldmx4(bf[g], bb + WH_S + 6144 + offB0 + g * 768);
#pragma unroll
        for (int mi = 0; mi < 4; mi++)
#pragma unroll
            for (int g = 0; g < 2; g++)
#pragma unroll
                for (int sub = 0; sub < 2; sub++)
                    mma16816(acc[mi][g * 2 + sub], ah[mi], &bf[g][sub * 2]);
#pragma unroll
        for (int mi = 0; mi < 4; mi++)
#pragma unroll
            for (int g = 0; g < 2; g++)
#pragma unroll
                for (int sub = 0; sub < 2; sub++)
                    mma16816(acc[mi][g * 2 + sub], al[mi], &bf[g][sub * 2]);
        if (passes == 3) {
#pragma unroll
            for (int g = 0; g < 2; g++)
                ldmx4(bf[g], bb + WL_S + 6144 + offB0 + g * 768);
#pragma unroll
            for (int mi = 0; mi < 4; mi++)
#pragma unroll
                for (int g = 0; g < 2; g++)
#pragma unroll
                    for (int sub = 0; sub < 2; sub++)
                        mma16816(acc[mi][g * 2 + sub], ah[mi], &bf[g][sub * 2]);
        }

        if (++stg == 3) { stg = 0; par ^= 1; }
    }

    // epilogue
    int rbase = m0 + mbase, cbase = n0 + nbase;
#pragma unroll
    for (int mi = 0; mi < 4; mi++)
#pragma unroll
        for (int ni = 0; ni < 4; ni++) {
            int rrow = rbase + mi * 16 + (lane >> 2);
            int col = cbase + ni * 8 + (lane & 3) * 2;
            if (mode == 1) {
                __half2* o0 = (__half2*)(g_qkvh + (size_t)rrow * N + col);
                __half2* o1 = (__half2*)(g_qkvh + (size_t)(rrow + 8) * N + col);
                *o0 = __floats2half2_rn(acc[mi][ni][0], acc[mi][ni][1]);
                *o1 = __floats2half2_rn(acc[mi][ni][2], acc[mi][ni][3]);
            } else {
                float b0 = 0.f, b1 = 0.f;
                if (mode == 2) { b0 = bias[col]; b1 = bias[col + 1]; }
                float* O = (mode == 0) ? g_qkvc : Oext;
                float2 v0 = make_float2(acc[mi][ni][0] + b0, acc[mi][ni][1] + b1);
                float2 v1 = make_float2(acc[mi][ni][2] + b0, acc[mi][ni][3] + b1);
                *(float2*)&O[(size_t)rrow * N + col] = v0;
                *(float2*)&O[(size_t)(rrow + 8) * N + col] = v1;
            }
        }
}

// ---------------- K3: coarse routing attention + top-k (flash-style) ------
#define CA_SMEM (2 * 256 * 48 * 4)
__global__ __launch_bounds__(128) void coarse_attn_kernel()
{
    extern __shared__ float cas[];
    float* Ks = cas;
    float* Vs = cas + 256 * 48;

    int bid = blockIdx.x;
    int half = bid & 1;
    int hd = (bid >> 1) & 7;
    int b = bid >> 4;
    int tid = threadIdx.x;

    const float* base = g_qkvc + (size_t)b * NCn * C3n;

    for (int idx = tid; idx < 3072; idx += 128) {
        int j = idx / 12, d4 = (idx % 12) * 4;
        const float* rp = base + (size_t)j * C3n + Cn + hd * Dh + d4;
        *(float4*)&Ks[j * 48 + d4] = *(const float4*)rp;
        *(float4*)&Vs[j * 48 + d4] = *(const float4*)(rp + Cn);
    }

    int q = half * 128 + tid;
    float qv[48];
    const float* qp = base + (size_t)q * C3n + hd * Dh;
#pragma unroll
    for (int i = 0; i < 12; i++) {
        float4 v = *(const float4*)(qp + i * 4);
        qv[i * 4 + 0] = v.x; qv[i * 4 + 1] = v.y;
        qv[i * 4 + 2] = v.z; qv[i * 4 + 3] = v.w;
    }
    __syncthreads();

    float v0 = -FLT_MAX, v1 = -FLT_MAX, v2 = -FLT_MAX, v3 = -FLT_MAX;
    int i0 = 0, i1 = 0, i2 = 0, i3 = 0;
    for (int j = 0; j < 256; j++) {
        float a0 = 0.f, a1 = 0.f, a2 = 0.f, a3 = 0.f;
        const float* kp = &Ks[j * 48];
#pragma unroll
        for (int d4 = 0; d4 < 12; d4++) {
            float4 kv = *(const float4*)(kp + d4 * 4);
            a0 += qv[d4 * 4 + 0] * kv.x;
            a1 += qv[d4 * 4 + 1] * kv.y;
            a2 += qv[d4 * 4 + 2] * kv.z;
            a3 += qv[d4 * 4 + 3] * kv.w;
        }
        float s = (a0 + a1) + (a2 + a3);
        if (s > v3) {
            if (s > v0)      { v3 = v2; i3 = i2; v2 = v1; i2 = i1; v1 = v0; i1 = i0; v0 = s; i0 = j; }
            else if (s > v1) { v3 = v2; i3 = i2; v2 = v1; i2 = i1; v1 = s; i1 = j; }
            else if (s > v2) { v3 = v2; i3 = i2; v2 = s; i2 = j; }
            else             { v3 = s; i3 = j; }
        }
    }
    int obase = ((b * 8 + hd) * 256 + q) * 4;
    g_topk[obase + 0] = i0; g_topk[obase + 1] = i1;
    g_topk[obase + 2] = i2; g_topk[obase + 3] = i3;

    float mx = v0 * SCALE;

    float oacc[48];
#pragma unroll
    for (int d = 0; d < 48; d++) oacc[d] = 0.f;
    float psum = 0.f;
    for (int j = 0; j < 256; j++) {
        float a0 = 0.f, a1 = 0.f, a2 = 0.f, a3 = 0.f;
        const float* kp = &Ks[j * 48];
#pragma unroll
        for (int d4 = 0; d4 < 12; d4++) {
            float4 kv = *(const float4*)(kp + d4 * 4);
            a0 += qv[d4 * 4 + 0] * kv.x;
            a1 += qv[d4 * 4 + 1] * kv.y;
            a2 += qv[d4 * 4 + 2] * kv.z;
            a3 += qv[d4 * 4 + 3] * kv.w;
        }
        float p = __expf(((a0 + a1) + (a2 + a3)) * SCALE - mx);
        psum += p;
        const float* vp = &Vs[j * 48];
#pragma unroll
        for (int d4 = 0; d4 < 12; d4++) {
            float4 vv = *(const float4*)(vp + d4 * 4);
            oacc[d4 * 4 + 0] += p * vv.x;
            oacc[d4 * 4 + 1] += p * vv.y;
            oacc[d4 * 4 + 2] += p * vv.z;
            oacc[d4 * 4 + 3] += p * vv.w;
        }
    }
    float inv = 1.f / psum;
    float* op = &g_xo[((size_t)(b * NCn + q)) * Cn + hd * Dh];
#pragma unroll
    for (int i = 0; i < 12; i++) {
        float4 v = make_float4(oacc[i * 4] * inv, oacc[i * 4 + 1] * inv,
                               oacc[i * 4 + 2] * inv, oacc[i * 4 + 3] * inv);
        *(float4*)(op + i * 4) = v;
    }
}

// ---------------- K5: fine windowed attention (tensor-core) ---------------
// smem halves layout: sQ[16][48] | sK[64][48] | sVt[48][64] | sP[16][64]
#define SQ_H  0
#define SK_H  768
#define SVT_H 3840
#define SP_H  6912
#define A2_P  68
__global__ __launch_bounds__(128) void fine_attn_kernel()
{
    __shared__ __half hsm[8192];
    __shared__ float A2[16 * A2_P];
    __shared__ int   wins[4];

    int bid = blockIdx.x;
    int n  = bid & 255;
    int hd = (bid >> 8) & 7;
    int b  = bid >> 11;

    int tid = threadIdx.x;
    int lane = tid & 31, wid = tid >> 5;
    int hc = n >> 4, wc = n & 15;
    const __half* base = g_qkvh + (size_t)b * HWn * C3n;

    if (tid < 4) wins[tid] = g_topk[(size_t)bid * 4 + tid];

    // stage Q (row-major 16x48)
    for (int idx = tid; idx < 16 * 12; idx += 128) {
        int p = idx / 12, d4 = (idx % 12) * 4;
        int s = (hc * 4 + (p >> 2)) * Wn + wc * 4 + (p & 3);
        uint2 r = *(const uint2*)&base[(size_t)s * C3n + hd * Dh + d4];
        *(uint2*)&hsm[SQ_H + p * 48 + d4] = r;
    }
    __syncthreads();  // wins visible

    // stage K (row-major 64x48) and V transposed (48x64)
    for (int idx = tid; idx < 64 * 12; idx += 128) {
        int p = idx / 12, d4 = (idx % 12) * 4;
        int t = p >> 4, pl = p & 15;
        int m = wins[t];
        int s = ((m >> 4) * 4 + (pl >> 2)) * Wn + (m & 15) * 4 + (pl & 3);
        const __half* rw = &base[(size_t)s * C3n + hd * Dh + d4];
        uint2 rk = *(const uint2*)(rw + Cn);
        uint2 rv = *(const uint2*)(rw + 2 * Cn);
        *(uint2*)&hsm[SK_H + p * 48 + d4] = rk;
        __half hv[4];
        *(uint2*)hv = rv;
#pragma unroll
        for (int j = 0; j < 4; j++)
            hsm[SVT_H + (d4 + j) * 64 + p] = hv[j];
    }
    __syncthreads();

    uint32_t sb = smem_u32(hsm);
    int br = (lane & 7) + ((lane >> 4) << 3);
    int bk = ((lane >> 3) & 1) * 8;

    // QK^T: warp w covers keys [w*16, w*16+16)
    {
        uint32_t offQ = sb + (SQ_H + (lane & 15) * 48 + (lane >> 4) * 8) * 2;
        uint32_t offK = sb + (SK_H + (wid * 16 + br) * 48 + bk) * 2;
        float acc[2][4] = {{0.f, 0.f, 0.f, 0.f}, {0.f, 0.f, 0.f, 0.f}};
#pragma unroll
        for (int kc = 0; kc < 3; kc++) {
            uint32_t aq[4], bkf[4];
            ldmx4(aq,  offQ + kc * 32);
            ldmx4(bkf, offK + kc * 32);
            mma16816(acc[0], aq, &bkf[0]);
            mma16816(acc[1], aq, &bkf[2]);
        }
        int row = lane >> 2, c2 = (lane & 3) * 2;
#pragma unroll
        for (int t = 0; t < 2; t++) {
            int col = wid * 16 + t * 8 + c2;
            A2[row * A2_P + col]           = acc[t][0] * SCALE;
            A2[row * A2_P + col + 1]       = acc[t][1] * SCALE;
            A2[(row + 8) * A2_P + col]     = acc[t][2] * SCALE;
            A2[(row + 8) * A2_P + col + 1] = acc[t][3] * SCALE;
        }
    }
    __syncthreads();

    // softmax: 8 threads per row, 8 cols each
    {
        int row = tid >> 3, j = tid & 7;
        float* ap = &A2[row * A2_P + j * 8];
        float v[8];
        float mx = -FLT_MAX;
#pragma unroll
        for (int i = 0; i < 8; i++) { v[i] = ap[i]; mx = fmaxf(mx, v[i]); }
#pragma unroll
        for (int m = 1; m < 8; m <<= 1)
            mx = fmaxf(mx, __shfl_xor_sync(0xffffffffu, mx, m));
        float sum = 0.f;
#pragma unroll
        for (int i = 0; i < 8; i++) { v[i] = __expf(v[i] - mx); sum += v[i]; }
#pragma unroll
        for (int m = 1; m < 8; m <<= 1)
            sum += __shfl_xor_sync(0xffffffffu, sum, m);
        float inv = 1.f / sum;
#pragma unroll
        for (int i = 0; i < 8; i++) ap[i] = v[i] * inv;
    }
    __syncthreads();

    // convert probabilities to fp16 sP[16][64]
    {
        int row = tid >> 3, c0 = (tid & 7) * 8;
        const float* ap = &A2[row * A2_P + c0];
        __half2* pp = (__half2*)&hsm[SP_H + row * 64 + c0];
        pp[0] = __floats2half2_rn(ap[0], ap[1]);
        pp[1] = __floats2half2_rn(ap[2], ap[3]);
        pp[2] = __floats2half2_rn(ap[4], ap[5]);
        pp[3] = __floats2half2_rn(ap[6], ap[7]);
    }
    __syncthreads();

    // AV: warps 0-2, warp w covers dims [w*16, w*16+16)
    if (wid < 3) {
        uint32_t offP = sb + (SP_H + (lane & 15) * 64 + (lane >> 4) * 8) * 2;
        uint32_t offV = sb + (SVT_H + (wid * 16 + br) * 64 + bk) * 2;
        float acc[2][4] = {{0.f, 0.f, 0.f, 0.f}, {0.f, 0.f, 0.f, 0.f}};
#pragma unroll
        for (int kc = 0; kc < 4; kc++) {
            uint32_t ap_[4], bv[4];
            ldmx4(ap_, offP + kc * 32);
            ldmx4(bv,  offV + kc * 32);
            mma16816(acc[0], ap_, &bv[0]);
            mma16816(acc[1], ap_, &bv[2]);
        }
        int row = lane >> 2, c2 = (lane & 3) * 2;
#pragma unroll
        for (int t = 0; t < 2; t++) {
            int dd = wid * 16 + t * 8 + c2;
#pragma unroll
            for (int rh = 0; rh < 2; rh++) {
                int p = row + rh * 8;
                int yy = hc * 4 + (p >> 2), xx = wc * 4 + (p & 3);
                __half2 hv = __floats2half2_rn(acc[t][rh * 2], acc[t][rh * 2 + 1]);
                *(__half2*)&g_yo[(((size_t)(b * Hn + yy)) * Wn + xx) * Cn + hd * Dh + dd] = hv;
            }
        }
    }
}

// ---------------- K6: upsample(xo) -> dwconv3x3(dwx) -> mix with yo -------
__global__ __launch_bounds__(384) void dwmix_kernel(
    const float* __restrict__ dwxw, const float* __restrict__ dwxb)
{
    __shared__ float wsh[Cn * 9];
    int tid = threadIdx.x;
    for (int i = tid; i < Cn * 9; i += 384) wsh[i] = dwxw[i];
    __syncthreads();

    int b  = blockIdx.x >> 6;
    int yy = blockIdx.x & 63;
    int c  = tid;
    float w[9];
#pragma unroll
    for (int i = 0; i < 9; i++) w[i] = wsh[c * 9 + i];
    float bias = dwxb[c];

    const float* xob = g_xo + (size_t)b * NCn * Cn + c;
    bool up = yy > 0, dn = yy < 63;
    int ru = (yy - 1) >> 2, rm = yy >> 2, rd = (yy + 1) >> 2;

    float3 cm = make_float3(0.f, 0.f, 0.f), cc, cp;
    cc.x = up ? xob[(size_t)(ru * 16) * Cn] : 0.f;
    cc.y = xob[(size_t)(rm * 16) * Cn];
    cc.z = dn ? xob[(size_t)(rd * 16) * Cn] : 0.f;

    size_t pix0 = ((size_t)(b * Hn + yy)) * Wn;
    for (int xx = 0; xx < 64; xx++) {
        if (xx < 63) {
            int xc4 = (xx + 1) >> 2;
            cp.x = up ? xob[(size_t)(ru * 16 + xc4) * Cn] : 0.f;
            cp.y = xob[(size_t)(rm * 16 + xc4) * Cn];
            cp.z = dn ? xob[(size_t)(rd * 16 + xc4) * Cn] : 0.f;
        } else {
            cp = make_float3(0.f, 0.f, 0.f);
        }
        float acc = bias
            + w[0] * cm.x + w[1] * cc.x + w[2] * cp.x
            + w[3] * cm.y + w[4] * cc.y + w[5] * cp.y
            + w[6] * cm.z + w[7] * cc.z + w[8] * cp.z;
        size_t pix = pix0 + xx;
        float yv = __half2float(g_yo[pix * Cn + c]);
        g_z[pix * Cn + c] = __float2half(0.5f * acc + 0.5f * yv);
        cm = cc; cc = cp;
    }
}

// ---------------- K7: dwconv3x3(dw) on z -> fp16 hi/lo planes (tiled) -----
__global__ __launch_bounds__(384) void dwconv2_kernel(
    const float* __restrict__ dww, const float* __restrict__ dwb)
{
    __shared__ float wsh[Cn * 9];
    int tid = threadIdx.x;
    for (int i = tid; i < Cn * 9; i += 384) wsh[i] = dww[i];
    __syncthreads();

    int b  = blockIdx.x >> 6;
    int yy = blockIdx.x & 63;
    int c  = tid;
    float w[9];
#pragma unroll
    for (int i = 0; i < 9; i++) w[i] = wsh[c * 9 + i];
    float bias = dwb[c];

    const __half* zb = g_z + (size_t)b * HWn * Cn + c;
    bool up = yy > 0, dn = yy < 63;
    size_t rowm = (size_t)yy * Wn;

    float3 cm = make_float3(0.f, 0.f, 0.f), cc, cp;
    cc.x = up ? __half2float(zb[(rowm - Wn) * Cn]) : 0.f;
    cc.y = __half2float(zb[rowm * Cn]);
    cc.z = dn ? __half2float(zb[(rowm + Wn) * Cn]) : 0.f;

    int mrow0 = b * HWn + yy * Wn;
    for (int xx = 0; xx < 64; xx++) {
        if (xx < 63) {
            size_t bcol = rowm + xx + 1;
            cp.x = up ? __half2float(zb[(bcol - Wn) * Cn]) : 0.f;
            cp.y = __half2float(zb[bcol * Cn]);
            cp.z = dn ? __half2float(zb[(bcol + Wn) * Cn]) : 0.f;
        } else {
            cp = make_float3(0.f, 0.f, 0.f);
        }
        float acc = bias
            + w[0] * cm.x + w[1] * cc.x + w[2] * cp.x
            + w[3] * cm.y + w[4] * cc.y + w[5] * cp.y
            + w[6] * cm.z + w[7] * cc.z + w[8] * cp.z;
        __half h = __float2half(acc);
        __half l = __float2half(acc - __half2float(h));
        size_t o = a_off(mrow0 + xx, c);
        g_abf[o] = h;
        g_abf[APL + o] = l;
        cm = cc; cc = cp;
    }
}

// ---------------- launch ----------------
extern "C" void kernel_launch(void* const* d_in, const int* in_sizes, int n_in,
                              void* d_out, int out_size)
{
    const float* x     = (const float*)d_in[0];
    const float* qkv_w = (const float*)d_in[1];
    const float* dwx_w = (const float*)d_in[2];
    const float* dwx_b = (const float*)d_in[3];
    const float* dw_w  = (const float*)d_in[4];
    const float* dw_b  = (const float*)d_in[5];
    const float* pw_w  = (const float*)d_in[6];
    const float* pw_b  = (const float*)d_in[7];
    float* out = (float*)d_out;

    cudaFuncSetAttribute(gemm_mma, cudaFuncAttributeMaxDynamicSharedMemorySize,
                         GSMEM);
    cudaFuncSetAttribute(coarse_attn_kernel,
                         cudaFuncAttributeMaxDynamicSharedMemorySize, CA_SMEM);

    // weight conversions (tiny)
    convw_kernel<<<(C3n * Cn + 255) / 256, 256>>>(qkv_w, C3n * Cn, 0);
    convw_kernel<<<(Cn * Cn + 255) / 256, 256>>>(pw_w, Cn * Cn, 1);

    // 1) coarse pooling
    pool_kernel<<<Bn * NCn, Cn>>>(x);

    // 2) coarse QKV (3-pass, exact top-k)
    gemm_mma<<<dim3(C3n / 128, (Bn * NCn) / 256), 512, GSMEM>>>(
        nullptr, nullptr, C3n, 0, 3);

    // 3) coarse routing attention + top-k
    coarse_attn_kernel<<<Bn * NHd * 2, 128, CA_SMEM>>>();

    // 4) fine QKV (2-pass, fp16 output)
    convA_kernel<<<(Bn * HWn * 48 + 255) / 256, 256>>>(x, Bn * HWn * 48);
    gemm_mma<<<dim3(C3n / 128, (Bn * HWn) / 256), 512, GSMEM>>>(
        nullptr, nullptr, C3n, 1, 2);

    // 5) fine windowed attention (tensor-core)
    fine_attn_kernel<<<Bn * NHd * NCn, 128>>>();

    // 6) upsample+dwconv(dwx)+mix (yo fp16, z fp16)
    dwmix_kernel<<<Bn * Hn, Cn>>>(dwx_w, dwx_b);

    // 7) dwconv(dw) -> fp16 planes
    dwconv2_kernel<<<Bn * Hn, Cn>>>(dw_w, dw_b);

    // 8) pointwise projection (+bias, 2-pass)
    gemm_mma<<<dim3(Cn / 128, (Bn * HWn) / 256), 512, GSMEM>>>(
        pw_b, out, Cn, 2, 2);
}

// round 16
// speedup vs baseline: 1.8565x; 1.1259x over previous
#include <cuda_runtime.h>
#include <cuda_fp16.h>
#include <float.h>
#include <stdint.h>

// Problem constants
#define Bn   8
#define Hn   64
#define Wn   64
#define Cn   384
#define NHd  8
#define Dh   48
#define NCn  256
#define HWn  4096
#define C3n  1152
#define SCALE 0.14433756729740643f

// ---- tiled operand layout: [tile][kchunk(24)][rows][pitch 24 halves] ----
#define TP     24
#define ACHH   (256 * TP)
#define WCHH   (128 * TP)
#define ATILEH (24 * ACHH)
#define WTILEH (24 * WCHH)
#define APL    ((size_t)128 * ATILEH)

// ---------------- scratch (device globals; no allocation) ----------------
__device__ float  g_qkvc[Bn * NCn * C3n];
__device__ int    g_topk[Bn * NHd * NCn * 4];
__device__ float  g_xo  [Bn * NCn * Cn];
__device__ __half g_qkvh[(size_t)Bn * HWn * C3n];   // fine QKV (fp16)
__device__ __half g_yo  [(size_t)Bn * HWn * Cn];    // fine attn out (fp16)
__device__ __half g_z   [(size_t)Bn * HWn * Cn];    // mixed (fp16)
__device__ __half g_abf[2 * APL];
__device__ __half g_wqh[9 * WTILEH];
__device__ __half g_wql[9 * WTILEH];
__device__ __half g_wph[3 * WTILEH];
__device__ __half g_wpl[3 * WTILEH];

__device__ __forceinline__ size_t a_off(int m, int k) {
    return (size_t)(m >> 8) * ATILEH + (size_t)(k >> 4) * ACHH
         + (m & 255) * TP + (k & 15);
}
__device__ __forceinline__ size_t w_off(int n, int k) {
    return (size_t)(n >> 7) * WTILEH + (size_t)(k >> 4) * WCHH
         + (n & 127) * TP + (k & 15);
}

// ---------------- helpers ----------------
__device__ __forceinline__ uint32_t smem_u32(const void* p) {
    uint32_t a;
    asm("{ .reg .u64 t; cvta.to.shared.u64 t, %1; cvt.u32.u64 %0, t; }"
        : "=r"(a) : "l"(p));
    return a;
}
__device__ __forceinline__ void ldmx4(uint32_t* r, uint32_t addr) {
    asm volatile("ldmatrix.sync.aligned.m8n8.x4.shared.b16 {%0,%1,%2,%3}, [%4];"
        : "=r"(r[0]), "=r"(r[1]), "=r"(r[2]), "=r"(r[3]) : "r"(addr));
}
__device__ __forceinline__ void mma16816(float* d, const uint32_t* a, const uint32_t* b) {
    asm volatile(
        "mma.sync.aligned.m16n8k16.row.col.f32.f16.f16.f32 "
        "{%0,%1,%2,%3}, {%4,%5,%6,%7}, {%8,%9}, {%0,%1,%2,%3};"
        : "+f"(d[0]), "+f"(d[1]), "+f"(d[2]), "+f"(d[3])
        : "r"(a[0]), "r"(a[1]), "r"(a[2]), "r"(a[3]), "r"(b[0]), "r"(b[1]));
}
__device__ __forceinline__ uint32_t pack_hf2(float x, float y) {
    unsigned short hx = __half_as_ushort(__float2half(x));
    unsigned short hy = __half_as_ushort(__float2half(y));
    return (uint32_t)hx | ((uint32_t)hy << 16);
}
__device__ __forceinline__ void mbar_init(uint32_t a, uint32_t cnt) {
    asm volatile("mbarrier.init.shared.b64 [%0], %1;" :: "r"(a), "r"(cnt) : "memory");
}
__device__ __forceinline__ void mbar_expect(uint32_t a, uint32_t bytes) {
    asm volatile("mbarrier.arrive.expect_tx.shared.b64 _, [%0], %1;"
                 :: "r"(a), "r"(bytes) : "memory");
}
__device__ __forceinline__ void mbar_wait(uint32_t a, uint32_t parity) {
    asm volatile(
        "{\n\t.reg .pred P;\n\t"
        "WL%=:\n\t"
        "mbarrier.try_wait.parity.acquire.cta.shared::cta.b64 P, [%0], %1, 0x989680;\n\t"
        "@P bra.uni WD%=;\n\t"
        "bra.uni WL%=;\n\t"
        "WD%=:\n\t}"
        :: "r"(a), "r"(parity) : "memory");
}
__device__ __forceinline__ void bulkcp(uint32_t sdst, const void* gsrc,
                                       uint32_t bytes, uint32_t mbar) {
    asm volatile(
        "cp.async.bulk.shared::cta.global.mbarrier::complete_tx::bytes "
        "[%0], [%1], %2, [%3];"
        :: "r"(sdst), "l"(gsrc), "r"(bytes), "r"(mbar) : "memory");
}

// ---------------- K1: 4x4 average pool -> fp16 hi/lo planes (tiled) -------
__global__ __launch_bounds__(384) void pool_kernel(const float* __restrict__ x)
{
    int blk = blockIdx.x;
    int n = blk & 255, b = blk >> 8;
    int hc = n >> 4, wc = n & 15;
    int c = threadIdx.x;
    float s = 0.f;
#pragma unroll
    for (int i = 0; i < 4; i++)
#pragma unroll
        for (int j = 0; j < 4; j++)
            s += x[(((size_t)(b * Hn + hc * 4 + i)) * Wn + wc * 4 + j) * Cn + c];
    s *= 0.0625f;
    __half h = __float2half(s);
    __half l = __float2half(s - __half2float(h));
    size_t o = a_off(b * NCn + n, c);
    g_abf[o] = h;
    g_abf[APL + o] = l;
}

// ---------------- weight fp16 hi/lo conversion (tiled) ----------------
__global__ __launch_bounds__(256) void convw_kernel(
    const float* __restrict__ w, int total, int mode)
{
    int i = blockIdx.x * 256 + threadIdx.x;
    if (i >= total) return;
    float v = w[i];
    __half h = __float2half(v);
    __half l = __float2half(v - __half2float(h));
    int n = i / 384, k = i % 384;
    size_t o = w_off(n, k);
    if (mode == 0) { g_wqh[o] = h; g_wql[o] = l; }
    else           { g_wph[o] = h; g_wpl[o] = l; }
}

// ---------------- A conversion: x (f32) -> fp16 hi plane only (tiled) -----
__global__ __launch_bounds__(256) void convA_kernel(
    const float* __restrict__ src, int n8)
{
    int i = blockIdx.x * 256 + threadIdx.x;
    if (i >= n8) return;
    float4 v0 = ((const float4*)src)[i * 2];
    float4 v1 = ((const float4*)src)[i * 2 + 1];
    uint4 H;
    H.x = pack_hf2(v0.x, v0.y); H.y = pack_hf2(v0.z, v0.w);
    H.z = pack_hf2(v1.x, v1.y); H.w = pack_hf2(v1.z, v1.w);
    int m = i / 48, k0 = (i % 48) * 8;
    size_t o = a_off(m, k0);
    *(uint4*)(g_abf + o) = H;
}

// ---------------- tensor-core GEMM ----------------------------------------
// passes==3: Ah*Wh + Al*Wh + Ah*Wl   passes==2: Ah*Wh + Al*Wh
// passes==1: Ah*Wh
// mode 0: O=g_qkvc (f32)  mode 1: O=g_qkvh (f16)  mode 2: O=out (+bias)
#define AH_S 0
#define AL_S 24576
#define WH_S 49152
#define WL_S 61440
#define STG  73728
#define GSMEM (3 * STG + 64)

__global__ __launch_bounds__(512, 1) void gemm_mma(
    const float* __restrict__ bias, float* __restrict__ Oext, int N, int mode,
    int passes)
{
    extern __shared__ __half sm[];

    const __half* WHp = (mode == 2) ? g_wph : g_wqh;
    const __half* WLp = (mode == 2) ? g_wpl : g_wql;

    int tid = threadIdx.x;
    int m0 = blockIdx.y * 256, n0 = blockIdx.x * 128;

    const __half* aH = g_abf + (size_t)(m0 >> 8) * ATILEH;
    const __half* aL = aH + APL;
    const __half* wH = WHp + (size_t)(n0 >> 7) * WTILEH;
    const __half* wL = WLp + (size_t)(n0 >> 7) * WTILEH;

    uint32_t sbase = smem_u32(sm);
    uint32_t mb = sbase + 3 * STG;

    uint32_t stgbytes = (passes == 3) ? STG
                      : (passes == 2) ? (STG - 12288) : 36864u;

    if (tid == 0) {
#pragma unroll
        for (int s = 0; s < 3; s++) mbar_init(mb + s * 8, 1);
    }
    __syncthreads();

    if (tid == 0) {
#pragma unroll
        for (int s = 0; s < 2; s++) {
            uint32_t sb = sbase + s * STG;
            uint32_t mbs = mb + s * 8;
            mbar_expect(mbs, stgbytes);
            bulkcp(sb + AH_S, aH + s * 2 * ACHH, 24576, mbs);
            if (passes >= 2)
                bulkcp(sb + AL_S, aL + s * 2 * ACHH, 24576, mbs);
            bulkcp(sb + WH_S, wH + s * 2 * WCHH, 12288, mbs);
            if (passes == 3)
                bulkcp(sb + WL_S, wL + s * 2 * WCHH, 12288, mbs);
        }
    }

    int lane = tid & 31;
    int wid = tid >> 5;
    int mbase = (wid & 3) * 64;
    int nbase = (wid >> 2) * 32;

    int ar = lane & 15, ak = (lane >> 4) * 8;
    uint32_t offA0 = ((mbase + ar) * TP + ak) * 2;
    int br = (lane & 7) + ((lane >> 4) << 3), bk = ((lane >> 3) & 1) * 8;
    uint32_t offB0 = ((nbase + br) * TP + bk) * 2;

    float acc[4][4][4];
#pragma unroll
    for (int i = 0; i < 4; i++)
#pragma unroll
        for (int j = 0; j < 4; j++)
#pragma unroll
            for (int k = 0; k < 4; k++) acc[i][j][k] = 0.f;

    int stg = 0, par = 0;
    for (int pc = 0; pc < 12; pc++) {
        mbar_wait(mb + stg * 8, par);
        uint32_t bb = sbase + stg * STG;

        uint32_t ah[4][4], al[4][4], bf[2][4];
#pragma unroll
        for (int g = 0; g < 4; g++)
            ldmx4(ah[g], bb + AH_S + offA0 + g * 768);
        if (passes >= 2) {
#pragma unroll
            for (int g = 0; g < 4; g++)
                ldmx4(al[g], bb + AL_S + offA0 + g * 768);
        }
#pragma unroll
        for (int g = 0; g < 2; g++)
            ldmx4(bf[g], bb + WH_S + offB0 + g * 768);

        __syncthreads();

        if (tid == 0 && pc < 10) {
            int s = (pc + 2) % 3;
            uint32_t sb = sbase + s * STG;
            uint32_t mbs = mb + s * 8;
            int ck = pc + 2;
            mbar_expect(mbs, stgbytes);
            bulkcp(sb + AH_S, aH + ck * 2 * ACHH, 24576, mbs);
            if (passes >= 2)
                bulkcp(sb + AL_S, aL + ck * 2 * ACHH, 24576, mbs);
            bulkcp(sb + WH_S, wH + ck * 2 * WCHH, 12288, mbs);
            if (passes == 3)
                bulkcp(sb + WL_S, wL + ck * 2 * WCHH, 12288, mbs);
        }

        // ---- sub 0 math ----
#pragma unroll
        for (int mi = 0; mi < 4; mi++)
#pragma unroll
            for (int g = 0; g < 2; g++)
#pragma unroll
                for (int sub = 0; sub < 2; sub++)
                    mma16816(acc[mi][g * 2 + sub], ah[mi], &bf[g][sub * 2]);
        if (passes >= 2) {
#pragma unroll
            for (int mi = 0; mi < 4; mi++)
#pragma unroll
                for (int g = 0; g < 2; g++)
#pragma unroll
                    for (int sub = 0; sub < 2; sub++)
                        mma16816(acc[mi][g * 2 + sub], al[mi], &bf[g][sub * 2]);
        }
        if (passes == 3) {
#pragma unroll
            for (int g = 0; g < 2; g++)
                ldmx4(bf[g], bb + WL_S + offB0 + g * 768);
#pragma unroll
            for (int mi = 0; mi < 4; mi++)
#pragma unroll
                for (int g = 0; g < 2; g++)
#pragma unroll
                    for (int sub = 0; sub < 2; sub++)
                        mma16816(acc[mi][g * 2 + sub], ah[mi], &bf[g][sub * 2]);
        }

        // ---- sub 1 ----
#pragma unroll
        for (int g = 0; g < 4; g++)
            ldmx4(ah[g], bb + AH_S + 12288 + offA0 + g * 768);
        if (passes >= 2) {
#pragma unroll
            for (int g = 0; g < 4; g++)
                ldmx4(al[g], bb + AL_S + 12288 + offA0 + g * 768);
        }
#pragma unroll
        for (int g = 0; g < 2; g++)
            ldmx4(bf[g], bb + WH_S + 6144 + offB0 + g * 768);
#pragma unroll
        for (int mi = 0; mi < 4; mi++)
#pragma unroll
            for (int g = 0; g < 2; g++)
#pragma unroll
                for (int sub = 0; sub < 2; sub++)
                    mma16816(acc[mi][g * 2 + sub], ah[mi], &bf[g][sub * 2]);
        if (passes >= 2) {
#pragma unroll
            for (int mi = 0; mi < 4; mi++)
#pragma unroll
                for (int g = 0; g < 2; g++)
#pragma unroll
                    for (int sub = 0; sub < 2; sub++)
                        mma16816(acc[mi][g * 2 + sub], al[mi], &bf[g][sub * 2]);
        }
        if (passes == 3) {
#pragma unroll
            for (int g = 0; g < 2; g++)
                ldmx4(bf[g], bb + WL_S + 6144 + offB0 + g * 768);
#pragma unroll
            for (int mi = 0; mi < 4; mi++)
#pragma unroll
                for (int g = 0; g < 2; g++)
#pragma unroll
                    for (int sub = 0; sub < 2; sub++)
                        mma16816(acc[mi][g * 2 + sub], ah[mi], &bf[g][sub * 2]);
        }

        if (++stg == 3) { stg = 0; par ^= 1; }
    }

    // epilogue
    int rbase = m0 + mbase, cbase = n0 + nbase;
#pragma unroll
    for (int mi = 0; mi < 4; mi++)
#pragma unroll
        for (int ni = 0; ni < 4; ni++) {
            int rrow = rbase + mi * 16 + (lane >> 2);
            int col = cbase + ni * 8 + (lane & 3) * 2;
            if (mode == 1) {
                __half2* o0 = (__half2*)(g_qkvh + (size_t)rrow * N + col);
                __half2* o1 = (__half2*)(g_qkvh + (size_t)(rrow + 8) * N + col);
                *o0 = __floats2half2_rn(acc[mi][ni][0], acc[mi][ni][1]);
                *o1 = __floats2half2_rn(acc[mi][ni][2], acc[mi][ni][3]);
            } else {
                float b0 = 0.f, b1 = 0.f;
                if (mode == 2) { b0 = bias[col]; b1 = bias[col + 1]; }
                float* O = (mode == 0) ? g_qkvc : Oext;
                float2 v0 = make_float2(acc[mi][ni][0] + b0, acc[mi][ni][1] + b1);
                float2 v1 = make_float2(acc[mi][ni][2] + b0, acc[mi][ni][3] + b1);
                *(float2*)&O[(size_t)rrow * N + col] = v0;
                *(float2*)&O[(size_t)(rrow + 8) * N + col] = v1;
            }
        }
}

// ---------------- K3: coarse routing attention + top-k (flash-style) ------
#define CA_SMEM (2 * 256 * 48 * 4)
__global__ __launch_bounds__(128) void coarse_attn_kernel()
{
    extern __shared__ float cas[];
    float* Ks = cas;
    float* Vs = cas + 256 * 48;

    int bid = blockIdx.x;
    int half = bid & 1;
    int hd = (bid >> 1) & 7;
    int b = bid >> 4;
    int tid = threadIdx.x;

    const float* base = g_qkvc + (size_t)b * NCn * C3n;

    for (int idx = tid; idx < 3072; idx += 128) {
        int j = idx / 12, d4 = (idx % 12) * 4;
        const float* rp = base + (size_t)j * C3n + Cn + hd * Dh + d4;
        *(float4*)&Ks[j * 48 + d4] = *(const float4*)rp;
        *(float4*)&Vs[j * 48 + d4] = *(const float4*)(rp + Cn);
    }

    int q = half * 128 + tid;
    float qv[48];
    const float* qp = base + (size_t)q * C3n + hd * Dh;
#pragma unroll
    for (int i = 0; i < 12; i++) {
        float4 v = *(const float4*)(qp + i * 4);
        qv[i * 4 + 0] = v.x; qv[i * 4 + 1] = v.y;
        qv[i * 4 + 2] = v.z; qv[i * 4 + 3] = v.w;
    }
    __syncthreads();

    float v0 = -FLT_MAX, v1 = -FLT_MAX, v2 = -FLT_MAX, v3 = -FLT_MAX;
    int i0 = 0, i1 = 0, i2 = 0, i3 = 0;
    for (int j = 0; j < 256; j++) {
        float a0 = 0.f, a1 = 0.f, a2 = 0.f, a3 = 0.f;
        const float* kp = &Ks[j * 48];
#pragma unroll
        for (int d4 = 0; d4 < 12; d4++) {
            float4 kv = *(const float4*)(kp + d4 * 4);
            a0 += qv[d4 * 4 + 0] * kv.x;
            a1 += qv[d4 * 4 + 1] * kv.y;
            a2 += qv[d4 * 4 + 2] * kv.z;
            a3 += qv[d4 * 4 + 3] * kv.w;
        }
        float s = (a0 + a1) + (a2 + a3);
        if (s > v3) {
            if (s > v0)      { v3 = v2; i3 = i2; v2 = v1; i2 = i1; v1 = v0; i1 = i0; v0 = s; i0 = j; }
            else if (s > v1) { v3 = v2; i3 = i2; v2 = v1; i2 = i1; v1 = s; i1 = j; }
            else if (s > v2) { v3 = v2; i3 = i2; v2 = s; i2 = j; }
            else             { v3 = s; i3 = j; }
        }
    }
    int obase = ((b * 8 + hd) * 256 + q) * 4;
    g_topk[obase + 0] = i0; g_topk[obase + 1] = i1;
    g_topk[obase + 2] = i2; g_topk[obase + 3] = i3;

    float mx = v0 * SCALE;

    float oacc[48];
#pragma unroll
    for (int d = 0; d < 48; d++) oacc[d] = 0.f;
    float psum = 0.f;
    for (int j = 0; j < 256; j++) {
        float a0 = 0.f, a1 = 0.f, a2 = 0.f, a3 = 0.f;
        const float* kp = &Ks[j * 48];
#pragma unroll
        for (int d4 = 0; d4 < 12; d4++) {
            float4 kv = *(const float4*)(kp + d4 * 4);
            a0 += qv[d4 * 4 + 0] * kv.x;
            a1 += qv[d4 * 4 + 1] * kv.y;
            a2 += qv[d4 * 4 + 2] * kv.z;
            a3 += qv[d4 * 4 + 3] * kv.w;
        }
        float p = __expf(((a0 + a1) + (a2 + a3)) * SCALE - mx);
        psum += p;
        const float* vp = &Vs[j * 48];
#pragma unroll
        for (int d4 = 0; d4 < 12; d4++) {
            float4 vv = *(const float4*)(vp + d4 * 4);
            oacc[d4 * 4 + 0] += p * vv.x;
            oacc[d4 * 4 + 1] += p * vv.y;
            oacc[d4 * 4 + 2] += p * vv.z;
            oacc[d4 * 4 + 3] += p * vv.w;
        }
    }
    float inv = 1.f / psum;
    float* op = &g_xo[((size_t)(b * NCn + q)) * Cn + hd * Dh];
#pragma unroll
    for (int i = 0; i < 12; i++) {
        float4 v = make_float4(oacc[i * 4] * inv, oacc[i * 4 + 1] * inv,
                               oacc[i * 4 + 2] * inv, oacc[i * 4 + 3] * inv);
        *(float4*)(op + i * 4) = v;
    }
}

// ---------------- K5: fine windowed attention (tensor-core) ---------------
#define SQ_H  0
#define SK_H  768
#define SVT_H 3840
#define SP_H  6912
#define A2_P  68
__global__ __launch_bounds__(128) void fine_attn_kernel()
{
    __shared__ __half hsm[8192];
    __shared__ float A2[16 * A2_P];
    __shared__ int   wins[4];

    int bid = blockIdx.x;
    int n  = bid & 255;
    int hd = (bid >> 8) & 7;
    int b  = bid >> 11;

    int tid = threadIdx.x;
    int lane = tid & 31, wid = tid >> 5;
    int hc = n >> 4, wc = n & 15;
    const __half* base = g_qkvh + (size_t)b * HWn * C3n;

    if (tid < 4) wins[tid] = g_topk[(size_t)bid * 4 + tid];

    for (int idx = tid; idx < 16 * 12; idx += 128) {
        int p = idx / 12, d4 = (idx % 12) * 4;
        int s = (hc * 4 + (p >> 2)) * Wn + wc * 4 + (p & 3);
        uint2 r = *(const uint2*)&base[(size_t)s * C3n + hd * Dh + d4];
        *(uint2*)&hsm[SQ_H + p * 48 + d4] = r;
    }
    __syncthreads();

    for (int idx = tid; idx < 64 * 12; idx += 128) {
        int p = idx / 12, d4 = (idx % 12) * 4;
        int t = p >> 4, pl = p & 15;
        int m = wins[t];
        int s = ((m >> 4) * 4 + (pl >> 2)) * Wn + (m & 15) * 4 + (pl & 3);
        const __half* rw = &base[(size_t)s * C3n + hd * Dh + d4];
        uint2 rk = *(const uint2*)(rw + Cn);
        uint2 rv = *(const uint2*)(rw + 2 * Cn);
        *(uint2*)&hsm[SK_H + p * 48 + d4] = rk;
        __half hv[4];
        *(uint2*)hv = rv;
#pragma unroll
        for (int j = 0; j < 4; j++)
            hsm[SVT_H + (d4 + j) * 64 + p] = hv[j];
    }
    __syncthreads();

    uint32_t sb = smem_u32(hsm);
    int br = (lane & 7) + ((lane >> 4) << 3);
    int bk = ((lane >> 3) & 1) * 8;

    {
        uint32_t offQ = sb + (SQ_H + (lane & 15) * 48 + (lane >> 4) * 8) * 2;
        uint32_t offK = sb + (SK_H + (wid * 16 + br) * 48 + bk) * 2;
        float acc[2][4] = {{0.f, 0.f, 0.f, 0.f}, {0.f, 0.f, 0.f, 0.f}};
#pragma unroll
        for (int kc = 0; kc < 3; kc++) {
            uint32_t aq[4], bkf[4];
            ldmx4(aq,  offQ + kc * 32);
            ldmx4(bkf, offK + kc * 32);
            mma16816(acc[0], aq, &bkf[0]);
            mma16816(acc[1], aq, &bkf[2]);
        }
        int row = lane >> 2, c2 = (lane & 3) * 2;
#pragma unroll
        for (int t = 0; t < 2; t++) {
            int col = wid * 16 + t * 8 + c2;
            A2[row * A2_P + col]           = acc[t][0] * SCALE;
            A2[row * A2_P + col + 1]       = acc[t][1] * SCALE;
            A2[(row + 8) * A2_P + col]     = acc[t][2] * SCALE;
            A2[(row + 8) * A2_P + col + 1] = acc[t][3] * SCALE;
        }
    }
    __syncthreads();

    {
        int row = tid >> 3, j = tid & 7;
        float* ap = &A2[row * A2_P + j * 8];
        float v[8];
        float mx = -FLT_MAX;
#pragma unroll
        for (int i = 0; i < 8; i++) { v[i] = ap[i]; mx = fmaxf(mx, v[i]); }
#pragma unroll
        for (int m = 1; m < 8; m <<= 1)
            mx = fmaxf(mx, __shfl_xor_sync(0xffffffffu, mx, m));
        float sum = 0.f;
#pragma unroll
        for (int i = 0; i < 8; i++) { v[i] = __expf(v[i] - mx); sum += v[i]; }
#pragma unroll
        for (int m = 1; m < 8; m <<= 1)
            sum += __shfl_xor_sync(0xffffffffu, sum, m);
        float inv = 1.f / sum;
#pragma unroll
        for (int i = 0; i < 8; i++) ap[i] = v[i] * inv;
    }
    __syncthreads();

    {
        int row = tid >> 3, c0 = (tid & 7) * 8;
        const float* ap = &A2[row * A2_P + c0];
        __half2* pp = (__half2*)&hsm[SP_H + row * 64 + c0];
        pp[0] = __floats2half2_rn(ap[0], ap[1]);
        pp[1] = __floats2half2_rn(ap[2], ap[3]);
        pp[2] = __floats2half2_rn(ap[4], ap[5]);
        pp[3] = __floats2half2_rn(ap[6], ap[7]);
    }
    __syncthreads();

    if (wid < 3) {
        uint32_t offP = sb + (SP_H + (lane & 15) * 64 + (lane >> 4) * 8) * 2;
        uint32_t offV = sb + (SVT_H + (wid * 16 + br) * 64 + bk) * 2;
        float acc[2][4] = {{0.f, 0.f, 0.f, 0.f}, {0.f, 0.f, 0.f, 0.f}};
#pragma unroll
        for (int kc = 0; kc < 4; kc++) {
            uint32_t ap_[4], bv[4];
            ldmx4(ap_, offP + kc * 32);
            ldmx4(bv,  offV + kc * 32);
            mma16816(acc[0], ap_, &bv[0]);
            mma16816(acc[1], ap_, &bv[2]);
        }
        int row = lane >> 2, c2 = (lane & 3) * 2;
#pragma unroll
        for (int t = 0; t < 2; t++) {
            int dd = wid * 16 + t * 8 + c2;
#pragma unroll
            for (int rh = 0; rh < 2; rh++) {
                int p = row + rh * 8;
                int yy = hc * 4 + (p >> 2), xx = wc * 4 + (p & 3);
                __half2 hv = __floats2half2_rn(acc[t][rh * 2], acc[t][rh * 2 + 1]);
                *(__half2*)&g_yo[(((size_t)(b * Hn + yy)) * Wn + xx) * Cn + hd * Dh + dd] = hv;
            }
        }
    }
}

// ---------------- K6: upsample(xo) -> dwconv3x3(dwx) -> mix with yo -------
__global__ __launch_bounds__(384) void dwmix_kernel(
    const float* __restrict__ dwxw, const float* __restrict__ dwxb)
{
    __shared__ float wsh[Cn * 9];
    int tid = threadIdx.x;
    for (int i = tid; i < Cn * 9; i += 384) wsh[i] = dwxw[i];
    __syncthreads();

    int b  = blockIdx.x >> 6;
    int yy = blockIdx.x & 63;
    int c  = tid;
    float w[9];
#pragma unroll
    for (int i = 0; i < 9; i++) w[i] = wsh[c * 9 + i];
    float bias = dwxb[c];

    const float* xob = g_xo + (size_t)b * NCn * Cn + c;
    bool up = yy > 0, dn = yy < 63;
    int ru = (yy - 1) >> 2, rm = yy >> 2, rd = (yy + 1) >> 2;

    float3 cm = make_float3(0.f, 0.f, 0.f), cc, cp;
    cc.x = up ? xob[(size_t)(ru * 16) * Cn] : 0.f;
    cc.y = xob[(size_t)(rm * 16) * Cn];
    cc.z = dn ? xob[(size_t)(rd * 16) * Cn] : 0.f;

    size_t pix0 = ((size_t)(b * Hn + yy)) * Wn;
    for (int xx = 0; xx < 64; xx++) {
        if (xx < 63) {
            int xc4 = (xx + 1) >> 2;
            cp.x = up ? xob[(size_t)(ru * 16 + xc4) * Cn] : 0.f;
            cp.y = xob[(size_t)(rm * 16 + xc4) * Cn];
            cp.z = dn ? xob[(size_t)(rd * 16 + xc4) * Cn] : 0.f;
        } else {
            cp = make_float3(0.f, 0.f, 0.f);
        }
        float acc = bias
            + w[0] * cm.x + w[1] * cc.x + w[2] * cp.x
            + w[3] * cm.y + w[4] * cc.y + w[5] * cp.y
            + w[6] * cm.z + w[7] * cc.z + w[8] * cp.z;
        size_t pix = pix0 + xx;
        float yv = __half2float(g_yo[pix * Cn + c]);
        g_z[pix * Cn + c] = __float2half(0.5f * acc + 0.5f * yv);
        cm = cc; cc = cp;
    }
}

// ---------------- K7: dwconv3x3(dw) on z -> fp16 hi/lo planes (tiled) -----
__global__ __launch_bounds__(384) void dwconv2_kernel(
    const float* __restrict__ dww, const float* __restrict__ dwb)
{
    __shared__ float wsh[Cn * 9];
    int tid = threadIdx.x;
    for (int i = tid; i < Cn * 9; i += 384) wsh[i] = dww[i];
    __syncthreads();

    int b  = blockIdx.x >> 6;
    int yy = blockIdx.x & 63;
    int c  = tid;
    float w[9];
#pragma unroll
    for (int i = 0; i < 9; i++) w[i] = wsh[c * 9 + i];
    float bias = dwb[c];

    const __half* zb = g_z + (size_t)b * HWn * Cn + c;
    bool up = yy > 0, dn = yy < 63;
    size_t rowm = (size_t)yy * Wn;

    float3 cm = make_float3(0.f, 0.f, 0.f), cc, cp;
    cc.x = up ? __half2float(zb[(rowm - Wn) * Cn]) : 0.f;
    cc.y = __half2float(zb[rowm * Cn]);
    cc.z = dn ? __half2float(zb[(rowm + Wn) * Cn]) : 0.f;

    int mrow0 = b * HWn + yy * Wn;
    for (int xx = 0; xx < 64; xx++) {
        if (xx < 63) {
            size_t bcol = rowm + xx + 1;
            cp.x = up ? __half2float(zb[(bcol - Wn) * Cn]) : 0.f;
            cp.y = __half2float(zb[bcol * Cn]);
            cp.z = dn ? __half2float(zb[(bcol + Wn) * Cn]) : 0.f;
        } else {
            cp = make_float3(0.f, 0.f, 0.f);
        }
        float acc = bias
            + w[0] * cm.x + w[1] * cc.x + w[2] * cp.x
            + w[3] * cm.y + w[4] * cc.y + w[5] * cp.y
            + w[6] * cm.z + w[7] * cc.z + w[8] * cp.z;
        __half h = __float2half(acc);
        __half l = __float2half(acc - __half2float(h));
        size_t o = a_off(mrow0 + xx, c);
        g_abf[o] = h;
        g_abf[APL + o] = l;
        cm = cc; cc = cp;
    }
}

// ---------------- launch ----------------
extern "C" void kernel_launch(void* const* d_in, const int* in_sizes, int n_in,
                              void* d_out, int out_size)
{
    const float* x     = (const float*)d_in[0];
    const float* qkv_w = (const float*)d_in[1];
    const float* dwx_w = (const float*)d_in[2];
    const float* dwx_b = (const float*)d_in[3];
    const float* dw_w  = (const float*)d_in[4];
    const float* dw_b  = (const float*)d_in[5];
    const float* pw_w  = (const float*)d_in[6];
    const float* pw_b  = (const float*)d_in[7];
    float* out = (float*)d_out;

    cudaFuncSetAttribute(gemm_mma, cudaFuncAttributeMaxDynamicSharedMemorySize,
                         GSMEM);
    cudaFuncSetAttribute(coarse_attn_kernel,
                         cudaFuncAttributeMaxDynamicSharedMemorySize, CA_SMEM);

    // weight conversions (tiny)
    convw_kernel<<<(C3n * Cn + 255) / 256, 256>>>(qkv_w, C3n * Cn, 0);
    convw_kernel<<<(Cn * Cn + 255) / 256, 256>>>(pw_w, Cn * Cn, 1);

    // 1) coarse pooling
    pool_kernel<<<Bn * NCn, Cn>>>(x);

    // 2) coarse QKV (3-pass, exact top-k)
    gemm_mma<<<dim3(C3n / 128, (Bn * NCn) / 256), 512, GSMEM>>>(
        nullptr, nullptr, C3n, 0, 3);

    // 3) coarse routing attention + top-k
    coarse_attn_kernel<<<Bn * NHd * 2, 128, CA_SMEM>>>();

    // 4) fine QKV (1-pass fp16, fp16 output)
    convA_kernel<<<(Bn * HWn * 48 + 255) / 256, 256>>>(x, Bn * HWn * 48);
    gemm_mma<<<dim3(C3n / 128, (Bn * HWn) / 256), 512, GSMEM>>>(
        nullptr, nullptr, C3n, 1, 1);

    // 5) fine windowed attention (tensor-core)
    fine_attn_kernel<<<Bn * NHd * NCn, 128>>>();

    // 6) upsample+dwconv(dwx)+mix
    dwmix_kernel<<<Bn * Hn, Cn>>>(dwx_w, dwx_b);

    // 7) dwconv(dw) -> fp16 planes
    dwconv2_kernel<<<Bn * Hn, Cn>>>(dw_w, dw_b);

    // 8) pointwise projection (+bias, 2-pass)
    gemm_mma<<<dim3(Cn / 128, (Bn * HWn) / 256), 512, GSMEM>>>(
        pw_b, out, Cn, 2, 2);
}

// round 17
// speedup vs baseline: 1.9921x; 1.0730x over previous
#include <cuda_runtime.h>
#include <cuda_fp16.h>
#include <float.h>
#include <stdint.h>

// Problem constants
#define Bn   8
#define Hn   64
#define Wn   64
#define Cn   384
#define NHd  8
#define Dh   48
#define NCn  256
#define HWn  4096
#define C3n  1152
#define SCALE 0.14433756729740643f

// ---- tiled operand layout: [tile][kchunk(24)][rows][pitch 24 halves] ----
#define TP     24
#define ACHH   (256 * TP)
#define WCHH   (128 * TP)
#define ATILEH (24 * ACHH)
#define WTILEH (24 * WCHH)
#define APL    ((size_t)128 * ATILEH)

// ---------------- scratch (device globals; no allocation) ----------------
__device__ float  g_qkvc[Bn * NCn * C3n];
__device__ int    g_topk[Bn * NHd * NCn * 4];
__device__ float  g_xo  [Bn * NCn * Cn];
__device__ __half g_qkvh[(size_t)Bn * HWn * C3n];   // fine QKV (fp16)
__device__ __half g_yo  [(size_t)Bn * HWn * Cn];    // fine attn out (fp16)
__device__ __half g_z   [(size_t)Bn * HWn * Cn];    // mixed (fp16)
__device__ __half g_abf[2 * APL];
__device__ __half g_wqh[9 * WTILEH];
__device__ __half g_wql[9 * WTILEH];
__device__ __half g_wph[3 * WTILEH];
__device__ __half g_wpl[3 * WTILEH];

__device__ __forceinline__ size_t a_off(int m, int k) {
    return (size_t)(m >> 8) * ATILEH + (size_t)(k >> 4) * ACHH
         + (m & 255) * TP + (k & 15);
}
__device__ __forceinline__ size_t w_off(int n, int k) {
    return (size_t)(n >> 7) * WTILEH + (size_t)(k >> 4) * WCHH
         + (n & 127) * TP + (k & 15);
}

// ---------------- helpers ----------------
__device__ __forceinline__ uint32_t smem_u32(const void* p) {
    uint32_t a;
    asm("{ .reg .u64 t; cvta.to.shared.u64 t, %1; cvt.u32.u64 %0, t; }"
        : "=r"(a) : "l"(p));
    return a;
}
__device__ __forceinline__ void ldmx4(uint32_t* r, uint32_t addr) {
    asm volatile("ldmatrix.sync.aligned.m8n8.x4.shared.b16 {%0,%1,%2,%3}, [%4];"
        : "=r"(r[0]), "=r"(r[1]), "=r"(r[2]), "=r"(r[3]) : "r"(addr));
}
__device__ __forceinline__ void mma16816(float* d, const uint32_t* a, const uint32_t* b) {
    asm volatile(
        "mma.sync.aligned.m16n8k16.row.col.f32.f16.f16.f32 "
        "{%0,%1,%2,%3}, {%4,%5,%6,%7}, {%8,%9}, {%0,%1,%2,%3};"
        : "+f"(d[0]), "+f"(d[1]), "+f"(d[2]), "+f"(d[3])
        : "r"(a[0]), "r"(a[1]), "r"(a[2]), "r"(a[3]), "r"(b[0]), "r"(b[1]));
}
__device__ __forceinline__ uint32_t pack_hf2(float x, float y) {
    unsigned short hx = __half_as_ushort(__float2half(x));
    unsigned short hy = __half_as_ushort(__float2half(y));
    return (uint32_t)hx | ((uint32_t)hy << 16);
}
__device__ __forceinline__ void mbar_init(uint32_t a, uint32_t cnt) {
    asm volatile("mbarrier.init.shared.b64 [%0], %1;" :: "r"(a), "r"(cnt) : "memory");
}
__device__ __forceinline__ void mbar_expect(uint32_t a, uint32_t bytes) {
    asm volatile("mbarrier.arrive.expect_tx.shared.b64 _, [%0], %1;"
                 :: "r"(a), "r"(bytes) : "memory");
}
__device__ __forceinline__ void mbar_wait(uint32_t a, uint32_t parity) {
    asm volatile(
        "{\n\t.reg .pred P;\n\t"
        "WL%=:\n\t"
        "mbarrier.try_wait.parity.acquire.cta.shared::cta.b64 P, [%0], %1, 0x989680;\n\t"
        "@P bra.uni WD%=;\n\t"
        "bra.uni WL%=;\n\t"
        "WD%=:\n\t}"
        :: "r"(a), "r"(parity) : "memory");
}
__device__ __forceinline__ void bulkcp(uint32_t sdst, const void* gsrc,
                                       uint32_t bytes, uint32_t mbar) {
    asm volatile(
        "cp.async.bulk.shared::cta.global.mbarrier::complete_tx::bytes "
        "[%0], [%1], %2, [%3];"
        :: "r"(sdst), "l"(gsrc), "r"(bytes), "r"(mbar) : "memory");
}

// ---------------- K1: 4x4 average pool -> fp16 hi/lo planes (tiled) -------
__global__ __launch_bounds__(384) void pool_kernel(const float* __restrict__ x)
{
    int blk = blockIdx.x;
    int n = blk & 255, b = blk >> 8;
    int hc = n >> 4, wc = n & 15;
    int c = threadIdx.x;
    float s = 0.f;
#pragma unroll
    for (int i = 0; i < 4; i++)
#pragma unroll
        for (int j = 0; j < 4; j++)
            s += x[(((size_t)(b * Hn + hc * 4 + i)) * Wn + wc * 4 + j) * Cn + c];
    s *= 0.0625f;
    __half h = __float2half(s);
    __half l = __float2half(s - __half2float(h));
    size_t o = a_off(b * NCn + n, c);
    g_abf[o] = h;
    g_abf[APL + o] = l;
}

// ---------------- weight fp16 hi/lo conversion (tiled) ----------------
__global__ __launch_bounds__(256) void convw_kernel(
    const float* __restrict__ w, int total, int mode)
{
    int i = blockIdx.x * 256 + threadIdx.x;
    if (i >= total) return;
    float v = w[i];
    __half h = __float2half(v);
    __half l = __float2half(v - __half2float(h));
    int n = i / 384, k = i % 384;
    size_t o = w_off(n, k);
    if (mode == 0) { g_wqh[o] = h; g_wql[o] = l; }
    else           { g_wph[o] = h; g_wpl[o] = l; }
}

// ---------------- A conversion: x (f32) -> fp16 hi plane only (tiled) -----
__global__ __launch_bounds__(256) void convA_kernel(
    const float* __restrict__ src, int n8)
{
    int i = blockIdx.x * 256 + threadIdx.x;
    if (i >= n8) return;
    float4 v0 = ((const float4*)src)[i * 2];
    float4 v1 = ((const float4*)src)[i * 2 + 1];
    uint4 H;
    H.x = pack_hf2(v0.x, v0.y); H.y = pack_hf2(v0.z, v0.w);
    H.z = pack_hf2(v1.x, v1.y); H.w = pack_hf2(v1.z, v1.w);
    int m = i / 48, k0 = (i % 48) * 8;
    size_t o = a_off(m, k0);
    *(uint4*)(g_abf + o) = H;
}

// ---------------- tensor-core GEMM ----------------------------------------
// passes==3: Ah*Wh + Al*Wh + Ah*Wl   passes==2: Ah*Wh + Al*Wh
// passes==1: Ah*Wh
// mode 0: O=g_qkvc (f32)  mode 1: O=g_qkvh (f16)  mode 2: O=out (+bias)
#define AH_S 0
#define AL_S 24576
#define WH_S 49152
#define WL_S 61440
#define STG  73728
#define GSMEM (3 * STG + 64)

__global__ __launch_bounds__(512, 1) void gemm_mma(
    const float* __restrict__ bias, float* __restrict__ Oext, int N, int mode,
    int passes)
{
    extern __shared__ __half sm[];

    const __half* WHp = (mode == 2) ? g_wph : g_wqh;
    const __half* WLp = (mode == 2) ? g_wpl : g_wql;

    int tid = threadIdx.x;
    int m0 = blockIdx.y * 256, n0 = blockIdx.x * 128;

    const __half* aH = g_abf + (size_t)(m0 >> 8) * ATILEH;
    const __half* aL = aH + APL;
    const __half* wH = WHp + (size_t)(n0 >> 7) * WTILEH;
    const __half* wL = WLp + (size_t)(n0 >> 7) * WTILEH;

    uint32_t sbase = smem_u32(sm);
    uint32_t mb = sbase + 3 * STG;

    uint32_t stgbytes = (passes == 3) ? STG
                      : (passes == 2) ? (STG - 12288) : 36864u;

    if (tid == 0) {
#pragma unroll
        for (int s = 0; s < 3; s++) mbar_init(mb + s * 8, 1);
    }
    __syncthreads();

    if (tid == 0) {
#pragma unroll
        for (int s = 0; s < 2; s++) {
            uint32_t sb = sbase + s * STG;
            uint32_t mbs = mb + s * 8;
            mbar_expect(mbs, stgbytes);
            bulkcp(sb + AH_S, aH + s * 2 * ACHH, 24576, mbs);
            if (passes >= 2)
                bulkcp(sb + AL_S, aL + s * 2 * ACHH, 24576, mbs);
            bulkcp(sb + WH_S, wH + s * 2 * WCHH, 12288, mbs);
            if (passes == 3)
                bulkcp(sb + WL_S, wL + s * 2 * WCHH, 12288, mbs);
        }
    }

    int lane = tid & 31;
    int wid = tid >> 5;
    int mbase = (wid & 3) * 64;
    int nbase = (wid >> 2) * 32;

    int ar = lane & 15, ak = (lane >> 4) * 8;
    uint32_t offA0 = ((mbase + ar) * TP + ak) * 2;
    int br = (lane & 7) + ((lane >> 4) << 3), bk = ((lane >> 3) & 1) * 8;
    uint32_t offB0 = ((nbase + br) * TP + bk) * 2;

    float acc[4][4][4];
#pragma unroll
    for (int i = 0; i < 4; i++)
#pragma unroll
        for (int j = 0; j < 4; j++)
#pragma unroll
            for (int k = 0; k < 4; k++) acc[i][j][k] = 0.f;

    int stg = 0, par = 0;
    for (int pc = 0; pc < 12; pc++) {
        mbar_wait(mb + stg * 8, par);
        uint32_t bb = sbase + stg * STG;

        uint32_t ah[4][4], al[4][4], bf[2][4];
#pragma unroll
        for (int g = 0; g < 4; g++)
            ldmx4(ah[g], bb + AH_S + offA0 + g * 768);
        if (passes >= 2) {
#pragma unroll
            for (int g = 0; g < 4; g++)
                ldmx4(al[g], bb + AL_S + offA0 + g * 768);
        }
#pragma unroll
        for (int g = 0; g < 2; g++)
            ldmx4(bf[g], bb + WH_S + offB0 + g * 768);

        __syncthreads();

        if (tid == 0 && pc < 10) {
            int s = (pc + 2) % 3;
            uint32_t sb = sbase + s * STG;
            uint32_t mbs = mb + s * 8;
            int ck = pc + 2;
            mbar_expect(mbs, stgbytes);
            bulkcp(sb + AH_S, aH + ck * 2 * ACHH, 24576, mbs);
            if (passes >= 2)
                bulkcp(sb + AL_S, aL + ck * 2 * ACHH, 24576, mbs);
            bulkcp(sb + WH_S, wH + ck * 2 * WCHH, 12288, mbs);
            if (passes == 3)
                bulkcp(sb + WL_S, wL + ck * 2 * WCHH, 12288, mbs);
        }

        // ---- sub 0 math ----
#pragma unroll
        for (int mi = 0; mi < 4; mi++)
#pragma unroll
            for (int g = 0; g < 2; g++)
#pragma unroll
                for (int sub = 0; sub < 2; sub++)
                    mma16816(acc[mi][g * 2 + sub], ah[mi], &bf[g][sub * 2]);
        if (passes >= 2) {
#pragma unroll
            for (int mi = 0; mi < 4; mi++)
#pragma unroll
                for (int g = 0; g < 2; g++)
#pragma unroll
                    for (int sub = 0; sub < 2; sub++)
                        mma16816(acc[mi][g * 2 + sub], al[mi], &bf[g][sub * 2]);
        }
        if (passes == 3) {
#pragma unroll
            for (int g = 0; g < 2; g++)
                ldmx4(bf[g], bb + WL_S + offB0 + g * 768);
#pragma unroll
            for (int mi = 0; mi < 4; mi++)
#pragma unroll
                for (int g = 0; g < 2; g++)
#pragma unroll
                    for (int sub = 0; sub < 2; sub++)
                        mma16816(acc[mi][g * 2 + sub], ah[mi], &bf[g][sub * 2]);
        }

        // ---- sub 1 ----
#pragma unroll
        for (int g = 0; g < 4; g++)
            ldmx4(ah[g], bb + AH_S + 12288 + offA0 + g * 768);
        if (passes >= 2) {
#pragma unroll
            for (int g = 0; g < 4; g++)
                ldmx4(al[g], bb + AL_S + 12288 + offA0 + g * 768);
        }
#pragma unroll
        for (int g = 0; g < 2; g++)
            ldmx4(bf[g], bb + WH_S + 6144 + offB0 + g * 768);
#pragma unroll
        for (int mi = 0; mi < 4; mi++)
#pragma unroll
            for (int g = 0; g < 2; g++)
#pragma unroll
                for (int sub = 0; sub < 2; sub++)
                    mma16816(acc[mi][g * 2 + sub], ah[mi], &bf[g][sub * 2]);
        if (passes >= 2) {
#pragma unroll
            for (int mi = 0; mi < 4; mi++)
#pragma unroll
                for (int g = 0; g < 2; g++)
#pragma unroll
                    for (int sub = 0; sub < 2; sub++)
                        mma16816(acc[mi][g * 2 + sub], al[mi], &bf[g][sub * 2]);
        }
        if (passes == 3) {
#pragma unroll
            for (int g = 0; g < 2; g++)
                ldmx4(bf[g], bb + WL_S + 6144 + offB0 + g * 768);
#pragma unroll
            for (int mi = 0; mi < 4; mi++)
#pragma unroll
                for (int g = 0; g < 2; g++)
#pragma unroll
                    for (int sub = 0; sub < 2; sub++)
                        mma16816(acc[mi][g * 2 + sub], ah[mi], &bf[g][sub * 2]);
        }

        if (++stg == 3) { stg = 0; par ^= 1; }
    }

    // epilogue
    int rbase = m0 + mbase, cbase = n0 + nbase;
#pragma unroll
    for (int mi = 0; mi < 4; mi++)
#pragma unroll
        for (int ni = 0; ni < 4; ni++) {
            int rrow = rbase + mi * 16 + (lane >> 2);
            int col = cbase + ni * 8 + (lane & 3) * 2;
            if (mode == 1) {
                __half2* o0 = (__half2*)(g_qkvh + (size_t)rrow * N + col);
                __half2* o1 = (__half2*)(g_qkvh + (size_t)(rrow + 8) * N + col);
                *o0 = __floats2half2_rn(acc[mi][ni][0], acc[mi][ni][1]);
                *o1 = __floats2half2_rn(acc[mi][ni][2], acc[mi][ni][3]);
            } else {
                float b0 = 0.f, b1 = 0.f;
                if (mode == 2) { b0 = bias[col]; b1 = bias[col + 1]; }
                float* O = (mode == 0) ? g_qkvc : Oext;
                float2 v0 = make_float2(acc[mi][ni][0] + b0, acc[mi][ni][1] + b1);
                float2 v1 = make_float2(acc[mi][ni][2] + b0, acc[mi][ni][3] + b1);
                *(float2*)&O[(size_t)rrow * N + col] = v0;
                *(float2*)&O[(size_t)(rrow + 8) * N + col] = v1;
            }
        }
}

// ---------------- K3: coarse routing attention + top-k (flash-style) ------
#define CA_SMEM (2 * 256 * 48 * 4)
__global__ __launch_bounds__(128) void coarse_attn_kernel()
{
    extern __shared__ float cas[];
    float* Ks = cas;
    float* Vs = cas + 256 * 48;

    int bid = blockIdx.x;
    int half = bid & 1;
    int hd = (bid >> 1) & 7;
    int b = bid >> 4;
    int tid = threadIdx.x;

    const float* base = g_qkvc + (size_t)b * NCn * C3n;

    for (int idx = tid; idx < 3072; idx += 128) {
        int j = idx / 12, d4 = (idx % 12) * 4;
        const float* rp = base + (size_t)j * C3n + Cn + hd * Dh + d4;
        *(float4*)&Ks[j * 48 + d4] = *(const float4*)rp;
        *(float4*)&Vs[j * 48 + d4] = *(const float4*)(rp + Cn);
    }

    int q = half * 128 + tid;
    float qv[48];
    const float* qp = base + (size_t)q * C3n + hd * Dh;
#pragma unroll
    for (int i = 0; i < 12; i++) {
        float4 v = *(const float4*)(qp + i * 4);
        qv[i * 4 + 0] = v.x; qv[i * 4 + 1] = v.y;
        qv[i * 4 + 2] = v.z; qv[i * 4 + 3] = v.w;
    }
    __syncthreads();

    float v0 = -FLT_MAX, v1 = -FLT_MAX, v2 = -FLT_MAX, v3 = -FLT_MAX;
    int i0 = 0, i1 = 0, i2 = 0, i3 = 0;
    for (int j = 0; j < 256; j++) {
        float a0 = 0.f, a1 = 0.f, a2 = 0.f, a3 = 0.f;
        const float* kp = &Ks[j * 48];
#pragma unroll
        for (int d4 = 0; d4 < 12; d4++) {
            float4 kv = *(const float4*)(kp + d4 * 4);
            a0 += qv[d4 * 4 + 0] * kv.x;
            a1 += qv[d4 * 4 + 1] * kv.y;
            a2 += qv[d4 * 4 + 2] * kv.z;
            a3 += qv[d4 * 4 + 3] * kv.w;
        }
        float s = (a0 + a1) + (a2 + a3);
        if (s > v3) {
            if (s > v0)      { v3 = v2; i3 = i2; v2 = v1; i2 = i1; v1 = v0; i1 = i0; v0 = s; i0 = j; }
            else if (s > v1) { v3 = v2; i3 = i2; v2 = v1; i2 = i1; v1 = s; i1 = j; }
            else if (s > v2) { v3 = v2; i3 = i2; v2 = s; i2 = j; }
            else             { v3 = s; i3 = j; }
        }
    }
    int obase = ((b * 8 + hd) * 256 + q) * 4;
    g_topk[obase + 0] = i0; g_topk[obase + 1] = i1;
    g_topk[obase + 2] = i2; g_topk[obase + 3] = i3;

    float mx = v0 * SCALE;

    float oacc[48];
#pragma unroll
    for (int d = 0; d < 48; d++) oacc[d] = 0.f;
    float psum = 0.f;
    for (int j = 0; j < 256; j++) {
        float a0 = 0.f, a1 = 0.f, a2 = 0.f, a3 = 0.f;
        const float* kp = &Ks[j * 48];
#pragma unroll
        for (int d4 = 0; d4 < 12; d4++) {
            float4 kv = *(const float4*)(kp + d4 * 4);
            a0 += qv[d4 * 4 + 0] * kv.x;
            a1 += qv[d4 * 4 + 1] * kv.y;
            a2 += qv[d4 * 4 + 2] * kv.z;
            a3 += qv[d4 * 4 + 3] * kv.w;
        }
        float p = __expf(((a0 + a1) + (a2 + a3)) * SCALE - mx);
        psum += p;
        const float* vp = &Vs[j * 48];
#pragma unroll
        for (int d4 = 0; d4 < 12; d4++) {
            float4 vv = *(const float4*)(vp + d4 * 4);
            oacc[d4 * 4 + 0] += p * vv.x;
            oacc[d4 * 4 + 1] += p * vv.y;
            oacc[d4 * 4 + 2] += p * vv.z;
            oacc[d4 * 4 + 3] += p * vv.w;
        }
    }
    float inv = 1.f / psum;
    float* op = &g_xo[((size_t)(b * NCn + q)) * Cn + hd * Dh];
#pragma unroll
    for (int i = 0; i < 12; i++) {
        float4 v = make_float4(oacc[i * 4] * inv, oacc[i * 4 + 1] * inv,
                               oacc[i * 4 + 2] * inv, oacc[i * 4 + 3] * inv);
        *(float4*)(op + i * 4) = v;
    }
}

// ---------------- K5: fine windowed attention (tensor-core) ---------------
#define SQ_H  0
#define SK_H  768
#define SVT_H 3840
#define SP_H  6912
#define A2_P  68
__global__ __launch_bounds__(128) void fine_attn_kernel()
{
    __shared__ __half hsm[8192];
    __shared__ float A2[16 * A2_P];
    __shared__ int   wins[4];

    int bid = blockIdx.x;
    int n  = bid & 255;
    int hd = (bid >> 8) & 7;
    int b  = bid >> 11;

    int tid = threadIdx.x;
    int lane = tid & 31, wid = tid >> 5;
    int hc = n >> 4, wc = n & 15;
    const __half* base = g_qkvh + (size_t)b * HWn * C3n;

    if (tid < 4) wins[tid] = g_topk[(size_t)bid * 4 + tid];

    for (int idx = tid; idx < 16 * 12; idx += 128) {
        int p = idx / 12, d4 = (idx % 12) * 4;
        int s = (hc * 4 + (p >> 2)) * Wn + wc * 4 + (p & 3);
        uint2 r = *(const uint2*)&base[(size_t)s * C3n + hd * Dh + d4];
        *(uint2*)&hsm[SQ_H + p * 48 + d4] = r;
    }
    __syncthreads();

    for (int idx = tid; idx < 64 * 12; idx += 128) {
        int p = idx / 12, d4 = (idx % 12) * 4;
        int t = p >> 4, pl = p & 15;
        int m = wins[t];
        int s = ((m >> 4) * 4 + (pl >> 2)) * Wn + (m & 15) * 4 + (pl & 3);
        const __half* rw = &base[(size_t)s * C3n + hd * Dh + d4];
        uint2 rk = *(const uint2*)(rw + Cn);
        uint2 rv = *(const uint2*)(rw + 2 * Cn);
        *(uint2*)&hsm[SK_H + p * 48 + d4] = rk;
        __half hv[4];
        *(uint2*)hv = rv;
#pragma unroll
        for (int j = 0; j < 4; j++)
            hsm[SVT_H + (d4 + j) * 64 + p] = hv[j];
    }
    __syncthreads();

    uint32_t sb = smem_u32(hsm);
    int br = (lane & 7) + ((lane >> 4) << 3);
    int bk = ((lane >> 3) & 1) * 8;

    {
        uint32_t offQ = sb + (SQ_H + (lane & 15) * 48 + (lane >> 4) * 8) * 2;
        uint32_t offK = sb + (SK_H + (wid * 16 + br) * 48 + bk) * 2;
        float acc[2][4] = {{0.f, 0.f, 0.f, 0.f}, {0.f, 0.f, 0.f, 0.f}};
#pragma unroll
        for (int kc = 0; kc < 3; kc++) {
            uint32_t aq[4], bkf[4];
            ldmx4(aq,  offQ + kc * 32);
            ldmx4(bkf, offK + kc * 32);
            mma16816(acc[0], aq, &bkf[0]);
            mma16816(acc[1], aq, &bkf[2]);
        }
        int row = lane >> 2, c2 = (lane & 3) * 2;
#pragma unroll
        for (int t = 0; t < 2; t++) {
            int col = wid * 16 + t * 8 + c2;
            A2[row * A2_P + col]           = acc[t][0] * SCALE;
            A2[row * A2_P + col + 1]       = acc[t][1] * SCALE;
            A2[(row + 8) * A2_P + col]     = acc[t][2] * SCALE;
            A2[(row + 8) * A2_P + col + 1] = acc[t][3] * SCALE;
        }
    }
    __syncthreads();

    {
        int row = tid >> 3, j = tid & 7;
        float* ap = &A2[row * A2_P + j * 8];
        float v[8];
        float mx = -FLT_MAX;
#pragma unroll
        for (int i = 0; i < 8; i++) { v[i] = ap[i]; mx = fmaxf(mx, v[i]); }
#pragma unroll
        for (int m = 1; m < 8; m <<= 1)
            mx = fmaxf(mx, __shfl_xor_sync(0xffffffffu, mx, m));
        float sum = 0.f;
#pragma unroll
        for (int i = 0; i < 8; i++) { v[i] = __expf(v[i] - mx); sum += v[i]; }
#pragma unroll
        for (int m = 1; m < 8; m <<= 1)
            sum += __shfl_xor_sync(0xffffffffu, sum, m);
        float inv = 1.f / sum;
#pragma unroll
        for (int i = 0; i < 8; i++) ap[i] = v[i] * inv;
    }
    __syncthreads();

    {
        int row = tid >> 3, c0 = (tid & 7) * 8;
        const float* ap = &A2[row * A2_P + c0];
        __half2* pp = (__half2*)&hsm[SP_H + row * 64 + c0];
        pp[0] = __floats2half2_rn(ap[0], ap[1]);
        pp[1] = __floats2half2_rn(ap[2], ap[3]);
        pp[2] = __floats2half2_rn(ap[4], ap[5]);
        pp[3] = __floats2half2_rn(ap[6], ap[7]);
    }
    __syncthreads();

    if (wid < 3) {
        uint32_t offP = sb + (SP_H + (lane & 15) * 64 + (lane >> 4) * 8) * 2;
        uint32_t offV = sb + (SVT_H + (wid * 16 + br) * 64 + bk) * 2;
        float acc[2][4] = {{0.f, 0.f, 0.f, 0.f}, {0.f, 0.f, 0.f, 0.f}};
#pragma unroll
        for (int kc = 0; kc < 4; kc++) {
            uint32_t ap_[4], bv[4];
            ldmx4(ap_, offP + kc * 32);
            ldmx4(bv,  offV + kc * 32);
            mma16816(acc[0], ap_, &bv[0]);
            mma16816(acc[1], ap_, &bv[2]);
        }
        int row = lane >> 2, c2 = (lane & 3) * 2;
#pragma unroll
        for (int t = 0; t < 2; t++) {
            int dd = wid * 16 + t * 8 + c2;
#pragma unroll
            for (int rh = 0; rh < 2; rh++) {
                int p = row + rh * 8;
                int yy = hc * 4 + (p >> 2), xx = wc * 4 + (p & 3);
                __half2 hv = __floats2half2_rn(acc[t][rh * 2], acc[t][rh * 2 + 1]);
                *(__half2*)&g_yo[(((size_t)(b * Hn + yy)) * Wn + xx) * Cn + hd * Dh + dd] = hv;
            }
        }
    }
}

// ---------------- K6: upsample(xo) -> dwconv3x3(dwx) -> mix with yo -------
__global__ __launch_bounds__(384) void dwmix_kernel(
    const float* __restrict__ dwxw, const float* __restrict__ dwxb)
{
    __shared__ float wsh[Cn * 9];
    int tid = threadIdx.x;
    for (int i = tid; i < Cn * 9; i += 384) wsh[i] = dwxw[i];
    __syncthreads();

    int b  = blockIdx.x >> 6;
    int yy = blockIdx.x & 63;
    int c  = tid;
    float w[9];
#pragma unroll
    for (int i = 0; i < 9; i++) w[i] = wsh[c * 9 + i];
    float bias = dwxb[c];

    const float* xob = g_xo + (size_t)b * NCn * Cn + c;
    bool up = yy > 0, dn = yy < 63;
    int ru = (yy - 1) >> 2, rm = yy >> 2, rd = (yy + 1) >> 2;

    float3 cm = make_float3(0.f, 0.f, 0.f), cc, cp;
    cc.x = up ? xob[(size_t)(ru * 16) * Cn] : 0.f;
    cc.y = xob[(size_t)(rm * 16) * Cn];
    cc.z = dn ? xob[(size_t)(rd * 16) * Cn] : 0.f;

    size_t pix0 = ((size_t)(b * Hn + yy)) * Wn;
    for (int xx = 0; xx < 64; xx++) {
        if (xx < 63) {
            int xc4 = (xx + 1) >> 2;
            cp.x = up ? xob[(size_t)(ru * 16 + xc4) * Cn] : 0.f;
            cp.y = xob[(size_t)(rm * 16 + xc4) * Cn];
            cp.z = dn ? xob[(size_t)(rd * 16 + xc4) * Cn] : 0.f;
        } else {
            cp = make_float3(0.f, 0.f, 0.f);
        }
        float acc = bias
            + w[0] * cm.x + w[1] * cc.x + w[2] * cp.x
            + w[3] * cm.y + w[4] * cc.y + w[5] * cp.y
            + w[6] * cm.z + w[7] * cc.z + w[8] * cp.z;
        size_t pix = pix0 + xx;
        float yv = __half2float(g_yo[pix * Cn + c]);
        g_z[pix * Cn + c] = __float2half(0.5f * acc + 0.5f * yv);
        cm = cc; cc = cp;
    }
}

// ---------------- K7: dwconv3x3(dw) on z -> fp16 hi plane (tiled) ---------
__global__ __launch_bounds__(384) void dwconv2_kernel(
    const float* __restrict__ dww, const float* __restrict__ dwb)
{
    __shared__ float wsh[Cn * 9];
    int tid = threadIdx.x;
    for (int i = tid; i < Cn * 9; i += 384) wsh[i] = dww[i];
    __syncthreads();

    int b  = blockIdx.x >> 6;
    int yy = blockIdx.x & 63;
    int c  = tid;
    float w[9];
#pragma unroll
    for (int i = 0; i < 9; i++) w[i] = wsh[c * 9 + i];
    float bias = dwb[c];

    const __half* zb = g_z + (size_t)b * HWn * Cn + c;
    bool up = yy > 0, dn = yy < 63;
    size_t rowm = (size_t)yy * Wn;

    float3 cm = make_float3(0.f, 0.f, 0.f), cc, cp;
    cc.x = up ? __half2float(zb[(rowm - Wn) * Cn]) : 0.f;
    cc.y = __half2float(zb[rowm * Cn]);
    cc.z = dn ? __half2float(zb[(rowm + Wn) * Cn]) : 0.f;

    int mrow0 = b * HWn + yy * Wn;
    for (int xx = 0; xx < 64; xx++) {
        if (xx < 63) {
            size_t bcol = rowm + xx + 1;
            cp.x = up ? __half2float(zb[(bcol - Wn) * Cn]) : 0.f;
            cp.y = __half2float(zb[bcol * Cn]);
            cp.z = dn ? __half2float(zb[(bcol + Wn) * Cn]) : 0.f;
        } else {
            cp = make_float3(0.f, 0.f, 0.f);
        }
        float acc = bias
            + w[0] * cm.x + w[1] * cc.x + w[2] * cp.x
            + w[3] * cm.y + w[4] * cc.y + w[5] * cp.y
            + w[6] * cm.z + w[7] * cc.z + w[8] * cp.z;
        size_t o = a_off(mrow0 + xx, c);
        g_abf[o] = __float2half(acc);
        cm = cc; cc = cp;
    }
}

// ---------------- launch ----------------
extern "C" void kernel_launch(void* const* d_in, const int* in_sizes, int n_in,
                              void* d_out, int out_size)
{
    const float* x     = (const float*)d_in[0];
    const float* qkv_w = (const float*)d_in[1];
    const float* dwx_w = (const float*)d_in[2];
    const float* dwx_b = (const float*)d_in[3];
    const float* dw_w  = (const float*)d_in[4];
    const float* dw_b  = (const float*)d_in[5];
    const float* pw_w  = (const float*)d_in[6];
    const float* pw_b  = (const float*)d_in[7];
    float* out = (float*)d_out;

    cudaFuncSetAttribute(gemm_mma, cudaFuncAttributeMaxDynamicSharedMemorySize,
                         GSMEM);
    cudaFuncSetAttribute(coarse_attn_kernel,
                         cudaFuncAttributeMaxDynamicSharedMemorySize, CA_SMEM);

    // weight conversions (tiny)
    convw_kernel<<<(C3n * Cn + 255) / 256, 256>>>(qkv_w, C3n * Cn, 0);
    convw_kernel<<<(Cn * Cn + 255) / 256, 256>>>(pw_w, Cn * Cn, 1);

    // 1) coarse pooling
    pool_kernel<<<Bn * NCn, Cn>>>(x);

    // 2) coarse QKV (3-pass, exact top-k)
    gemm_mma<<<dim3(C3n / 128, (Bn * NCn) / 256), 512, GSMEM>>>(
        nullptr, nullptr, C3n, 0, 3);

    // 3) coarse routing attention + top-k
    coarse_attn_kernel<<<Bn * NHd * 2, 128, CA_SMEM>>>();

    // 4) fine QKV (1-pass fp16, fp16 output)
    convA_kernel<<<(Bn * HWn * 48 + 255) / 256, 256>>>(x, Bn * HWn * 48);
    gemm_mma<<<dim3(C3n / 128, (Bn * HWn) / 256), 512, GSMEM>>>(
        nullptr, nullptr, C3n, 1, 1);

    // 5) fine windowed attention (tensor-core)
    fine_attn_kernel<<<Bn * NHd * NCn, 128>>>();

    // 6) upsample+dwconv(dwx)+mix
    dwmix_kernel<<<Bn * Hn, Cn>>>(dwx_w, dwx_b);

    // 7) dwconv(dw) -> fp16 hi plane only
    dwconv2_kernel<<<Bn * Hn, Cn>>>(dw_w, dw_b);

    // 8) pointwise projection (+bias, 1-pass)
    gemm_mma<<<dim3(Cn / 128, (Bn * HWn) / 256), 512, GSMEM>>>(
        pw_b, out, Cn, 2, 1);
}